// round 8
// baseline (speedup 1.0000x reference)
#include <cuda_runtime.h>
#include <cuda_bf16.h>
#include <math.h>
#include <cstdint>

#define NB 4
#define NH 16
#define DH 64
#define SQ 1024
#define LI 128
#define HIDDEN 1024
#define BHN (NB * NH)
#define KW 2048   // stored operand width (hi|lo)

// ---------------- scratch ---------------------------------------------------
__device__ __align__(16) __nv_bfloat16 g_Qh[BHN * SQ * DH];
__device__ __align__(16) __nv_bfloat16 g_Ql[BHN * SQ * DH];
__device__ __align__(16) __nv_bfloat16 g_Kh[BHN * SQ * DH];
__device__ __align__(16) __nv_bfloat16 g_Kl[BHN * SQ * DH];
__device__ __align__(16) __nv_bfloat16 g_Vh[BHN * SQ * DH];
__device__ __align__(16) __nv_bfloat16 g_Vl[BHN * SQ * DH];
__device__ __align__(16) __nv_bfloat16 g_IKh[BHN * LI * DH];
__device__ __align__(16) __nv_bfloat16 g_IKl[BHN * LI * DH];
__device__ __align__(16) __nv_bfloat16 g_IVh[BHN * LI * DH];
__device__ __align__(16) __nv_bfloat16 g_IVl[BHN * LI * DH];
__device__ __align__(16) __nv_bfloat16 g_Eh[2048 * DH];

__device__ __align__(16) __nv_bfloat16 g_Xcat[NB * SQ * KW];
__device__ __align__(16) __nv_bfloat16 g_IXcat[NB * LI * KW];
__device__ __align__(16) __nv_bfloat16 g_Wcat[3 * HIDDEN * KW];

// ---------------- helpers ---------------------------------------------------
__device__ __forceinline__ uint32_t smem_u32(const void* p) {
    uint32_t a;
    asm("{ .reg .u64 t; cvta.to.shared.u64 t, %1; cvt.u32.u64 %0, t; }" : "=r"(a) : "l"(p));
    return a;
}
__device__ __forceinline__ void ldsm4(uint32_t& r0, uint32_t& r1, uint32_t& r2,
                                      uint32_t& r3, uint32_t addr) {
    asm volatile("ldmatrix.sync.aligned.m8n8.x4.shared.b16 {%0,%1,%2,%3}, [%4];"
                 : "=r"(r0), "=r"(r1), "=r"(r2), "=r"(r3) : "r"(addr));
}
__device__ __forceinline__ void ldsm4t(uint32_t& r0, uint32_t& r1, uint32_t& r2,
                                       uint32_t& r3, uint32_t addr) {
    asm volatile("ldmatrix.sync.aligned.m8n8.x4.trans.shared.b16 {%0,%1,%2,%3}, [%4];"
                 : "=r"(r0), "=r"(r1), "=r"(r2), "=r"(r3) : "r"(addr));
}
__device__ __forceinline__ void mma16816(float* c, uint32_t a0, uint32_t a1,
                                         uint32_t a2, uint32_t a3,
                                         uint32_t b0, uint32_t b1) {
    asm volatile(
        "mma.sync.aligned.m16n8k16.row.col.f32.bf16.bf16.f32 "
        "{%0,%1,%2,%3}, {%4,%5,%6,%7}, {%8,%9}, {%0,%1,%2,%3};"
        : "+f"(c[0]), "+f"(c[1]), "+f"(c[2]), "+f"(c[3])
        : "r"(a0), "r"(a1), "r"(a2), "r"(a3), "r"(b0), "r"(b1));
}
__device__ __forceinline__ uint32_t pk2(float a, float b) {
    __nv_bfloat162 t = __floats2bfloat162_rn(a, b);
    return *(uint32_t*)&t;
}
__device__ __forceinline__ void cpasync16(uint32_t dst, const void* src) {
    asm volatile("cp.async.cg.shared.global [%0], [%1], 16;" :: "r"(dst), "l"(src));
}
#define CP_COMMIT() asm volatile("cp.async.commit_group;" ::: "memory")
#define CP_WAIT(n)  asm volatile("cp.async.wait_group %0;" :: "n"(n) : "memory")

// ---------------------------------------------------------------------------
// Conversions (merged X-main / X-instruct / E in one launch)
// ---------------------------------------------------------------------------
#define NX_MAIN (NB * SQ * HIDDEN / 4 / 256)
#define NX_INST (NB * LI * HIDDEN / 4 / 256)
#define NX_E    (2048 * 64 / 256)

__global__ __launch_bounds__(256)
void conv_all(const float4* __restrict__ xm, __nv_bfloat16* __restrict__ dm,
              const float4* __restrict__ xi, __nv_bfloat16* __restrict__ di,
              const float* __restrict__ dist, __nv_bfloat16* __restrict__ eh)
{
    int blk = blockIdx.x;
    if (blk >= NX_MAIN + NX_INST) {
        int i = (blk - NX_MAIN - NX_INST) * 256 + threadIdx.x;
        float v = (i < 2047 * 64) ? dist[i] : 0.f;
        eh[i] = __float2bfloat16(v);
        return;
    }
    const float4* src = (blk < NX_MAIN) ? xm : xi;
    __nv_bfloat16* dst = (blk < NX_MAIN) ? dm : di;
    int i = ((blk < NX_MAIN) ? blk : blk - NX_MAIN) * 256 + threadIdx.x;
    int row = i >> 8, c4 = (i & 255) * 4;
    float4 v = src[i];
    __nv_bfloat16 hx = __float2bfloat16(v.x), hy = __float2bfloat16(v.y);
    __nv_bfloat16 hz = __float2bfloat16(v.z), hw = __float2bfloat16(v.w);
    __nv_bfloat16 lx = __float2bfloat16(v.x - __bfloat162float(hx));
    __nv_bfloat16 ly = __float2bfloat16(v.y - __bfloat162float(hy));
    __nv_bfloat16 lz = __float2bfloat16(v.z - __bfloat162float(hz));
    __nv_bfloat16 lw = __float2bfloat16(v.w - __bfloat162float(hw));
    uint2 H, L;
    H.x = (uint32_t)__bfloat16_as_ushort(hx) | ((uint32_t)__bfloat16_as_ushort(hy) << 16);
    H.y = (uint32_t)__bfloat16_as_ushort(hz) | ((uint32_t)__bfloat16_as_ushort(hw) << 16);
    L.x = (uint32_t)__bfloat16_as_ushort(lx) | ((uint32_t)__bfloat16_as_ushort(ly) << 16);
    L.y = (uint32_t)__bfloat16_as_ushort(lz) | ((uint32_t)__bfloat16_as_ushort(lw) << 16);
    __nv_bfloat16* rb = dst + (size_t)row * KW + c4;
    *(uint2*)(rb)        = H;
    *(uint2*)(rb + 1024) = L;
}

__global__ __launch_bounds__(256)
void conv_w(const float* __restrict__ Wq, const float* __restrict__ Wk,
            const float* __restrict__ Wv, __nv_bfloat16* __restrict__ dst)
{
    const float* W = (blockIdx.z == 0) ? Wq : (blockIdx.z == 1) ? Wk : Wv;
    __shared__ float t[32][33];
    int tx = threadIdx.x & 31, ty = threadIdx.x >> 5;
    int n = blockIdx.x * 32 + tx, k0 = blockIdx.y * 32;
#pragma unroll
    for (int j = 0; j < 4; j++)
        t[ty + 8 * j][tx] = W[(size_t)(k0 + ty + 8 * j) * HIDDEN + n];
    __syncthreads();
    size_t nrow = (size_t)blockIdx.z * HIDDEN + blockIdx.x * 32;
#pragma unroll
    for (int j = 0; j < 4; j++) {
        float v = t[tx][ty + 8 * j];
        __nv_bfloat16 h = __float2bfloat16(v);
        __nv_bfloat16 l = __float2bfloat16(v - __bfloat162float(h));
        __nv_bfloat16* o = dst + (nrow + ty + 8 * j) * KW + k0 + tx;
        o[0]    = h;
        o[1024] = l;
    }
}

// ---------------------------------------------------------------------------
// Merged projection GEMM (unchanged from R7): CTA 128x256, warp 64x64.
// ---------------------------------------------------------------------------
#define KC 64
#define AST 72
#define TA (128 * AST * 2)
#define TB (256 * AST * 2)
#define GEMM_SMEM (2 * (TA + TB))

__global__ __launch_bounds__(256, 1)
void gemm_mma(const __nv_bfloat16* __restrict__ Am,
              const __nv_bfloat16* __restrict__ Ai,
              const __nv_bfloat16* __restrict__ Bm,
              const float* __restrict__ bq, const float* __restrict__ bk,
              const float* __restrict__ bv,
              __nv_bfloat16* oQh, __nv_bfloat16* oQl,
              __nv_bfloat16* oKh, __nv_bfloat16* oKl,
              __nv_bfloat16* oVh, __nv_bfloat16* oVl,
              __nv_bfloat16* oIKh, __nv_bfloat16* oIKl,
              __nv_bfloat16* oIVh, __nv_bfloat16* oIVl)
{
    extern __shared__ char smem[];
    const uint32_t sb = smem_u32(smem);
    const int tid = threadIdx.x, warp = tid >> 5, lane = tid & 31;

    const __nv_bfloat16* A;
    int msh, Slen, m0, n0g, inst;
    {
        int blk = blockIdx.x;
        if (blk < 384) {
            A = Am; msh = 10; Slen = SQ; inst = 0;
            m0 = (blk / 12) * 128; n0g = (blk % 12) * 256;
        } else {
            blk -= 384;
            A = Ai; msh = 7; Slen = LI; inst = 1;
            m0 = (blk / 8) * 128; n0g = 1024 + (blk % 8) * 256;
        }
    }
    const int wm = (warp >> 2) * 64, wn = (warp & 3) * 64;

    const int cr = tid >> 3, cko = (tid & 7) * 8;
    const __nv_bfloat16* Ag = A + (size_t)(m0 + cr) * KW + cko;
    const __nv_bfloat16* Bg = Bm + (size_t)(n0g + cr) * KW + cko;
    const uint32_t sAo = (cr * AST + cko) * 2;

    float acc[4][8][4];
#pragma unroll
    for (int i = 0; i < 4; i++)
#pragma unroll
        for (int j = 0; j < 8; j++)
#pragma unroll
            for (int p = 0; p < 4; p++) acc[i][j][p] = 0.f;

#pragma unroll
    for (int i = 0; i < 4; i++)
        cpasync16(sb + sAo + i * 32 * AST * 2, Ag + (size_t)(i * 32) * KW);
#pragma unroll
    for (int i = 0; i < 8; i++)
        cpasync16(sb + TA + sAo + i * 32 * AST * 2, Bg + (size_t)(i * 32) * KW);
    CP_COMMIT();

    const int NCH = 48;
    for (int c = 0; c < NCH; c++) {
        const int p = c & 1;
        if (c + 1 < NCH) {
            const int pn = (c + 1) & 1;
            const int cn = c + 1;
            const int aoff = (cn < 16) ? cn * 64 : cn * 64 - 1024;
            const int boff = (cn < 32) ? cn * 64 : cn * 64 - 2048;
#pragma unroll
            for (int i = 0; i < 4; i++)
                cpasync16(sb + pn * (TA + TB) + sAo + i * 32 * AST * 2,
                          Ag + (size_t)(i * 32) * KW + aoff);
#pragma unroll
            for (int i = 0; i < 8; i++)
                cpasync16(sb + pn * (TA + TB) + TA + sAo + i * 32 * AST * 2,
                          Bg + (size_t)(i * 32) * KW + boff);
            CP_COMMIT();
            CP_WAIT(1);
        } else {
            CP_WAIT(0);
        }
        __syncthreads();

        const uint32_t aw = sb + p * (TA + TB) +
                            ((wm + (lane & 15)) * AST + (lane >> 4) * 8) * 2;
        const uint32_t bw = sb + p * (TA + TB) + TA +
                            ((wn + (lane & 15)) * AST + (lane >> 4) * 8) * 2;
#pragma unroll
        for (int k16 = 0; k16 < 4; k16++) {
            const uint32_t ko = k16 * 32;
            uint32_t a[4][4], b[4][4];
#pragma unroll
            for (int mt = 0; mt < 4; mt++)
                ldsm4(a[mt][0], a[mt][1], a[mt][2], a[mt][3],
                      aw + mt * 16 * AST * 2 + ko);
#pragma unroll
            for (int nb = 0; nb < 4; nb++)
                ldsm4(b[nb][0], b[nb][1], b[nb][2], b[nb][3],
                      bw + nb * 16 * AST * 2 + ko);
#pragma unroll
            for (int mt = 0; mt < 4; mt++)
#pragma unroll
                for (int nb = 0; nb < 4; nb++) {
                    mma16816(acc[mt][2 * nb], a[mt][0], a[mt][1], a[mt][2], a[mt][3],
                             b[nb][0], b[nb][2]);
                    mma16816(acc[mt][2 * nb + 1], a[mt][0], a[mt][1], a[mt][2], a[mt][3],
                             b[nb][1], b[nb][3]);
                }
        }
        __syncthreads();
    }

#pragma unroll
    for (int nt = 0; nt < 8; nt++) {
        const int n = n0g + wn + nt * 8 + (lane & 3) * 2;
        const int wsel = n >> 10, nn = n & 1023;
        const float* bias = (wsel == 0) ? bq : (wsel == 1) ? bk : bv;
        __nv_bfloat16* ph;
        __nv_bfloat16* pl;
        if (inst) {
            ph = (wsel == 1) ? oIKh : oIVh;
            pl = (wsel == 1) ? oIKl : oIVl;
        } else {
            ph = (wsel == 0) ? oQh : (wsel == 1) ? oKh : oVh;
            pl = (wsel == 0) ? oQl : (wsel == 1) ? oKl : oVl;
        }
        const float b0 = bias[nn], b1 = bias[nn + 1];
        const size_t hoff = ((size_t)(nn >> 6)) * Slen;
        const int d = nn & 63;
#pragma unroll
        for (int mt = 0; mt < 4; mt++) {
#pragma unroll
            for (int half = 0; half < 2; half++) {
                const int r = m0 + wm + mt * 16 + (lane >> 2) + half * 8;
                const int bb = r >> msh, t = r - (bb << msh);
                float vx = acc[mt][nt][half * 2 + 0] + b0;
                float vy = acc[mt][nt][half * 2 + 1] + b1;
                __nv_bfloat16 hx = __float2bfloat16(vx);
                __nv_bfloat16 hy = __float2bfloat16(vy);
                float lxf = vx - __bfloat162float(hx);
                float lyf = vy - __bfloat162float(hy);
                size_t off = ((size_t)bb * NH * Slen + hoff + t) * DH + d;
                *(uint32_t*)(ph + off) =
                    (uint32_t)__bfloat16_as_ushort(hx) |
                    ((uint32_t)__bfloat16_as_ushort(hy) << 16);
                *(uint32_t*)(pl + off) = pk2(lxf, lyf);
            }
        }
    }
}

// ---------------------------------------------------------------------------
// Tensor-core attention (term-outer MMA scheduling to break acc dep chains).
// ---------------------------------------------------------------------------
#define PST 72
#define P12 136
#define A_SQH 0
#define A_SQL 9216
#define A_KV0 18432
#define KVSET 36864
#define KOH 0
#define KOL 9216
#define VOH 18432
#define VOL 27648
#define A_E0 92160
#define ESET 18432
#define A_SPH 129024
#define A_SPL 138240
#define A_SP1 147456
#define A_SP2 164864
#define A_CORR 182272
#define A_SSM 182528
#define A_SSI 182784
#define A_AMSK 183040
#define A_IMSK 187136
#define A_TOTAL 187648

__device__ __forceinline__ void cp_tile64(char* sm, int dstoff,
                                          const __nv_bfloat16* src, int tid)
{
#pragma unroll
    for (int it = 0; it < 2; it++) {
        int i = tid + it * 256;
        int r = i >> 3, c = (i & 7) * 8;
        *(uint4*)(sm + dstoff + (r * PST + c) * 2) = *(const uint4*)(src + r * 64 + c);
    }
}
__device__ __forceinline__ void cpa_tile64(uint32_t sb, int dstoff,
                                           const __nv_bfloat16* src, int tid)
{
#pragma unroll
    for (int it = 0; it < 2; it++) {
        int i = tid + it * 256;
        int r = i >> 3, c = (i & 7) * 8;
        cpasync16(sb + dstoff + (r * PST + c) * 2, src + r * 64 + c);
    }
}
__device__ __forceinline__ float ldbf(const char* sm, int base, int idx) {
    return __bfloat162float(*(const __nv_bfloat16*)(sm + base + idx * 2));
}

// QK 3-term split, term-outer ordering (acc reuse distance = 8 MMAs).
__device__ __forceinline__ void qk_tile(float sacc[8][4], uint32_t sb,
                                        int qh_off, int ql_off,
                                        int kh_off, int kl_off,
                                        int wm, int lane)
{
#pragma unroll
    for (int k = 0; k < 4; k++) {
        const uint32_t ko = (k * 16 + (lane >> 4) * 8) * 2;
        uint32_t aH[4], aL[4], bH[4][4], bL[4][4];
        ldsm4(aH[0], aH[1], aH[2], aH[3],
              sb + qh_off + (wm + (lane & 15)) * PST * 2 + ko);
        ldsm4(aL[0], aL[1], aL[2], aL[3],
              sb + ql_off + (wm + (lane & 15)) * PST * 2 + ko);
#pragma unroll
        for (int nb = 0; nb < 4; nb++) {
            ldsm4(bH[nb][0], bH[nb][1], bH[nb][2], bH[nb][3],
                  sb + kh_off + (nb * 16 + (lane & 15)) * PST * 2 + ko);
            ldsm4(bL[nb][0], bL[nb][1], bL[nb][2], bL[nb][3],
                  sb + kl_off + (nb * 16 + (lane & 15)) * PST * 2 + ko);
        }
#pragma unroll
        for (int nb = 0; nb < 4; nb++) {
            mma16816(sacc[2 * nb], aH[0], aH[1], aH[2], aH[3], bH[nb][0], bH[nb][2]);
            mma16816(sacc[2 * nb + 1], aH[0], aH[1], aH[2], aH[3], bH[nb][1], bH[nb][3]);
        }
#pragma unroll
        for (int nb = 0; nb < 4; nb++) {
            mma16816(sacc[2 * nb], aH[0], aH[1], aH[2], aH[3], bL[nb][0], bL[nb][2]);
            mma16816(sacc[2 * nb + 1], aH[0], aH[1], aH[2], aH[3], bL[nb][1], bL[nb][3]);
        }
#pragma unroll
        for (int nb = 0; nb < 4; nb++) {
            mma16816(sacc[2 * nb], aL[0], aL[1], aL[2], aL[3], bH[nb][0], bH[nb][2]);
            mma16816(sacc[2 * nb + 1], aL[0], aL[1], aL[2], aL[3], bH[nb][1], bH[nb][3]);
        }
    }
}

// PV 3-term split, term-outer ordering (acc reuse distance = 4 MMAs).
__device__ __forceinline__ void pv_tile(float cacc[4][4], uint32_t sb,
                                        int vh_off, int vl_off,
                                        int wm2, int wn2, int lane)
{
#pragma unroll
    for (int kk = 0; kk < 4; kk++) {
        const uint32_t ko = (kk * 16 + (lane >> 4) * 8) * 2;
        uint32_t aPh[4], aPl[4], vh[2][4], vl[2][4];
        ldsm4(aPh[0], aPh[1], aPh[2], aPh[3],
              sb + A_SPH + (wm2 + (lane & 15)) * PST * 2 + ko);
        ldsm4(aPl[0], aPl[1], aPl[2], aPl[3],
              sb + A_SPL + (wm2 + (lane & 15)) * PST * 2 + ko);
        const uint32_t trow = (kk * 16 + (lane & 7) + 8 * ((lane >> 3) & 1)) * PST;
#pragma unroll
        for (int dh = 0; dh < 2; dh++) {
            const uint32_t tcol = wn2 + dh * 16 + ((lane >> 4) & 1) * 8;
            ldsm4t(vh[dh][0], vh[dh][1], vh[dh][2], vh[dh][3],
                   sb + vh_off + (trow + tcol) * 2);
            ldsm4t(vl[dh][0], vl[dh][1], vl[dh][2], vl[dh][3],
                   sb + vl_off + (trow + tcol) * 2);
        }
#pragma unroll
        for (int dh = 0; dh < 2; dh++) {
            mma16816(cacc[2 * dh], aPh[0], aPh[1], aPh[2], aPh[3], vh[dh][0], vh[dh][1]);
            mma16816(cacc[2 * dh + 1], aPh[0], aPh[1], aPh[2], aPh[3], vh[dh][2], vh[dh][3]);
        }
#pragma unroll
        for (int dh = 0; dh < 2; dh++) {
            mma16816(cacc[2 * dh], aPh[0], aPh[1], aPh[2], aPh[3], vl[dh][0], vl[dh][1]);
            mma16816(cacc[2 * dh + 1], aPh[0], aPh[1], aPh[2], aPh[3], vl[dh][2], vl[dh][3]);
        }
#pragma unroll
        for (int dh = 0; dh < 2; dh++) {
            mma16816(cacc[2 * dh], aPl[0], aPl[1], aPl[2], aPl[3], vh[dh][0], vh[dh][1]);
            mma16816(cacc[2 * dh + 1], aPl[0], aPl[1], aPl[2], aPl[3], vh[dh][2], vh[dh][3]);
        }
    }
}

__global__ __launch_bounds__(256, 1)
void attn_mma(const float* __restrict__ amask, const float* __restrict__ imask,
              const float* __restrict__ gate, float* __restrict__ outp)
{
    extern __shared__ char sm[];
    const uint32_t sb = smem_u32(sm);
    const int tid = threadIdx.x, warp = tid >> 5, lane = tid & 31;
    const int g = lane >> 2, t4 = lane & 3;
    const int bh = blockIdx.y, b = bh >> 4, h = bh & 15;
    const int l0 = blockIdx.x * 64;
    const int wm = warp * 16;
    const int wm2 = (warp >> 1) * 16, wn2 = (warp & 1) * 32;

    cp_tile64(sm, A_SQH, g_Qh + ((size_t)bh * SQ + l0) * DH, tid);
    cp_tile64(sm, A_SQL, g_Ql + ((size_t)bh * SQ + l0) * DH, tid);
    ((float4*)(sm + A_AMSK))[tid] = ((const float4*)(amask + b * SQ))[tid];
    if (tid < 32)
        ((float4*)(sm + A_IMSK))[tid] = ((const float4*)(imask + b * LI))[tid];

    float cacc[4][4];
#pragma unroll
    for (int i = 0; i < 4; i++)
#pragma unroll
        for (int j = 0; j < 4; j++) cacc[i][j] = 0.f;
    float mrow[2] = {-1e30f, -1e30f}, ssum[2] = {0.f, 0.f};
    float* corr_sm = (float*)(sm + A_CORR);
    const float* amsk = (const float*)(sm + A_AMSK);
    const float* imsk = (const float*)(sm + A_IMSK);

    {
        cpa_tile64(sb, A_KV0 + KOH, g_Kh + ((size_t)bh * SQ) * DH, tid);
        cpa_tile64(sb, A_KV0 + KOL, g_Kl + ((size_t)bh * SQ) * DH, tid);
        cpa_tile64(sb, A_KV0 + VOH, g_Vh + ((size_t)bh * SQ) * DH, tid);
        cpa_tile64(sb, A_KV0 + VOL, g_Vl + ((size_t)bh * SQ) * DH, tid);
        const __nv_bfloat16* Eg = g_Eh + (size_t)(l0 + 960) * 64;
#pragma unroll
        for (int it = 0; it < 4; it++) {
            int i = tid + it * 256;
            int r = i >> 3, c = (i & 7) * 8;
            cpasync16(sb + A_E0 + (r * PST + c) * 2, Eg + r * 64 + c);
        }
        CP_COMMIT();
    }

    // ======================= main pass =======================
    for (int rt = 0; rt < 16; rt++) {
        const int pb = rt & 1;
        const int kvb = A_KV0 + pb * KVSET;
        const int eb = A_E0 + pb * ESET;
        const int r0 = rt * 64;

        if (rt + 1 < 16) {
            const int nb2 = A_KV0 + (pb ^ 1) * KVSET;
            const int r1 = r0 + 64;
            cpa_tile64(sb, nb2 + KOH, g_Kh + ((size_t)bh * SQ + r1) * DH, tid);
            cpa_tile64(sb, nb2 + KOL, g_Kl + ((size_t)bh * SQ + r1) * DH, tid);
            cpa_tile64(sb, nb2 + VOH, g_Vh + ((size_t)bh * SQ + r1) * DH, tid);
            cpa_tile64(sb, nb2 + VOL, g_Vl + ((size_t)bh * SQ + r1) * DH, tid);
            const __nv_bfloat16* Eg = g_Eh + (size_t)(l0 - r1 + 960) * 64;
            const int eb2 = A_E0 + (pb ^ 1) * ESET;
#pragma unroll
            for (int it = 0; it < 4; it++) {
                int i = tid + it * 256;
                int r = i >> 3, c = (i & 7) * 8;
                cpasync16(sb + eb2 + (r * PST + c) * 2, Eg + r * 64 + c);
            }
            CP_COMMIT();
            CP_WAIT(1);
        } else {
            CP_WAIT(0);
        }
        __syncthreads();

        float sacc[8][4];
        if (warp < 4) {
#pragma unroll
            for (int j = 0; j < 8; j++)
#pragma unroll
                for (int p = 0; p < 4; p++) sacc[j][p] = 0.f;
            qk_tile(sacc, sb, A_SQH, A_SQL, kvb + KOH, kvb + KOL, wm, lane);
        } else {
            const int isP2 = (warp >= 6);
            const int m0p = (warp - (isP2 ? 6 : 4)) * 32;
            const int srcA = isP2 ? (kvb + KOH) : A_SQH;
            const int dstP = isP2 ? A_SP2 : A_SP1;
#pragma unroll
            for (int ch = 0; ch < 2; ch++) {
                float pacc[2][8][4];
#pragma unroll
                for (int s = 0; s < 2; s++)
#pragma unroll
                    for (int j = 0; j < 8; j++)
#pragma unroll
                        for (int p = 0; p < 4; p++) pacc[s][j][p] = 0.f;
#pragma unroll
                for (int k = 0; k < 4; k++) {
                    const uint32_t ko = (k * 16 + (lane >> 4) * 8) * 2;
                    uint32_t aU[4], aD[4];
                    ldsm4(aU[0], aU[1], aU[2], aU[3],
                          sb + srcA + (m0p + (lane & 15)) * PST * 2 + ko);
                    ldsm4(aD[0], aD[1], aD[2], aD[3],
                          sb + srcA + (m0p + 16 + (lane & 15)) * PST * 2 + ko);
#pragma unroll
                    for (int nb = 0; nb < 4; nb++) {
                        uint32_t be[4];
                        ldsm4(be[0], be[1], be[2], be[3],
                              sb + eb + (ch * 64 + nb * 16 + (lane & 15)) * PST * 2 + ko);
                        mma16816(pacc[0][2 * nb], aU[0], aU[1], aU[2], aU[3], be[0], be[2]);
                        mma16816(pacc[0][2 * nb + 1], aU[0], aU[1], aU[2], aU[3], be[1], be[3]);
                        mma16816(pacc[1][2 * nb], aD[0], aD[1], aD[2], aD[3], be[0], be[2]);
                        mma16816(pacc[1][2 * nb + 1], aD[0], aD[1], aD[2], aD[3], be[1], be[3]);
                    }
                }
#pragma unroll
                for (int s = 0; s < 2; s++)
#pragma unroll
                    for (int j = 0; j < 8; j++) {
                        int l = m0p + s * 16 + g;
                        int w = ch * 64 + 8 * j + 2 * t4;
                        *(uint32_t*)(sm + dstP + (l * P12 + w) * 2) =
                            pk2(pacc[s][j][0], pacc[s][j][1]);
                        *(uint32_t*)(sm + dstP + ((l + 8) * P12 + w) * 2) =
                            pk2(pacc[s][j][2], pacc[s][j][3]);
                    }
            }
        }
        __syncthreads();

        if (warp < 4) {
            const int l = wm + g;
#pragma unroll
            for (int j = 0; j < 8; j++) {
                const int r = 8 * j + 2 * t4;
                const int w = l - r + 63;
                sacc[j][0] = (sacc[j][0] + ldbf(sm, A_SP1, l * P12 + w)
                              + ldbf(sm, A_SP2, r * P12 + w)) * 0.125f + amsk[r0 + r];
                sacc[j][1] = (sacc[j][1] + ldbf(sm, A_SP1, l * P12 + w - 1)
                              + ldbf(sm, A_SP2, (r + 1) * P12 + w - 1)) * 0.125f + amsk[r0 + r + 1];
                sacc[j][2] = (sacc[j][2] + ldbf(sm, A_SP1, (l + 8) * P12 + w + 8)
                              + ldbf(sm, A_SP2, r * P12 + w + 8)) * 0.125f + amsk[r0 + r];
                sacc[j][3] = (sacc[j][3] + ldbf(sm, A_SP1, (l + 8) * P12 + w + 7)
                              + ldbf(sm, A_SP2, (r + 1) * P12 + w + 7)) * 0.125f + amsk[r0 + r + 1];
            }
            float mt0 = -1e30f, mt1 = -1e30f;
#pragma unroll
            for (int j = 0; j < 8; j++) {
                mt0 = fmaxf(mt0, fmaxf(sacc[j][0], sacc[j][1]));
                mt1 = fmaxf(mt1, fmaxf(sacc[j][2], sacc[j][3]));
            }
            mt0 = fmaxf(mt0, __shfl_xor_sync(0xffffffffu, mt0, 1));
            mt0 = fmaxf(mt0, __shfl_xor_sync(0xffffffffu, mt0, 2));
            mt1 = fmaxf(mt1, __shfl_xor_sync(0xffffffffu, mt1, 1));
            mt1 = fmaxf(mt1, __shfl_xor_sync(0xffffffffu, mt1, 2));
            float mn0 = fmaxf(mrow[0], mt0), mn1 = fmaxf(mrow[1], mt1);
            float cr0 = __expf(mrow[0] - mn0), cr1 = __expf(mrow[1] - mn1);
            mrow[0] = mn0; mrow[1] = mn1;
            float ps0 = 0.f, ps1 = 0.f;
#pragma unroll
            for (int j = 0; j < 8; j++) {
                float p00 = __expf(sacc[j][0] - mn0), p01 = __expf(sacc[j][1] - mn0);
                float p10 = __expf(sacc[j][2] - mn1), p11 = __expf(sacc[j][3] - mn1);
                ps0 += p00 + p01; ps1 += p10 + p11;
                int cidx = 8 * j + 2 * t4;
                uint32_t h0 = pk2(p00, p01), h1 = pk2(p10, p11);
                *(uint32_t*)(sm + A_SPH + (l * PST + cidx) * 2) = h0;
                *(uint32_t*)(sm + A_SPH + ((l + 8) * PST + cidx) * 2) = h1;
                __nv_bfloat162 hh0 = *(__nv_bfloat162*)&h0;
                __nv_bfloat162 hh1 = *(__nv_bfloat162*)&h1;
                *(uint32_t*)(sm + A_SPL + (l * PST + cidx) * 2) =
                    pk2(p00 - __bfloat162float(hh0.x), p01 - __bfloat162float(hh0.y));
                *(uint32_t*)(sm + A_SPL + ((l + 8) * PST + cidx) * 2) =
                    pk2(p10 - __bfloat162float(hh1.x), p11 - __bfloat162float(hh1.y));
            }
            ps0 += __shfl_xor_sync(0xffffffffu, ps0, 1);
            ps0 += __shfl_xor_sync(0xffffffffu, ps0, 2);
            ps1 += __shfl_xor_sync(0xffffffffu, ps1, 1);
            ps1 += __shfl_xor_sync(0xffffffffu, ps1, 2);
            ssum[0] = ssum[0] * cr0 + ps0;
            ssum[1] = ssum[1] * cr1 + ps1;
            if (t4 == 0) { corr_sm[l] = cr0; corr_sm[l + 8] = cr1; }
        }
        __syncthreads();

        {
            float c0r = corr_sm[wm2 + g], c1r = corr_sm[wm2 + 8 + g];
#pragma unroll
            for (int nf = 0; nf < 4; nf++) {
                cacc[nf][0] *= c0r; cacc[nf][1] *= c0r;
                cacc[nf][2] *= c1r; cacc[nf][3] *= c1r;
            }
            pv_tile(cacc, sb, kvb + VOH, kvb + VOL, wm2, wn2, lane);
        }
        __syncthreads();
    }

    {
        float* stash = (float*)(sm + A_SP1);
#pragma unroll
        for (int nf = 0; nf < 4; nf++) {
            int d = wn2 + 8 * nf + 2 * t4;
            stash[(wm2 + g) * 68 + d] = cacc[nf][0];
            stash[(wm2 + g) * 68 + d + 1] = cacc[nf][1];
            stash[(wm2 + 8 + g) * 68 + d] = cacc[nf][2];
            stash[(wm2 + 8 + g) * 68 + d + 1] = cacc[nf][3];
            cacc[nf][0] = cacc[nf][1] = cacc[nf][2] = cacc[nf][3] = 0.f;
        }
        if (warp < 4 && t4 == 0) {
            ((float*)(sm + A_SSM))[wm + g] = ssum[0];
            ((float*)(sm + A_SSM))[wm + g + 8] = ssum[1];
        }
        mrow[0] = mrow[1] = -1e30f; ssum[0] = ssum[1] = 0.f;
    }

    // ======================= instruct pass =======================
    for (int rt = 0; rt < 2; rt++) {
        const int r0 = rt * 64;
        const int kvb = A_KV0;
        __syncthreads();
        cp_tile64(sm, kvb + KOH, g_IKh + ((size_t)bh * LI + r0) * DH, tid);
        cp_tile64(sm, kvb + KOL, g_IKl + ((size_t)bh * LI + r0) * DH, tid);
        cp_tile64(sm, kvb + VOH, g_IVh + ((size_t)bh * LI + r0) * DH, tid);
        cp_tile64(sm, kvb + VOL, g_IVl + ((size_t)bh * LI + r0) * DH, tid);
        __syncthreads();

        if (warp < 4) {
            float sacc[8][4];
#pragma unroll
            for (int j = 0; j < 8; j++)
#pragma unroll
                for (int p = 0; p < 4; p++) sacc[j][p] = 0.f;
            qk_tile(sacc, sb, A_SQH, A_SQL, kvb + KOH, kvb + KOL, wm, lane);

            const int l = wm + g;
            float mt0 = -1e30f, mt1 = -1e30f;
#pragma unroll
            for (int j = 0; j < 8; j++) {
                const int r = 8 * j + 2 * t4;
                sacc[j][0] = sacc[j][0] * 0.125f + imsk[r0 + r];
                sacc[j][1] = sacc[j][1] * 0.125f + imsk[r0 + r + 1];
                sacc[j][2] = sacc[j][2] * 0.125f + imsk[r0 + r];
                sacc[j][3] = sacc[j][3] * 0.125f + imsk[r0 + r + 1];
                mt0 = fmaxf(mt0, fmaxf(sacc[j][0], sacc[j][1]));
                mt1 = fmaxf(mt1, fmaxf(sacc[j][2], sacc[j][3]));
            }
            mt0 = fmaxf(mt0, __shfl_xor_sync(0xffffffffu, mt0, 1));
            mt0 = fmaxf(mt0, __shfl_xor_sync(0xffffffffu, mt0, 2));
            mt1 = fmaxf(mt1, __shfl_xor_sync(0xffffffffu, mt1, 1));
            mt1 = fmaxf(mt1, __shfl_xor_sync(0xffffffffu, mt1, 2));
            float mn0 = fmaxf(mrow[0], mt0), mn1 = fmaxf(mrow[1], mt1);
            float cr0 = __expf(mrow[0] - mn0), cr1 = __expf(mrow[1] - mn1);
            mrow[0] = mn0; mrow[1] = mn1;
            float ps0 = 0.f, ps1 = 0.f;
#pragma unroll
            for (int j = 0; j < 8; j++) {
                float p00 = __expf(sacc[j][0] - mn0), p01 = __expf(sacc[j][1] - mn0);
                float p10 = __expf(sacc[j][2] - mn1), p11 = __expf(sacc[j][3] - mn1);
                ps0 += p00 + p01; ps1 += p10 + p11;
                int cidx = 8 * j + 2 * t4;
                uint32_t h0 = pk2(p00, p01), h1 = pk2(p10, p11);
                *(uint32_t*)(sm + A_SPH + (l * PST + cidx) * 2) = h0;
                *(uint32_t*)(sm + A_SPH + ((l + 8) * PST + cidx) * 2) = h1;
                __nv_bfloat162 hh0 = *(__nv_bfloat162*)&h0;
                __nv_bfloat162 hh1 = *(__nv_bfloat162*)&h1;
                *(uint32_t*)(sm + A_SPL + (l * PST + cidx) * 2) =
                    pk2(p00 - __bfloat162float(hh0.x), p01 - __bfloat162float(hh0.y));
                *(uint32_t*)(sm + A_SPL + ((l + 8) * PST + cidx) * 2) =
                    pk2(p10 - __bfloat162float(hh1.x), p11 - __bfloat162float(hh1.y));
            }
            ps0 += __shfl_xor_sync(0xffffffffu, ps0, 1);
            ps0 += __shfl_xor_sync(0xffffffffu, ps0, 2);
            ps1 += __shfl_xor_sync(0xffffffffu, ps1, 1);
            ps1 += __shfl_xor_sync(0xffffffffu, ps1, 2);
            ssum[0] = ssum[0] * cr0 + ps0;
            ssum[1] = ssum[1] * cr1 + ps1;
            if (t4 == 0) { corr_sm[l] = cr0; corr_sm[l + 8] = cr1; }
        }
        __syncthreads();

        {
            float c0r = corr_sm[wm2 + g], c1r = corr_sm[wm2 + 8 + g];
#pragma unroll
            for (int nf = 0; nf < 4; nf++) {
                cacc[nf][0] *= c0r; cacc[nf][1] *= c0r;
                cacc[nf][2] *= c1r; cacc[nf][3] *= c1r;
            }
            pv_tile(cacc, sb, kvb + VOH, kvb + VOL, wm2, wn2, lane);
        }
    }

    __syncthreads();
    if (warp < 4 && t4 == 0) {
        ((float*)(sm + A_SSI))[wm + g] = ssum[0];
        ((float*)(sm + A_SSI))[wm + g + 8] = ssum[1];
    }
    __syncthreads();

    {
        const float tg = tanhf(gate[h]);
        const float* stash = (const float*)(sm + A_SP1);
        const float* ssmv = (const float*)(sm + A_SSM);
        const float* ssiv = (const float*)(sm + A_SSI);
        const float rnm0 = 1.f / ssmv[wm2 + g], rni0 = tg / ssiv[wm2 + g];
        const float rnm1 = 1.f / ssmv[wm2 + 8 + g], rni1 = tg / ssiv[wm2 + 8 + g];
#pragma unroll
        for (int nf = 0; nf < 4; nf++) {
            const int d = wn2 + 8 * nf + 2 * t4;
            float2 o0, o1;
            o0.x = stash[(wm2 + g) * 68 + d] * rnm0 + cacc[nf][0] * rni0;
            o0.y = stash[(wm2 + g) * 68 + d + 1] * rnm0 + cacc[nf][1] * rni0;
            o1.x = stash[(wm2 + 8 + g) * 68 + d] * rnm1 + cacc[nf][2] * rni1;
            o1.y = stash[(wm2 + 8 + g) * 68 + d + 1] * rnm1 + cacc[nf][3] * rni1;
            *(float2*)(outp + ((size_t)(b * SQ + l0 + wm2 + g)) * HIDDEN + h * DH + d) = o0;
            *(float2*)(outp + ((size_t)(b * SQ + l0 + wm2 + 8 + g)) * HIDDEN + h * DH + d) = o1;
        }
    }
}

// ---------------------------------------------------------------------------
extern "C" void kernel_launch(void* const* d_in, const int* in_sizes, int n_in,
                              void* d_out, int out_size)
{
    (void)in_sizes; (void)n_in; (void)out_size;
    const float* hs    = (const float*)d_in[0];
    const float* amask = (const float*)d_in[1];
    const float* ihs   = (const float*)d_in[2];
    const float* imask = (const float*)d_in[3];
    const float* Wq    = (const float*)d_in[4];
    const float* bq    = (const float*)d_in[5];
    const float* Wk    = (const float*)d_in[6];
    const float* bk    = (const float*)d_in[7];
    const float* Wv    = (const float*)d_in[8];
    const float* bv    = (const float*)d_in[9];
    const float* gate  = (const float*)d_in[10];
    const float* dist  = (const float*)d_in[11];
    float* out = (float*)d_out;

    __nv_bfloat16 *qh, *ql, *kh, *kl, *vh, *vl, *ikh, *ikl, *ivh, *ivl, *eh;
    __nv_bfloat16 *xc, *ixc, *wc;
    cudaGetSymbolAddress((void**)&qh, g_Qh);
    cudaGetSymbolAddress((void**)&ql, g_Ql);
    cudaGetSymbolAddress((void**)&kh, g_Kh);
    cudaGetSymbolAddress((void**)&kl, g_Kl);
    cudaGetSymbolAddress((void**)&vh, g_Vh);
    cudaGetSymbolAddress((void**)&vl, g_Vl);
    cudaGetSymbolAddress((void**)&ikh, g_IKh);
    cudaGetSymbolAddress((void**)&ikl, g_IKl);
    cudaGetSymbolAddress((void**)&ivh, g_IVh);
    cudaGetSymbolAddress((void**)&ivl, g_IVl);
    cudaGetSymbolAddress((void**)&eh, g_Eh);
    cudaGetSymbolAddress((void**)&xc, g_Xcat);
    cudaGetSymbolAddress((void**)&ixc, g_IXcat);
    cudaGetSymbolAddress((void**)&wc, g_Wcat);

    cudaFuncSetAttribute(gemm_mma, cudaFuncAttributeMaxDynamicSharedMemorySize, GEMM_SMEM);
    cudaFuncSetAttribute(attn_mma, cudaFuncAttributeMaxDynamicSharedMemorySize, A_TOTAL);

    conv_all<<<NX_MAIN + NX_INST + NX_E, 256>>>((const float4*)hs, xc,
                                                (const float4*)ihs, ixc, dist, eh);
    conv_w<<<dim3(32, 32, 3), 256>>>(Wq, Wk, Wv, wc);

    gemm_mma<<<416, 256, GEMM_SMEM>>>(xc, ixc, wc, bq, bk, bv,
                                      qh, ql, kh, kl, vh, vl,
                                      ikh, ikl, ivh, ivl);

    attn_mma<<<dim3(SQ / 64, BHN), 256, A_TOTAL>>>(amask, imask, gate, out);
}

// round 9
// speedup vs baseline: 1.0200x; 1.0200x over previous
#include <cuda_runtime.h>
#include <cuda_bf16.h>
#include <math.h>
#include <cstdint>

#define NB 4
#define NH 16
#define DH 64
#define SQ 1024
#define LI 128
#define HIDDEN 1024
#define BHN (NB * NH)
#define KW 2048   // stored operand width (hi|lo)

// ---------------- scratch ---------------------------------------------------
__device__ __align__(16) __nv_bfloat16 g_Qh[BHN * SQ * DH];
__device__ __align__(16) __nv_bfloat16 g_Ql[BHN * SQ * DH];
__device__ __align__(16) __nv_bfloat16 g_Kh[BHN * SQ * DH];
__device__ __align__(16) __nv_bfloat16 g_Kl[BHN * SQ * DH];
__device__ __align__(16) __nv_bfloat16 g_Vh[BHN * SQ * DH];
__device__ __align__(16) __nv_bfloat16 g_Vl[BHN * SQ * DH];
__device__ __align__(16) __nv_bfloat16 g_IKh[BHN * LI * DH];
__device__ __align__(16) __nv_bfloat16 g_IKl[BHN * LI * DH];
__device__ __align__(16) __nv_bfloat16 g_IVh[BHN * LI * DH];
__device__ __align__(16) __nv_bfloat16 g_IVl[BHN * LI * DH];
__device__ __align__(16) __nv_bfloat16 g_Eh[2048 * DH];

__device__ __align__(16) __nv_bfloat16 g_Xcat[NB * SQ * KW];
__device__ __align__(16) __nv_bfloat16 g_IXcat[NB * LI * KW];
__device__ __align__(16) __nv_bfloat16 g_Wcat[3 * HIDDEN * KW];

// ---------------- helpers ---------------------------------------------------
__device__ __forceinline__ uint32_t smem_u32(const void* p) {
    uint32_t a;
    asm("{ .reg .u64 t; cvta.to.shared.u64 t, %1; cvt.u32.u64 %0, t; }" : "=r"(a) : "l"(p));
    return a;
}
__device__ __forceinline__ void ldsm4(uint32_t& r0, uint32_t& r1, uint32_t& r2,
                                      uint32_t& r3, uint32_t addr) {
    asm volatile("ldmatrix.sync.aligned.m8n8.x4.shared.b16 {%0,%1,%2,%3}, [%4];"
                 : "=r"(r0), "=r"(r1), "=r"(r2), "=r"(r3) : "r"(addr));
}
__device__ __forceinline__ void ldsm4t(uint32_t& r0, uint32_t& r1, uint32_t& r2,
                                       uint32_t& r3, uint32_t addr) {
    asm volatile("ldmatrix.sync.aligned.m8n8.x4.trans.shared.b16 {%0,%1,%2,%3}, [%4];"
                 : "=r"(r0), "=r"(r1), "=r"(r2), "=r"(r3) : "r"(addr));
}
__device__ __forceinline__ void mma16816(float* c, uint32_t a0, uint32_t a1,
                                         uint32_t a2, uint32_t a3,
                                         uint32_t b0, uint32_t b1) {
    asm volatile(
        "mma.sync.aligned.m16n8k16.row.col.f32.bf16.bf16.f32 "
        "{%0,%1,%2,%3}, {%4,%5,%6,%7}, {%8,%9}, {%0,%1,%2,%3};"
        : "+f"(c[0]), "+f"(c[1]), "+f"(c[2]), "+f"(c[3])
        : "r"(a0), "r"(a1), "r"(a2), "r"(a3), "r"(b0), "r"(b1));
}
__device__ __forceinline__ uint32_t pk2(float a, float b) {
    __nv_bfloat162 t = __floats2bfloat162_rn(a, b);
    return *(uint32_t*)&t;
}
__device__ __forceinline__ void cpasync16(uint32_t dst, const void* src) {
    asm volatile("cp.async.cg.shared.global [%0], [%1], 16;" :: "r"(dst), "l"(src));
}
#define CP_COMMIT() asm volatile("cp.async.commit_group;" ::: "memory")
#define CP_WAIT(n)  asm volatile("cp.async.wait_group %0;" :: "n"(n) : "memory")

// ---------------------------------------------------------------------------
// Conversions (merged X-main / X-instruct / E in one launch)
// ---------------------------------------------------------------------------
#define NX_MAIN (NB * SQ * HIDDEN / 4 / 256)
#define NX_INST (NB * LI * HIDDEN / 4 / 256)
#define NX_E    (2048 * 64 / 256)

__global__ __launch_bounds__(256)
void conv_all(const float4* __restrict__ xm, __nv_bfloat16* __restrict__ dm,
              const float4* __restrict__ xi, __nv_bfloat16* __restrict__ di,
              const float* __restrict__ dist, __nv_bfloat16* __restrict__ eh)
{
    int blk = blockIdx.x;
    if (blk >= NX_MAIN + NX_INST) {
        int i = (blk - NX_MAIN - NX_INST) * 256 + threadIdx.x;
        float v = (i < 2047 * 64) ? dist[i] : 0.f;
        eh[i] = __float2bfloat16(v);
        return;
    }
    const float4* src = (blk < NX_MAIN) ? xm : xi;
    __nv_bfloat16* dst = (blk < NX_MAIN) ? dm : di;
    int i = ((blk < NX_MAIN) ? blk : blk - NX_MAIN) * 256 + threadIdx.x;
    int row = i >> 8, c4 = (i & 255) * 4;
    float4 v = src[i];
    __nv_bfloat16 hx = __float2bfloat16(v.x), hy = __float2bfloat16(v.y);
    __nv_bfloat16 hz = __float2bfloat16(v.z), hw = __float2bfloat16(v.w);
    __nv_bfloat16 lx = __float2bfloat16(v.x - __bfloat162float(hx));
    __nv_bfloat16 ly = __float2bfloat16(v.y - __bfloat162float(hy));
    __nv_bfloat16 lz = __float2bfloat16(v.z - __bfloat162float(hz));
    __nv_bfloat16 lw = __float2bfloat16(v.w - __bfloat162float(hw));
    uint2 H, L;
    H.x = (uint32_t)__bfloat16_as_ushort(hx) | ((uint32_t)__bfloat16_as_ushort(hy) << 16);
    H.y = (uint32_t)__bfloat16_as_ushort(hz) | ((uint32_t)__bfloat16_as_ushort(hw) << 16);
    L.x = (uint32_t)__bfloat16_as_ushort(lx) | ((uint32_t)__bfloat16_as_ushort(ly) << 16);
    L.y = (uint32_t)__bfloat16_as_ushort(lz) | ((uint32_t)__bfloat16_as_ushort(lw) << 16);
    __nv_bfloat16* rb = dst + (size_t)row * KW + c4;
    *(uint2*)(rb)        = H;
    *(uint2*)(rb + 1024) = L;
}

__global__ __launch_bounds__(256)
void conv_w(const float* __restrict__ Wq, const float* __restrict__ Wk,
            const float* __restrict__ Wv, __nv_bfloat16* __restrict__ dst)
{
    const float* W = (blockIdx.z == 0) ? Wq : (blockIdx.z == 1) ? Wk : Wv;
    __shared__ float t[32][33];
    int tx = threadIdx.x & 31, ty = threadIdx.x >> 5;
    int n = blockIdx.x * 32 + tx, k0 = blockIdx.y * 32;
#pragma unroll
    for (int j = 0; j < 4; j++)
        t[ty + 8 * j][tx] = W[(size_t)(k0 + ty + 8 * j) * HIDDEN + n];
    __syncthreads();
    size_t nrow = (size_t)blockIdx.z * HIDDEN + blockIdx.x * 32;
#pragma unroll
    for (int j = 0; j < 4; j++) {
        float v = t[tx][ty + 8 * j];
        __nv_bfloat16 h = __float2bfloat16(v);
        __nv_bfloat16 l = __float2bfloat16(v - __bfloat162float(h));
        __nv_bfloat16* o = dst + (nrow + ty + 8 * j) * KW + k0 + tx;
        o[0]    = h;
        o[1024] = l;
    }
}

// ---------------------------------------------------------------------------
// Merged projection GEMM (unchanged): CTA 128x256, warp 64x64.
// ---------------------------------------------------------------------------
#define KC 64
#define AST 72
#define TA (128 * AST * 2)
#define TB (256 * AST * 2)
#define GEMM_SMEM (2 * (TA + TB))

__global__ __launch_bounds__(256, 1)
void gemm_mma(const __nv_bfloat16* __restrict__ Am,
              const __nv_bfloat16* __restrict__ Ai,
              const __nv_bfloat16* __restrict__ Bm,
              const float* __restrict__ bq, const float* __restrict__ bk,
              const float* __restrict__ bv,
              __nv_bfloat16* oQh, __nv_bfloat16* oQl,
              __nv_bfloat16* oKh, __nv_bfloat16* oKl,
              __nv_bfloat16* oVh, __nv_bfloat16* oVl,
              __nv_bfloat16* oIKh, __nv_bfloat16* oIKl,
              __nv_bfloat16* oIVh, __nv_bfloat16* oIVl)
{
    extern __shared__ char smem[];
    const uint32_t sb = smem_u32(smem);
    const int tid = threadIdx.x, warp = tid >> 5, lane = tid & 31;

    const __nv_bfloat16* A;
    int msh, Slen, m0, n0g, inst;
    {
        int blk = blockIdx.x;
        if (blk < 384) {
            A = Am; msh = 10; Slen = SQ; inst = 0;
            m0 = (blk / 12) * 128; n0g = (blk % 12) * 256;
        } else {
            blk -= 384;
            A = Ai; msh = 7; Slen = LI; inst = 1;
            m0 = (blk / 8) * 128; n0g = 1024 + (blk % 8) * 256;
        }
    }
    const int wm = (warp >> 2) * 64, wn = (warp & 3) * 64;

    const int cr = tid >> 3, cko = (tid & 7) * 8;
    const __nv_bfloat16* Ag = A + (size_t)(m0 + cr) * KW + cko;
    const __nv_bfloat16* Bg = Bm + (size_t)(n0g + cr) * KW + cko;
    const uint32_t sAo = (cr * AST + cko) * 2;

    float acc[4][8][4];
#pragma unroll
    for (int i = 0; i < 4; i++)
#pragma unroll
        for (int j = 0; j < 8; j++)
#pragma unroll
            for (int p = 0; p < 4; p++) acc[i][j][p] = 0.f;

#pragma unroll
    for (int i = 0; i < 4; i++)
        cpasync16(sb + sAo + i * 32 * AST * 2, Ag + (size_t)(i * 32) * KW);
#pragma unroll
    for (int i = 0; i < 8; i++)
        cpasync16(sb + TA + sAo + i * 32 * AST * 2, Bg + (size_t)(i * 32) * KW);
    CP_COMMIT();

    const int NCH = 48;
    for (int c = 0; c < NCH; c++) {
        const int p = c & 1;
        if (c + 1 < NCH) {
            const int pn = (c + 1) & 1;
            const int cn = c + 1;
            const int aoff = (cn < 16) ? cn * 64 : cn * 64 - 1024;
            const int boff = (cn < 32) ? cn * 64 : cn * 64 - 2048;
#pragma unroll
            for (int i = 0; i < 4; i++)
                cpasync16(sb + pn * (TA + TB) + sAo + i * 32 * AST * 2,
                          Ag + (size_t)(i * 32) * KW + aoff);
#pragma unroll
            for (int i = 0; i < 8; i++)
                cpasync16(sb + pn * (TA + TB) + TA + sAo + i * 32 * AST * 2,
                          Bg + (size_t)(i * 32) * KW + boff);
            CP_COMMIT();
            CP_WAIT(1);
        } else {
            CP_WAIT(0);
        }
        __syncthreads();

        const uint32_t aw = sb + p * (TA + TB) +
                            ((wm + (lane & 15)) * AST + (lane >> 4) * 8) * 2;
        const uint32_t bw = sb + p * (TA + TB) + TA +
                            ((wn + (lane & 15)) * AST + (lane >> 4) * 8) * 2;
#pragma unroll
        for (int k16 = 0; k16 < 4; k16++) {
            const uint32_t ko = k16 * 32;
            uint32_t a[4][4], b[4][4];
#pragma unroll
            for (int mt = 0; mt < 4; mt++)
                ldsm4(a[mt][0], a[mt][1], a[mt][2], a[mt][3],
                      aw + mt * 16 * AST * 2 + ko);
#pragma unroll
            for (int nb = 0; nb < 4; nb++)
                ldsm4(b[nb][0], b[nb][1], b[nb][2], b[nb][3],
                      bw + nb * 16 * AST * 2 + ko);
#pragma unroll
            for (int mt = 0; mt < 4; mt++)
#pragma unroll
                for (int nb = 0; nb < 4; nb++) {
                    mma16816(acc[mt][2 * nb], a[mt][0], a[mt][1], a[mt][2], a[mt][3],
                             b[nb][0], b[nb][2]);
                    mma16816(acc[mt][2 * nb + 1], a[mt][0], a[mt][1], a[mt][2], a[mt][3],
                             b[nb][1], b[nb][3]);
                }
        }
        __syncthreads();
    }

#pragma unroll
    for (int nt = 0; nt < 8; nt++) {
        const int n = n0g + wn + nt * 8 + (lane & 3) * 2;
        const int wsel = n >> 10, nn = n & 1023;
        const float* bias = (wsel == 0) ? bq : (wsel == 1) ? bk : bv;
        __nv_bfloat16* ph;
        __nv_bfloat16* pl;
        if (inst) {
            ph = (wsel == 1) ? oIKh : oIVh;
            pl = (wsel == 1) ? oIKl : oIVl;
        } else {
            ph = (wsel == 0) ? oQh : (wsel == 1) ? oKh : oVh;
            pl = (wsel == 0) ? oQl : (wsel == 1) ? oKl : oVl;
        }
        const float b0 = bias[nn], b1 = bias[nn + 1];
        const size_t hoff = ((size_t)(nn >> 6)) * Slen;
        const int d = nn & 63;
#pragma unroll
        for (int mt = 0; mt < 4; mt++) {
#pragma unroll
            for (int half = 0; half < 2; half++) {
                const int r = m0 + wm + mt * 16 + (lane >> 2) + half * 8;
                const int bb = r >> msh, t = r - (bb << msh);
                float vx = acc[mt][nt][half * 2 + 0] + b0;
                float vy = acc[mt][nt][half * 2 + 1] + b1;
                __nv_bfloat16 hx = __float2bfloat16(vx);
                __nv_bfloat16 hy = __float2bfloat16(vy);
                float lxf = vx - __bfloat162float(hx);
                float lyf = vy - __bfloat162float(hy);
                size_t off = ((size_t)bb * NH * Slen + hoff + t) * DH + d;
                *(uint32_t*)(ph + off) =
                    (uint32_t)__bfloat16_as_ushort(hx) |
                    ((uint32_t)__bfloat16_as_ushort(hy) << 16);
                *(uint32_t*)(pl + off) = pk2(lxf, lyf);
            }
        }
    }
}

// ---------------------------------------------------------------------------
// Tensor-core attention v2: 2 CTAs/SM (106.5 KB smem), single-buffered KV/E,
// SPH/SPL aliased onto the dead E slot, register-lean MMA paths.
// ---------------------------------------------------------------------------
#define PST 72
#define P12 132
#define A_SQH 0
#define A_SQL 9216
#define A_KH 18432
#define A_KL 27648
#define A_EP 36864            // E (phase1) / SPH+SPL (phases 2-3)
#define A_SPH A_EP
#define A_SPL (A_EP + 9216)
#define A_VH 55296
#define A_VL 64512
#define A_SP1 73728           // 64*132*2 = 16896
#define A_SP2 90624
#define A_CORR 107520
#define A_SSM 107776
#define A_SSI 108032
#define A_AMSK 108288
#define A_IMSK 108544
#define A_TOTAL 109056

__device__ __forceinline__ void cpa_tile64(uint32_t sb, int dstoff,
                                           const __nv_bfloat16* src, int tid)
{
#pragma unroll
    for (int it = 0; it < 2; it++) {
        int i = tid + it * 256;
        int r = i >> 3, c = (i & 7) * 8;
        cpasync16(sb + dstoff + (r * PST + c) * 2, src + r * 64 + c);
    }
}
__device__ __forceinline__ float ldbf(const char* sm, int base, int idx) {
    return __bfloat162float(*(const __nv_bfloat16*)(sm + base + idx * 2));
}

// QK 3-term split (register-lean nb-inner ordering).
__device__ __forceinline__ void qk_tile(float sacc[8][4], uint32_t sb,
                                        int wm, int lane)
{
#pragma unroll
    for (int k = 0; k < 4; k++) {
        const uint32_t ko = (k * 16 + (lane >> 4) * 8) * 2;
        uint32_t aH[4], aL[4];
        ldsm4(aH[0], aH[1], aH[2], aH[3],
              sb + A_SQH + (wm + (lane & 15)) * PST * 2 + ko);
        ldsm4(aL[0], aL[1], aL[2], aL[3],
              sb + A_SQL + (wm + (lane & 15)) * PST * 2 + ko);
#pragma unroll
        for (int nb = 0; nb < 4; nb++) {
            uint32_t bH[4], bL[4];
            ldsm4(bH[0], bH[1], bH[2], bH[3],
                  sb + A_KH + (nb * 16 + (lane & 15)) * PST * 2 + ko);
            ldsm4(bL[0], bL[1], bL[2], bL[3],
                  sb + A_KL + (nb * 16 + (lane & 15)) * PST * 2 + ko);
            mma16816(sacc[2 * nb], aH[0], aH[1], aH[2], aH[3], bH[0], bH[2]);
            mma16816(sacc[2 * nb + 1], aH[0], aH[1], aH[2], aH[3], bH[1], bH[3]);
            mma16816(sacc[2 * nb], aH[0], aH[1], aH[2], aH[3], bL[0], bL[2]);
            mma16816(sacc[2 * nb + 1], aH[0], aH[1], aH[2], aH[3], bL[1], bL[3]);
            mma16816(sacc[2 * nb], aL[0], aL[1], aL[2], aL[3], bH[0], bH[2]);
            mma16816(sacc[2 * nb + 1], aL[0], aL[1], aL[2], aL[3], bH[1], bH[3]);
        }
    }
}

// PV 3-term split (register-lean).
__device__ __forceinline__ void pv_tile(float cacc[4][4], uint32_t sb,
                                        int wm2, int wn2, int lane)
{
#pragma unroll
    for (int kk = 0; kk < 4; kk++) {
        const uint32_t ko = (kk * 16 + (lane >> 4) * 8) * 2;
        uint32_t aPh[4], aPl[4];
        ldsm4(aPh[0], aPh[1], aPh[2], aPh[3],
              sb + A_SPH + (wm2 + (lane & 15)) * PST * 2 + ko);
        ldsm4(aPl[0], aPl[1], aPl[2], aPl[3],
              sb + A_SPL + (wm2 + (lane & 15)) * PST * 2 + ko);
        const uint32_t trow = (kk * 16 + (lane & 7) + 8 * ((lane >> 3) & 1)) * PST;
#pragma unroll
        for (int dh = 0; dh < 2; dh++) {
            const uint32_t tcol = wn2 + dh * 16 + ((lane >> 4) & 1) * 8;
            uint32_t vh[4], vl[4];
            ldsm4t(vh[0], vh[1], vh[2], vh[3], sb + A_VH + (trow + tcol) * 2);
            ldsm4t(vl[0], vl[1], vl[2], vl[3], sb + A_VL + (trow + tcol) * 2);
            const int nf = dh * 2;
            mma16816(cacc[nf], aPh[0], aPh[1], aPh[2], aPh[3], vh[0], vh[1]);
            mma16816(cacc[nf + 1], aPh[0], aPh[1], aPh[2], aPh[3], vh[2], vh[3]);
            mma16816(cacc[nf], aPh[0], aPh[1], aPh[2], aPh[3], vl[0], vl[1]);
            mma16816(cacc[nf + 1], aPh[0], aPh[1], aPh[2], aPh[3], vl[2], vl[3]);
            mma16816(cacc[nf], aPl[0], aPl[1], aPl[2], aPl[3], vh[0], vh[1]);
            mma16816(cacc[nf + 1], aPl[0], aPl[1], aPl[2], aPl[3], vh[2], vh[3]);
        }
    }
}

__global__ __launch_bounds__(256, 2)
void attn_mma(const float* __restrict__ amask, const float* __restrict__ imask,
              const float* __restrict__ gate, float* __restrict__ outp)
{
    extern __shared__ char sm[];
    const uint32_t sb = smem_u32(sm);
    const int tid = threadIdx.x, warp = tid >> 5, lane = tid & 31;
    const int g = lane >> 2, t4 = lane & 3;
    const int bh = blockIdx.y, b = bh >> 4, h = bh & 15;
    const int l0 = blockIdx.x * 64;
    const int wm = warp * 16;
    const int wm2 = (warp >> 1) * 16, wn2 = (warp & 1) * 32;

    // Q (persistent) via cp.async
    cpa_tile64(sb, A_SQH, g_Qh + ((size_t)bh * SQ + l0) * DH, tid);
    cpa_tile64(sb, A_SQL, g_Ql + ((size_t)bh * SQ + l0) * DH, tid);
    if (tid < 32)
        ((float4*)(sm + A_IMSK))[tid] = ((const float4*)(imask + b * LI))[tid];

    float cacc[4][4];
#pragma unroll
    for (int i = 0; i < 4; i++)
#pragma unroll
        for (int j = 0; j < 4; j++) cacc[i][j] = 0.f;
    float mrow[2] = {-1e30f, -1e30f}, ssum[2] = {0.f, 0.f};
    float* corr_sm = (float*)(sm + A_CORR);
    const float* amsk = (const float*)(sm + A_AMSK);
    const float* imsk = (const float*)(sm + A_IMSK);

    // ======================= main pass =======================
    for (int rt = 0; rt < 16; rt++) {
        const int r0 = rt * 64;
        // single-buffer loads (prev PV's SPH/SPL reads done at loop-entry barrier)
        cpa_tile64(sb, A_KH, g_Kh + ((size_t)bh * SQ + r0) * DH, tid);
        cpa_tile64(sb, A_KL, g_Kl + ((size_t)bh * SQ + r0) * DH, tid);
        cpa_tile64(sb, A_VH, g_Vh + ((size_t)bh * SQ + r0) * DH, tid);
        cpa_tile64(sb, A_VL, g_Vl + ((size_t)bh * SQ + r0) * DH, tid);
        {
            const __nv_bfloat16* Eg = g_Eh + (size_t)(l0 - r0 + 960) * 64;
#pragma unroll
            for (int it = 0; it < 4; it++) {
                int i = tid + it * 256;
                int r = i >> 3, c = (i & 7) * 8;
                cpasync16(sb + A_EP + (r * PST + c) * 2, Eg + r * 64 + c);
            }
        }
        if (tid < 64) ((float*)(sm + A_AMSK))[tid] = amask[b * SQ + r0 + tid];
        CP_COMMIT();
        CP_WAIT(0);
        __syncthreads();

        float sacc[8][4];
        if (warp < 4) {
#pragma unroll
            for (int j = 0; j < 8; j++)
#pragma unroll
                for (int p = 0; p < 4; p++) sacc[j][p] = 0.f;
            qk_tile(sacc, sb, wm, lane);
        } else {
            const int isP2 = (warp >= 6);
            const int m0p = (warp - (isP2 ? 6 : 4)) * 32;
            const int srcA = isP2 ? A_KH : A_SQH;
            const int dstP = isP2 ? A_SP2 : A_SP1;
#pragma unroll
            for (int ch = 0; ch < 2; ch++) {
#pragma unroll
                for (int s = 0; s < 2; s++) {
                    float pacc[8][4];
#pragma unroll
                    for (int j = 0; j < 8; j++)
#pragma unroll
                        for (int p = 0; p < 4; p++) pacc[j][p] = 0.f;
#pragma unroll
                    for (int k = 0; k < 4; k++) {
                        const uint32_t ko = (k * 16 + (lane >> 4) * 8) * 2;
                        uint32_t aU[4];
                        ldsm4(aU[0], aU[1], aU[2], aU[3],
                              sb + srcA + (m0p + s * 16 + (lane & 15)) * PST * 2 + ko);
#pragma unroll
                        for (int nb = 0; nb < 4; nb++) {
                            uint32_t be[4];
                            ldsm4(be[0], be[1], be[2], be[3],
                                  sb + A_EP + (ch * 64 + nb * 16 + (lane & 15)) * PST * 2 + ko);
                            mma16816(pacc[2 * nb], aU[0], aU[1], aU[2], aU[3], be[0], be[2]);
                            mma16816(pacc[2 * nb + 1], aU[0], aU[1], aU[2], aU[3], be[1], be[3]);
                        }
                    }
#pragma unroll
                    for (int j = 0; j < 8; j++) {
                        int l = m0p + s * 16 + g;
                        int w = ch * 64 + 8 * j + 2 * t4;
                        *(uint32_t*)(sm + dstP + (l * P12 + w) * 2) =
                            pk2(pacc[j][0], pacc[j][1]);
                        *(uint32_t*)(sm + dstP + ((l + 8) * P12 + w) * 2) =
                            pk2(pacc[j][2], pacc[j][3]);
                    }
                }
            }
        }
        __syncthreads();   // E dead from here; SPH/SPL may now occupy its slot

        if (warp < 4) {
            const int l = wm + g;
#pragma unroll
            for (int j = 0; j < 8; j++) {
                const int r = 8 * j + 2 * t4;
                const int w = l - r + 63;
                sacc[j][0] = (sacc[j][0] + ldbf(sm, A_SP1, l * P12 + w)
                              + ldbf(sm, A_SP2, r * P12 + w)) * 0.125f + amsk[r];
                sacc[j][1] = (sacc[j][1] + ldbf(sm, A_SP1, l * P12 + w - 1)
                              + ldbf(sm, A_SP2, (r + 1) * P12 + w - 1)) * 0.125f + amsk[r + 1];
                sacc[j][2] = (sacc[j][2] + ldbf(sm, A_SP1, (l + 8) * P12 + w + 8)
                              + ldbf(sm, A_SP2, r * P12 + w + 8)) * 0.125f + amsk[r];
                sacc[j][3] = (sacc[j][3] + ldbf(sm, A_SP1, (l + 8) * P12 + w + 7)
                              + ldbf(sm, A_SP2, (r + 1) * P12 + w + 7)) * 0.125f + amsk[r + 1];
            }
            float mt0 = -1e30f, mt1 = -1e30f;
#pragma unroll
            for (int j = 0; j < 8; j++) {
                mt0 = fmaxf(mt0, fmaxf(sacc[j][0], sacc[j][1]));
                mt1 = fmaxf(mt1, fmaxf(sacc[j][2], sacc[j][3]));
            }
            mt0 = fmaxf(mt0, __shfl_xor_sync(0xffffffffu, mt0, 1));
            mt0 = fmaxf(mt0, __shfl_xor_sync(0xffffffffu, mt0, 2));
            mt1 = fmaxf(mt1, __shfl_xor_sync(0xffffffffu, mt1, 1));
            mt1 = fmaxf(mt1, __shfl_xor_sync(0xffffffffu, mt1, 2));
            float mn0 = fmaxf(mrow[0], mt0), mn1 = fmaxf(mrow[1], mt1);
            float cr0 = __expf(mrow[0] - mn0), cr1 = __expf(mrow[1] - mn1);
            mrow[0] = mn0; mrow[1] = mn1;
            float ps0 = 0.f, ps1 = 0.f;
#pragma unroll
            for (int j = 0; j < 8; j++) {
                float p00 = __expf(sacc[j][0] - mn0), p01 = __expf(sacc[j][1] - mn0);
                float p10 = __expf(sacc[j][2] - mn1), p11 = __expf(sacc[j][3] - mn1);
                ps0 += p00 + p01; ps1 += p10 + p11;
                int cidx = 8 * j + 2 * t4;
                uint32_t h0 = pk2(p00, p01), h1 = pk2(p10, p11);
                *(uint32_t*)(sm + A_SPH + (l * PST + cidx) * 2) = h0;
                *(uint32_t*)(sm + A_SPH + ((l + 8) * PST + cidx) * 2) = h1;
                __nv_bfloat162 hh0 = *(__nv_bfloat162*)&h0;
                __nv_bfloat162 hh1 = *(__nv_bfloat162*)&h1;
                *(uint32_t*)(sm + A_SPL + (l * PST + cidx) * 2) =
                    pk2(p00 - __bfloat162float(hh0.x), p01 - __bfloat162float(hh0.y));
                *(uint32_t*)(sm + A_SPL + ((l + 8) * PST + cidx) * 2) =
                    pk2(p10 - __bfloat162float(hh1.x), p11 - __bfloat162float(hh1.y));
            }
            ps0 += __shfl_xor_sync(0xffffffffu, ps0, 1);
            ps0 += __shfl_xor_sync(0xffffffffu, ps0, 2);
            ps1 += __shfl_xor_sync(0xffffffffu, ps1, 1);
            ps1 += __shfl_xor_sync(0xffffffffu, ps1, 2);
            ssum[0] = ssum[0] * cr0 + ps0;
            ssum[1] = ssum[1] * cr1 + ps1;
            if (t4 == 0) { corr_sm[l] = cr0; corr_sm[l + 8] = cr1; }
        }
        __syncthreads();

        {
            float c0r = corr_sm[wm2 + g], c1r = corr_sm[wm2 + 8 + g];
#pragma unroll
            for (int nf = 0; nf < 4; nf++) {
                cacc[nf][0] *= c0r; cacc[nf][1] *= c0r;
                cacc[nf][2] *= c1r; cacc[nf][3] *= c1r;
            }
            pv_tile(cacc, sb, wm2, wn2, lane);
        }
        __syncthreads();   // SPH/SPL reads done; next tile may overwrite E slot
    }

    // stash main ctx + ssum, reset
    {
        float* stash = (float*)(sm + A_SP1);   // 64x68 floats spans SP1+SP2
#pragma unroll
        for (int nf = 0; nf < 4; nf++) {
            int d = wn2 + 8 * nf + 2 * t4;
            stash[(wm2 + g) * 68 + d] = cacc[nf][0];
            stash[(wm2 + g) * 68 + d + 1] = cacc[nf][1];
            stash[(wm2 + 8 + g) * 68 + d] = cacc[nf][2];
            stash[(wm2 + 8 + g) * 68 + d + 1] = cacc[nf][3];
            cacc[nf][0] = cacc[nf][1] = cacc[nf][2] = cacc[nf][3] = 0.f;
        }
        if (warp < 4 && t4 == 0) {
            ((float*)(sm + A_SSM))[wm + g] = ssum[0];
            ((float*)(sm + A_SSM))[wm + g + 8] = ssum[1];
        }
        mrow[0] = mrow[1] = -1e30f; ssum[0] = ssum[1] = 0.f;
    }
    __syncthreads();

    // ======================= instruct pass =======================
    for (int rt = 0; rt < 2; rt++) {
        const int r0 = rt * 64;
        cpa_tile64(sb, A_KH, g_IKh + ((size_t)bh * LI + r0) * DH, tid);
        cpa_tile64(sb, A_KL, g_IKl + ((size_t)bh * LI + r0) * DH, tid);
        cpa_tile64(sb, A_VH, g_IVh + ((size_t)bh * LI + r0) * DH, tid);
        cpa_tile64(sb, A_VL, g_IVl + ((size_t)bh * LI + r0) * DH, tid);
        CP_COMMIT();
        CP_WAIT(0);
        __syncthreads();

        if (warp < 4) {
            float sacc[8][4];
#pragma unroll
            for (int j = 0; j < 8; j++)
#pragma unroll
                for (int p = 0; p < 4; p++) sacc[j][p] = 0.f;
            qk_tile(sacc, sb, wm, lane);

            const int l = wm + g;
            float mt0 = -1e30f, mt1 = -1e30f;
#pragma unroll
            for (int j = 0; j < 8; j++) {
                const int r = 8 * j + 2 * t4;
                sacc[j][0] = sacc[j][0] * 0.125f + imsk[r0 + r];
                sacc[j][1] = sacc[j][1] * 0.125f + imsk[r0 + r + 1];
                sacc[j][2] = sacc[j][2] * 0.125f + imsk[r0 + r];
                sacc[j][3] = sacc[j][3] * 0.125f + imsk[r0 + r + 1];
                mt0 = fmaxf(mt0, fmaxf(sacc[j][0], sacc[j][1]));
                mt1 = fmaxf(mt1, fmaxf(sacc[j][2], sacc[j][3]));
            }
            mt0 = fmaxf(mt0, __shfl_xor_sync(0xffffffffu, mt0, 1));
            mt0 = fmaxf(mt0, __shfl_xor_sync(0xffffffffu, mt0, 2));
            mt1 = fmaxf(mt1, __shfl_xor_sync(0xffffffffu, mt1, 1));
            mt1 = fmaxf(mt1, __shfl_xor_sync(0xffffffffu, mt1, 2));
            float mn0 = fmaxf(mrow[0], mt0), mn1 = fmaxf(mrow[1], mt1);
            float cr0 = __expf(mrow[0] - mn0), cr1 = __expf(mrow[1] - mn1);
            mrow[0] = mn0; mrow[1] = mn1;
            float ps0 = 0.f, ps1 = 0.f;
#pragma unroll
            for (int j = 0; j < 8; j++) {
                float p00 = __expf(sacc[j][0] - mn0), p01 = __expf(sacc[j][1] - mn0);
                float p10 = __expf(sacc[j][2] - mn1), p11 = __expf(sacc[j][3] - mn1);
                ps0 += p00 + p01; ps1 += p10 + p11;
                int cidx = 8 * j + 2 * t4;
                uint32_t h0 = pk2(p00, p01), h1 = pk2(p10, p11);
                *(uint32_t*)(sm + A_SPH + (l * PST + cidx) * 2) = h0;
                *(uint32_t*)(sm + A_SPH + ((l + 8) * PST + cidx) * 2) = h1;
                __nv_bfloat162 hh0 = *(__nv_bfloat162*)&h0;
                __nv_bfloat162 hh1 = *(__nv_bfloat162*)&h1;
                *(uint32_t*)(sm + A_SPL + (l * PST + cidx) * 2) =
                    pk2(p00 - __bfloat162float(hh0.x), p01 - __bfloat162float(hh0.y));
                *(uint32_t*)(sm + A_SPL + ((l + 8) * PST + cidx) * 2) =
                    pk2(p10 - __bfloat162float(hh1.x), p11 - __bfloat162float(hh1.y));
            }
            ps0 += __shfl_xor_sync(0xffffffffu, ps0, 1);
            ps0 += __shfl_xor_sync(0xffffffffu, ps0, 2);
            ps1 += __shfl_xor_sync(0xffffffffu, ps1, 1);
            ps1 += __shfl_xor_sync(0xffffffffu, ps1, 2);
            ssum[0] = ssum[0] * cr0 + ps0;
            ssum[1] = ssum[1] * cr1 + ps1;
            if (t4 == 0) { corr_sm[l] = cr0; corr_sm[l + 8] = cr1; }
        }
        __syncthreads();

        {
            float c0r = corr_sm[wm2 + g], c1r = corr_sm[wm2 + 8 + g];
#pragma unroll
            for (int nf = 0; nf < 4; nf++) {
                cacc[nf][0] *= c0r; cacc[nf][1] *= c0r;
                cacc[nf][2] *= c1r; cacc[nf][3] *= c1r;
            }
            pv_tile(cacc, sb, wm2, wn2, lane);
        }
        __syncthreads();
    }

    if (warp < 4 && t4 == 0) {
        ((float*)(sm + A_SSI))[wm + g] = ssum[0];
        ((float*)(sm + A_SSI))[wm + g + 8] = ssum[1];
    }
    __syncthreads();

    {
        const float tg = tanhf(gate[h]);
        const float* stash = (const float*)(sm + A_SP1);
        const float* ssmv = (const float*)(sm + A_SSM);
        const float* ssiv = (const float*)(sm + A_SSI);
        const float rnm0 = 1.f / ssmv[wm2 + g], rni0 = tg / ssiv[wm2 + g];
        const float rnm1 = 1.f / ssmv[wm2 + 8 + g], rni1 = tg / ssiv[wm2 + 8 + g];
#pragma unroll
        for (int nf = 0; nf < 4; nf++) {
            const int d = wn2 + 8 * nf + 2 * t4;
            float2 o0, o1;
            o0.x = stash[(wm2 + g) * 68 + d] * rnm0 + cacc[nf][0] * rni0;
            o0.y = stash[(wm2 + g) * 68 + d + 1] * rnm0 + cacc[nf][1] * rni0;
            o1.x = stash[(wm2 + 8 + g) * 68 + d] * rnm1 + cacc[nf][2] * rni1;
            o1.y = stash[(wm2 + 8 + g) * 68 + d + 1] * rnm1 + cacc[nf][3] * rni1;
            *(float2*)(outp + ((size_t)(b * SQ + l0 + wm2 + g)) * HIDDEN + h * DH + d) = o0;
            *(float2*)(outp + ((size_t)(b * SQ + l0 + wm2 + 8 + g)) * HIDDEN + h * DH + d) = o1;
        }
    }
}

// ---------------------------------------------------------------------------
extern "C" void kernel_launch(void* const* d_in, const int* in_sizes, int n_in,
                              void* d_out, int out_size)
{
    (void)in_sizes; (void)n_in; (void)out_size;
    const float* hs    = (const float*)d_in[0];
    const float* amask = (const float*)d_in[1];
    const float* ihs   = (const float*)d_in[2];
    const float* imask = (const float*)d_in[3];
    const float* Wq    = (const float*)d_in[4];
    const float* bq    = (const float*)d_in[5];
    const float* Wk    = (const float*)d_in[6];
    const float* bk    = (const float*)d_in[7];
    const float* Wv    = (const float*)d_in[8];
    const float* bv    = (const float*)d_in[9];
    const float* gate  = (const float*)d_in[10];
    const float* dist  = (const float*)d_in[11];
    float* out = (float*)d_out;

    __nv_bfloat16 *qh, *ql, *kh, *kl, *vh, *vl, *ikh, *ikl, *ivh, *ivl, *eh;
    __nv_bfloat16 *xc, *ixc, *wc;
    cudaGetSymbolAddress((void**)&qh, g_Qh);
    cudaGetSymbolAddress((void**)&ql, g_Ql);
    cudaGetSymbolAddress((void**)&kh, g_Kh);
    cudaGetSymbolAddress((void**)&kl, g_Kl);
    cudaGetSymbolAddress((void**)&vh, g_Vh);
    cudaGetSymbolAddress((void**)&vl, g_Vl);
    cudaGetSymbolAddress((void**)&ikh, g_IKh);
    cudaGetSymbolAddress((void**)&ikl, g_IKl);
    cudaGetSymbolAddress((void**)&ivh, g_IVh);
    cudaGetSymbolAddress((void**)&ivl, g_IVl);
    cudaGetSymbolAddress((void**)&eh, g_Eh);
    cudaGetSymbolAddress((void**)&xc, g_Xcat);
    cudaGetSymbolAddress((void**)&ixc, g_IXcat);
    cudaGetSymbolAddress((void**)&wc, g_Wcat);

    cudaFuncSetAttribute(gemm_mma, cudaFuncAttributeMaxDynamicSharedMemorySize, GEMM_SMEM);
    cudaFuncSetAttribute(attn_mma, cudaFuncAttributeMaxDynamicSharedMemorySize, A_TOTAL);

    conv_all<<<NX_MAIN + NX_INST + NX_E, 256>>>((const float4*)hs, xc,
                                                (const float4*)ihs, ixc, dist, eh);
    conv_w<<<dim3(32, 32, 3), 256>>>(Wq, Wk, Wv, wc);

    gemm_mma<<<416, 256, GEMM_SMEM>>>(xc, ixc, wc, bq, bk, bv,
                                      qh, ql, kh, kl, vh, vl,
                                      ikh, ikl, ivh, ivl);

    attn_mma<<<dim3(SQ / 64, BHN), 256, A_TOTAL>>>(amask, imask, gate, out);
}

// round 10
// speedup vs baseline: 1.1165x; 1.0946x over previous
#include <cuda_runtime.h>
#include <cuda_bf16.h>
#include <cuda_fp16.h>
#include <math.h>
#include <cstdint>

#define NB 4
#define NH 16
#define DH 64
#define SQ 1024
#define LI 128
#define HIDDEN 1024
#define BHN (NB * NH)
#define KW 2048   // stored operand width (hi|lo)

// ---------------- scratch ---------------------------------------------------
__device__ __align__(16) __nv_bfloat16 g_Qh[BHN * SQ * DH];
__device__ __align__(16) __nv_bfloat16 g_Ql[BHN * SQ * DH];
__device__ __align__(16) __nv_bfloat16 g_Kh[BHN * SQ * DH];
__device__ __align__(16) __nv_bfloat16 g_Kl[BHN * SQ * DH];
__device__ __align__(16) __half        g_Vf[BHN * SQ * DH];
__device__ __align__(16) __nv_bfloat16 g_IKh[BHN * LI * DH];
__device__ __align__(16) __nv_bfloat16 g_IKl[BHN * LI * DH];
__device__ __align__(16) __half        g_IVf[BHN * LI * DH];
__device__ __align__(16) __nv_bfloat16 g_Eh[2048 * DH];

__device__ __align__(16) __nv_bfloat16 g_Xcat[NB * SQ * KW];
__device__ __align__(16) __nv_bfloat16 g_IXcat[NB * LI * KW];
__device__ __align__(16) __nv_bfloat16 g_Wcat[3 * HIDDEN * KW];

// ---------------- helpers ---------------------------------------------------
__device__ __forceinline__ uint32_t smem_u32(const void* p) {
    uint32_t a;
    asm("{ .reg .u64 t; cvta.to.shared.u64 t, %1; cvt.u32.u64 %0, t; }" : "=r"(a) : "l"(p));
    return a;
}
__device__ __forceinline__ void ldsm4(uint32_t& r0, uint32_t& r1, uint32_t& r2,
                                      uint32_t& r3, uint32_t addr) {
    asm volatile("ldmatrix.sync.aligned.m8n8.x4.shared.b16 {%0,%1,%2,%3}, [%4];"
                 : "=r"(r0), "=r"(r1), "=r"(r2), "=r"(r3) : "r"(addr));
}
__device__ __forceinline__ void ldsm4t(uint32_t& r0, uint32_t& r1, uint32_t& r2,
                                       uint32_t& r3, uint32_t addr) {
    asm volatile("ldmatrix.sync.aligned.m8n8.x4.trans.shared.b16 {%0,%1,%2,%3}, [%4];"
                 : "=r"(r0), "=r"(r1), "=r"(r2), "=r"(r3) : "r"(addr));
}
__device__ __forceinline__ void mma16816(float* c, uint32_t a0, uint32_t a1,
                                         uint32_t a2, uint32_t a3,
                                         uint32_t b0, uint32_t b1) {
    asm volatile(
        "mma.sync.aligned.m16n8k16.row.col.f32.bf16.bf16.f32 "
        "{%0,%1,%2,%3}, {%4,%5,%6,%7}, {%8,%9}, {%0,%1,%2,%3};"
        : "+f"(c[0]), "+f"(c[1]), "+f"(c[2]), "+f"(c[3])
        : "r"(a0), "r"(a1), "r"(a2), "r"(a3), "r"(b0), "r"(b1));
}
__device__ __forceinline__ void mma16816h(float* c, uint32_t a0, uint32_t a1,
                                          uint32_t a2, uint32_t a3,
                                          uint32_t b0, uint32_t b1) {
    asm volatile(
        "mma.sync.aligned.m16n8k16.row.col.f32.f16.f16.f32 "
        "{%0,%1,%2,%3}, {%4,%5,%6,%7}, {%8,%9}, {%0,%1,%2,%3};"
        : "+f"(c[0]), "+f"(c[1]), "+f"(c[2]), "+f"(c[3])
        : "r"(a0), "r"(a1), "r"(a2), "r"(a3), "r"(b0), "r"(b1));
}
__device__ __forceinline__ uint32_t pk2(float a, float b) {
    __nv_bfloat162 t = __floats2bfloat162_rn(a, b);
    return *(uint32_t*)&t;
}
__device__ __forceinline__ uint32_t pk2h(float a, float b) {
    __half2 t = __floats2half2_rn(a, b);
    return *(uint32_t*)&t;
}
__device__ __forceinline__ void cpasync16(uint32_t dst, const void* src) {
    asm volatile("cp.async.cg.shared.global [%0], [%1], 16;" :: "r"(dst), "l"(src));
}
#define CP_COMMIT() asm volatile("cp.async.commit_group;" ::: "memory")
#define CP_WAIT(n)  asm volatile("cp.async.wait_group %0;" :: "n"(n) : "memory")

// ---------------------------------------------------------------------------
// Conversions: X-main / X-instruct / E / W-transpose merged into ONE launch.
// ---------------------------------------------------------------------------
#define NX_MAIN (NB * SQ * HIDDEN / 4 / 256)     // 4096
#define NX_INST (NB * LI * HIDDEN / 4 / 256)     // 512
#define NX_E    (2048 * 64 / 256)                // 512
#define NX_W    3072
#define NX_BASE3 (NX_MAIN + NX_INST + NX_E)

__global__ __launch_bounds__(256)
void conv_all(const float4* __restrict__ xm, __nv_bfloat16* __restrict__ dm,
              const float4* __restrict__ xi, __nv_bfloat16* __restrict__ di,
              const float* __restrict__ dist, __nv_bfloat16* __restrict__ eh,
              const float* __restrict__ Wq, const float* __restrict__ Wk,
              const float* __restrict__ Wv, __nv_bfloat16* __restrict__ wdst)
{
    __shared__ float t[32][33];
    int blk = blockIdx.x;
    if (blk >= NX_BASE3) {
        // W transpose + split
        int wblk = blk - NX_BASE3;
        int z = wblk >> 10, rem = wblk & 1023;
        int bx = rem & 31, by = rem >> 5;
        const float* W = (z == 0) ? Wq : (z == 1) ? Wk : Wv;
        int tx = threadIdx.x & 31, ty = threadIdx.x >> 5;
        int n = bx * 32 + tx, k0 = by * 32;
#pragma unroll
        for (int j = 0; j < 4; j++)
            t[ty + 8 * j][tx] = W[(size_t)(k0 + ty + 8 * j) * HIDDEN + n];
        __syncthreads();
        size_t nrow = (size_t)z * HIDDEN + bx * 32;
#pragma unroll
        for (int j = 0; j < 4; j++) {
            float v = t[tx][ty + 8 * j];
            __nv_bfloat16 h = __float2bfloat16(v);
            __nv_bfloat16 l = __float2bfloat16(v - __bfloat162float(h));
            __nv_bfloat16* o = wdst + (nrow + ty + 8 * j) * KW + k0 + tx;
            o[0]    = h;
            o[1024] = l;
        }
        return;
    }
    if (blk >= NX_MAIN + NX_INST) {
        int i = (blk - NX_MAIN - NX_INST) * 256 + threadIdx.x;
        float v = (i < 2047 * 64) ? dist[i] : 0.f;
        eh[i] = __float2bfloat16(v);
        return;
    }
    const float4* src = (blk < NX_MAIN) ? xm : xi;
    __nv_bfloat16* dst = (blk < NX_MAIN) ? dm : di;
    int i = ((blk < NX_MAIN) ? blk : blk - NX_MAIN) * 256 + threadIdx.x;
    int row = i >> 8, c4 = (i & 255) * 4;
    float4 v = src[i];
    __nv_bfloat16 hx = __float2bfloat16(v.x), hy = __float2bfloat16(v.y);
    __nv_bfloat16 hz = __float2bfloat16(v.z), hw = __float2bfloat16(v.w);
    __nv_bfloat16 lx = __float2bfloat16(v.x - __bfloat162float(hx));
    __nv_bfloat16 ly = __float2bfloat16(v.y - __bfloat162float(hy));
    __nv_bfloat16 lz = __float2bfloat16(v.z - __bfloat162float(hz));
    __nv_bfloat16 lw = __float2bfloat16(v.w - __bfloat162float(hw));
    uint2 H, L;
    H.x = (uint32_t)__bfloat16_as_ushort(hx) | ((uint32_t)__bfloat16_as_ushort(hy) << 16);
    H.y = (uint32_t)__bfloat16_as_ushort(hz) | ((uint32_t)__bfloat16_as_ushort(hw) << 16);
    L.x = (uint32_t)__bfloat16_as_ushort(lx) | ((uint32_t)__bfloat16_as_ushort(ly) << 16);
    L.y = (uint32_t)__bfloat16_as_ushort(lz) | ((uint32_t)__bfloat16_as_ushort(lw) << 16);
    __nv_bfloat16* rb = dst + (size_t)row * KW + c4;
    *(uint2*)(rb)        = H;
    *(uint2*)(rb + 1024) = L;
}

// ---------------------------------------------------------------------------
// Merged projection GEMM: CTA 128x256, warp 64x64. Q/K -> bf16 hi/lo; V -> fp16.
// ---------------------------------------------------------------------------
#define KC 64
#define AST 72
#define TA (128 * AST * 2)
#define TB (256 * AST * 2)
#define GEMM_SMEM (2 * (TA + TB))

__global__ __launch_bounds__(256, 1)
void gemm_mma(const __nv_bfloat16* __restrict__ Am,
              const __nv_bfloat16* __restrict__ Ai,
              const __nv_bfloat16* __restrict__ Bm,
              const float* __restrict__ bq, const float* __restrict__ bk,
              const float* __restrict__ bv,
              __nv_bfloat16* oQh, __nv_bfloat16* oQl,
              __nv_bfloat16* oKh, __nv_bfloat16* oKl,
              __half* oVf,
              __nv_bfloat16* oIKh, __nv_bfloat16* oIKl,
              __half* oIVf)
{
    extern __shared__ char smem[];
    const uint32_t sb = smem_u32(smem);
    const int tid = threadIdx.x, warp = tid >> 5, lane = tid & 31;

    const __nv_bfloat16* A;
    int msh, Slen, m0, n0g, inst;
    {
        int blk = blockIdx.x;
        if (blk < 384) {
            A = Am; msh = 10; Slen = SQ; inst = 0;
            m0 = (blk / 12) * 128; n0g = (blk % 12) * 256;
        } else {
            blk -= 384;
            A = Ai; msh = 7; Slen = LI; inst = 1;
            m0 = (blk / 8) * 128; n0g = 1024 + (blk % 8) * 256;
        }
    }
    const int wm = (warp >> 2) * 64, wn = (warp & 3) * 64;

    const int cr = tid >> 3, cko = (tid & 7) * 8;
    const __nv_bfloat16* Ag = A + (size_t)(m0 + cr) * KW + cko;
    const __nv_bfloat16* Bg = Bm + (size_t)(n0g + cr) * KW + cko;
    const uint32_t sAo = (cr * AST + cko) * 2;

    float acc[4][8][4];
#pragma unroll
    for (int i = 0; i < 4; i++)
#pragma unroll
        for (int j = 0; j < 8; j++)
#pragma unroll
            for (int p = 0; p < 4; p++) acc[i][j][p] = 0.f;

#pragma unroll
    for (int i = 0; i < 4; i++)
        cpasync16(sb + sAo + i * 32 * AST * 2, Ag + (size_t)(i * 32) * KW);
#pragma unroll
    for (int i = 0; i < 8; i++)
        cpasync16(sb + TA + sAo + i * 32 * AST * 2, Bg + (size_t)(i * 32) * KW);
    CP_COMMIT();

    const int NCH = 48;
    for (int c = 0; c < NCH; c++) {
        const int p = c & 1;
        if (c + 1 < NCH) {
            const int pn = (c + 1) & 1;
            const int cn = c + 1;
            const int aoff = (cn < 16) ? cn * 64 : cn * 64 - 1024;
            const int boff = (cn < 32) ? cn * 64 : cn * 64 - 2048;
#pragma unroll
            for (int i = 0; i < 4; i++)
                cpasync16(sb + pn * (TA + TB) + sAo + i * 32 * AST * 2,
                          Ag + (size_t)(i * 32) * KW + aoff);
#pragma unroll
            for (int i = 0; i < 8; i++)
                cpasync16(sb + pn * (TA + TB) + TA + sAo + i * 32 * AST * 2,
                          Bg + (size_t)(i * 32) * KW + boff);
            CP_COMMIT();
            CP_WAIT(1);
        } else {
            CP_WAIT(0);
        }
        __syncthreads();

        const uint32_t aw = sb + p * (TA + TB) +
                            ((wm + (lane & 15)) * AST + (lane >> 4) * 8) * 2;
        const uint32_t bw = sb + p * (TA + TB) + TA +
                            ((wn + (lane & 15)) * AST + (lane >> 4) * 8) * 2;
#pragma unroll
        for (int k16 = 0; k16 < 4; k16++) {
            const uint32_t ko = k16 * 32;
            uint32_t a[4][4], b[4][4];
#pragma unroll
            for (int mt = 0; mt < 4; mt++)
                ldsm4(a[mt][0], a[mt][1], a[mt][2], a[mt][3],
                      aw + mt * 16 * AST * 2 + ko);
#pragma unroll
            for (int nb = 0; nb < 4; nb++)
                ldsm4(b[nb][0], b[nb][1], b[nb][2], b[nb][3],
                      bw + nb * 16 * AST * 2 + ko);
#pragma unroll
            for (int mt = 0; mt < 4; mt++)
#pragma unroll
                for (int nb = 0; nb < 4; nb++) {
                    mma16816(acc[mt][2 * nb], a[mt][0], a[mt][1], a[mt][2], a[mt][3],
                             b[nb][0], b[nb][2]);
                    mma16816(acc[mt][2 * nb + 1], a[mt][0], a[mt][1], a[mt][2], a[mt][3],
                             b[nb][1], b[nb][3]);
                }
        }
        __syncthreads();
    }

#pragma unroll
    for (int nt = 0; nt < 8; nt++) {
        const int n = n0g + wn + nt * 8 + (lane & 3) * 2;
        const int wsel = n >> 10, nn = n & 1023;
        const float* bias = (wsel == 0) ? bq : (wsel == 1) ? bk : bv;
        const float b0 = bias[nn], b1 = bias[nn + 1];
        const size_t hoff = ((size_t)(nn >> 6)) * Slen;
        const int d = nn & 63;
        if (wsel == 2) {
            __half* pv = inst ? oIVf : oVf;
#pragma unroll
            for (int mt = 0; mt < 4; mt++)
#pragma unroll
                for (int half = 0; half < 2; half++) {
                    const int r = m0 + wm + mt * 16 + (lane >> 2) + half * 8;
                    const int bb = r >> msh, t = r - (bb << msh);
                    float vx = acc[mt][nt][half * 2 + 0] + b0;
                    float vy = acc[mt][nt][half * 2 + 1] + b1;
                    size_t off = ((size_t)bb * NH * Slen + hoff + t) * DH + d;
                    *(uint32_t*)(pv + off) = pk2h(vx, vy);
                }
        } else {
            __nv_bfloat16 *ph, *pl;
            if (inst) { ph = oIKh; pl = oIKl; }
            else if (wsel == 0) { ph = oQh; pl = oQl; }
            else { ph = oKh; pl = oKl; }
#pragma unroll
            for (int mt = 0; mt < 4; mt++)
#pragma unroll
                for (int half = 0; half < 2; half++) {
                    const int r = m0 + wm + mt * 16 + (lane >> 2) + half * 8;
                    const int bb = r >> msh, t = r - (bb << msh);
                    float vx = acc[mt][nt][half * 2 + 0] + b0;
                    float vy = acc[mt][nt][half * 2 + 1] + b1;
                    __nv_bfloat16 hx = __float2bfloat16(vx);
                    __nv_bfloat16 hy = __float2bfloat16(vy);
                    float lxf = vx - __bfloat162float(hx);
                    float lyf = vy - __bfloat162float(hy);
                    size_t off = ((size_t)bb * NH * Slen + hoff + t) * DH + d;
                    *(uint32_t*)(ph + off) =
                        (uint32_t)__bfloat16_as_ushort(hx) |
                        ((uint32_t)__bfloat16_as_ushort(hy) << 16);
                    *(uint32_t*)(pl + off) = pk2(lxf, lyf);
                }
        }
    }
}

// ---------------------------------------------------------------------------
// Tensor-core attention v3: QK 3-term bf16 split; PV single-term fp16.
// 2 CTAs/SM, ~100KB smem, P(fp16) aliased onto dead E slot.
// ---------------------------------------------------------------------------
#define PST 72
#define P12 132
#define A_SQH 0
#define A_SQL 9216
#define A_KH 18432
#define A_KL 27648
#define A_EP 36864            // E (phase1) / P-fp16 (phases 2-3)
#define A_SPH A_EP
#define A_VH 55296
#define A_SP1 64512           // 64*132*2 = 16896
#define A_SP2 81408
#define A_CORR 98304
#define A_SSM 98560
#define A_SSI 98816
#define A_AMSK 99072
#define A_IMSK 99328
#define A_TOTAL 99840

__device__ __forceinline__ void cpa_tile64(uint32_t sb, int dstoff,
                                           const void* srcv, int tid)
{
    const char* src = (const char*)srcv;
#pragma unroll
    for (int it = 0; it < 2; it++) {
        int i = tid + it * 256;
        int r = i >> 3, c = (i & 7) * 8;
        cpasync16(sb + dstoff + (r * PST + c) * 2, src + (r * 64 + c) * 2);
    }
}
__device__ __forceinline__ float ldbf(const char* sm, int base, int idx) {
    return __bfloat162float(*(const __nv_bfloat16*)(sm + base + idx * 2));
}

// QK 3-term split (register-lean nb-inner ordering).
__device__ __forceinline__ void qk_tile(float sacc[8][4], uint32_t sb,
                                        int wm, int lane)
{
#pragma unroll
    for (int k = 0; k < 4; k++) {
        const uint32_t ko = (k * 16 + (lane >> 4) * 8) * 2;
        uint32_t aH[4], aL[4];
        ldsm4(aH[0], aH[1], aH[2], aH[3],
              sb + A_SQH + (wm + (lane & 15)) * PST * 2 + ko);
        ldsm4(aL[0], aL[1], aL[2], aL[3],
              sb + A_SQL + (wm + (lane & 15)) * PST * 2 + ko);
#pragma unroll
        for (int nb = 0; nb < 4; nb++) {
            uint32_t bH[4], bL[4];
            ldsm4(bH[0], bH[1], bH[2], bH[3],
                  sb + A_KH + (nb * 16 + (lane & 15)) * PST * 2 + ko);
            ldsm4(bL[0], bL[1], bL[2], bL[3],
                  sb + A_KL + (nb * 16 + (lane & 15)) * PST * 2 + ko);
            mma16816(sacc[2 * nb], aH[0], aH[1], aH[2], aH[3], bH[0], bH[2]);
            mma16816(sacc[2 * nb + 1], aH[0], aH[1], aH[2], aH[3], bH[1], bH[3]);
            mma16816(sacc[2 * nb], aH[0], aH[1], aH[2], aH[3], bL[0], bL[2]);
            mma16816(sacc[2 * nb + 1], aH[0], aH[1], aH[2], aH[3], bL[1], bL[3]);
            mma16816(sacc[2 * nb], aL[0], aL[1], aL[2], aL[3], bH[0], bH[2]);
            mma16816(sacc[2 * nb + 1], aL[0], aL[1], aL[2], aL[3], bH[1], bH[3]);
        }
    }
}

// PV single-term fp16.
__device__ __forceinline__ void pv_tile(float cacc[4][4], uint32_t sb,
                                        int wm2, int wn2, int lane)
{
#pragma unroll
    for (int kk = 0; kk < 4; kk++) {
        const uint32_t ko = (kk * 16 + (lane >> 4) * 8) * 2;
        uint32_t aP[4];
        ldsm4(aP[0], aP[1], aP[2], aP[3],
              sb + A_SPH + (wm2 + (lane & 15)) * PST * 2 + ko);
        const uint32_t trow = (kk * 16 + (lane & 7) + 8 * ((lane >> 3) & 1)) * PST;
#pragma unroll
        for (int dh = 0; dh < 2; dh++) {
            const uint32_t tcol = wn2 + dh * 16 + ((lane >> 4) & 1) * 8;
            uint32_t v[4];
            ldsm4t(v[0], v[1], v[2], v[3], sb + A_VH + (trow + tcol) * 2);
            const int nf = dh * 2;
            mma16816h(cacc[nf], aP[0], aP[1], aP[2], aP[3], v[0], v[1]);
            mma16816h(cacc[nf + 1], aP[0], aP[1], aP[2], aP[3], v[2], v[3]);
        }
    }
}

__global__ __launch_bounds__(256, 2)
void attn_mma(const float* __restrict__ amask, const float* __restrict__ imask,
              const float* __restrict__ gate, float* __restrict__ outp)
{
    extern __shared__ char sm[];
    const uint32_t sb = smem_u32(sm);
    const int tid = threadIdx.x, warp = tid >> 5, lane = tid & 31;
    const int g = lane >> 2, t4 = lane & 3;
    const int bh = blockIdx.y, b = bh >> 4, h = bh & 15;
    const int l0 = blockIdx.x * 64;
    const int wm = warp * 16;
    const int wm2 = (warp >> 1) * 16, wn2 = (warp & 1) * 32;

    cpa_tile64(sb, A_SQH, g_Qh + ((size_t)bh * SQ + l0) * DH, tid);
    cpa_tile64(sb, A_SQL, g_Ql + ((size_t)bh * SQ + l0) * DH, tid);
    if (tid < 32)
        ((float4*)(sm + A_IMSK))[tid] = ((const float4*)(imask + b * LI))[tid];

    float cacc[4][4];
#pragma unroll
    for (int i = 0; i < 4; i++)
#pragma unroll
        for (int j = 0; j < 4; j++) cacc[i][j] = 0.f;
    float mrow[2] = {-1e30f, -1e30f}, ssum[2] = {0.f, 0.f};
    float* corr_sm = (float*)(sm + A_CORR);
    const float* amsk = (const float*)(sm + A_AMSK);
    const float* imsk = (const float*)(sm + A_IMSK);

    // ======================= main pass =======================
    for (int rt = 0; rt < 16; rt++) {
        const int r0 = rt * 64;
        cpa_tile64(sb, A_KH, g_Kh + ((size_t)bh * SQ + r0) * DH, tid);
        cpa_tile64(sb, A_KL, g_Kl + ((size_t)bh * SQ + r0) * DH, tid);
        cpa_tile64(sb, A_VH, g_Vf + ((size_t)bh * SQ + r0) * DH, tid);
        {
            const __nv_bfloat16* Eg = g_Eh + (size_t)(l0 - r0 + 960) * 64;
#pragma unroll
            for (int it = 0; it < 4; it++) {
                int i = tid + it * 256;
                int r = i >> 3, c = (i & 7) * 8;
                cpasync16(sb + A_EP + (r * PST + c) * 2, Eg + r * 64 + c);
            }
        }
        if (tid < 64) ((float*)(sm + A_AMSK))[tid] = amask[b * SQ + r0 + tid];
        CP_COMMIT();
        CP_WAIT(0);
        __syncthreads();

        float sacc[8][4];
        if (warp < 4) {
#pragma unroll
            for (int j = 0; j < 8; j++)
#pragma unroll
                for (int p = 0; p < 4; p++) sacc[j][p] = 0.f;
            qk_tile(sacc, sb, wm, lane);
        } else {
            const int isP2 = (warp >= 6);
            const int m0p = (warp - (isP2 ? 6 : 4)) * 32;
            const int srcA = isP2 ? A_KH : A_SQH;
            const int dstP = isP2 ? A_SP2 : A_SP1;
#pragma unroll
            for (int ch = 0; ch < 2; ch++) {
#pragma unroll
                for (int s = 0; s < 2; s++) {
                    float pacc[8][4];
#pragma unroll
                    for (int j = 0; j < 8; j++)
#pragma unroll
                        for (int p = 0; p < 4; p++) pacc[j][p] = 0.f;
#pragma unroll
                    for (int k = 0; k < 4; k++) {
                        const uint32_t ko = (k * 16 + (lane >> 4) * 8) * 2;
                        uint32_t aU[4];
                        ldsm4(aU[0], aU[1], aU[2], aU[3],
                              sb + srcA + (m0p + s * 16 + (lane & 15)) * PST * 2 + ko);
#pragma unroll
                        for (int nb = 0; nb < 4; nb++) {
                            uint32_t be[4];
                            ldsm4(be[0], be[1], be[2], be[3],
                                  sb + A_EP + (ch * 64 + nb * 16 + (lane & 15)) * PST * 2 + ko);
                            mma16816(pacc[2 * nb], aU[0], aU[1], aU[2], aU[3], be[0], be[2]);
                            mma16816(pacc[2 * nb + 1], aU[0], aU[1], aU[2], aU[3], be[1], be[3]);
                        }
                    }
#pragma unroll
                    for (int j = 0; j < 8; j++) {
                        int l = m0p + s * 16 + g;
                        int w = ch * 64 + 8 * j + 2 * t4;
                        *(uint32_t*)(sm + dstP + (l * P12 + w) * 2) =
                            pk2(pacc[j][0], pacc[j][1]);
                        *(uint32_t*)(sm + dstP + ((l + 8) * P12 + w) * 2) =
                            pk2(pacc[j][2], pacc[j][3]);
                    }
                }
            }
        }
        __syncthreads();   // E dead; P (fp16) may occupy its slot

        if (warp < 4) {
            const int l = wm + g;
#pragma unroll
            for (int j = 0; j < 8; j++) {
                const int r = 8 * j + 2 * t4;
                const int w = l - r + 63;
                sacc[j][0] = (sacc[j][0] + ldbf(sm, A_SP1, l * P12 + w)
                              + ldbf(sm, A_SP2, r * P12 + w)) * 0.125f + amsk[r];
                sacc[j][1] = (sacc[j][1] + ldbf(sm, A_SP1, l * P12 + w - 1)
                              + ldbf(sm, A_SP2, (r + 1) * P12 + w - 1)) * 0.125f + amsk[r + 1];
                sacc[j][2] = (sacc[j][2] + ldbf(sm, A_SP1, (l + 8) * P12 + w + 8)
                              + ldbf(sm, A_SP2, r * P12 + w + 8)) * 0.125f + amsk[r];
                sacc[j][3] = (sacc[j][3] + ldbf(sm, A_SP1, (l + 8) * P12 + w + 7)
                              + ldbf(sm, A_SP2, (r + 1) * P12 + w + 7)) * 0.125f + amsk[r + 1];
            }
            float mt0 = -1e30f, mt1 = -1e30f;
#pragma unroll
            for (int j = 0; j < 8; j++) {
                mt0 = fmaxf(mt0, fmaxf(sacc[j][0], sacc[j][1]));
                mt1 = fmaxf(mt1, fmaxf(sacc[j][2], sacc[j][3]));
            }
            mt0 = fmaxf(mt0, __shfl_xor_sync(0xffffffffu, mt0, 1));
            mt0 = fmaxf(mt0, __shfl_xor_sync(0xffffffffu, mt0, 2));
            mt1 = fmaxf(mt1, __shfl_xor_sync(0xffffffffu, mt1, 1));
            mt1 = fmaxf(mt1, __shfl_xor_sync(0xffffffffu, mt1, 2));
            float mn0 = fmaxf(mrow[0], mt0), mn1 = fmaxf(mrow[1], mt1);
            float cr0 = __expf(mrow[0] - mn0), cr1 = __expf(mrow[1] - mn1);
            mrow[0] = mn0; mrow[1] = mn1;
            float ps0 = 0.f, ps1 = 0.f;
#pragma unroll
            for (int j = 0; j < 8; j++) {
                float p00 = __expf(sacc[j][0] - mn0), p01 = __expf(sacc[j][1] - mn0);
                float p10 = __expf(sacc[j][2] - mn1), p11 = __expf(sacc[j][3] - mn1);
                ps0 += p00 + p01; ps1 += p10 + p11;
                int cidx = 8 * j + 2 * t4;
                *(uint32_t*)(sm + A_SPH + (l * PST + cidx) * 2) = pk2h(p00, p01);
                *(uint32_t*)(sm + A_SPH + ((l + 8) * PST + cidx) * 2) = pk2h(p10, p11);
            }
            ps0 += __shfl_xor_sync(0xffffffffu, ps0, 1);
            ps0 += __shfl_xor_sync(0xffffffffu, ps0, 2);
            ps1 += __shfl_xor_sync(0xffffffffu, ps1, 1);
            ps1 += __shfl_xor_sync(0xffffffffu, ps1, 2);
            ssum[0] = ssum[0] * cr0 + ps0;
            ssum[1] = ssum[1] * cr1 + ps1;
            if (t4 == 0) { corr_sm[l] = cr0; corr_sm[l + 8] = cr1; }
        }
        __syncthreads();

        {
            float c0r = corr_sm[wm2 + g], c1r = corr_sm[wm2 + 8 + g];
#pragma unroll
            for (int nf = 0; nf < 4; nf++) {
                cacc[nf][0] *= c0r; cacc[nf][1] *= c0r;
                cacc[nf][2] *= c1r; cacc[nf][3] *= c1r;
            }
            pv_tile(cacc, sb, wm2, wn2, lane);
        }
        __syncthreads();
    }

    // stash main ctx + ssum, reset
    {
        float* stash = (float*)(sm + A_SP1);
#pragma unroll
        for (int nf = 0; nf < 4; nf++) {
            int d = wn2 + 8 * nf + 2 * t4;
            stash[(wm2 + g) * 68 + d] = cacc[nf][0];
            stash[(wm2 + g) * 68 + d + 1] = cacc[nf][1];
            stash[(wm2 + 8 + g) * 68 + d] = cacc[nf][2];
            stash[(wm2 + 8 + g) * 68 + d + 1] = cacc[nf][3];
            cacc[nf][0] = cacc[nf][1] = cacc[nf][2] = cacc[nf][3] = 0.f;
        }
        if (warp < 4 && t4 == 0) {
            ((float*)(sm + A_SSM))[wm + g] = ssum[0];
            ((float*)(sm + A_SSM))[wm + g + 8] = ssum[1];
        }
        mrow[0] = mrow[1] = -1e30f; ssum[0] = ssum[1] = 0.f;
    }
    __syncthreads();

    // ======================= instruct pass =======================
    for (int rt = 0; rt < 2; rt++) {
        const int r0 = rt * 64;
        cpa_tile64(sb, A_KH, g_IKh + ((size_t)bh * LI + r0) * DH, tid);
        cpa_tile64(sb, A_KL, g_IKl + ((size_t)bh * LI + r0) * DH, tid);
        cpa_tile64(sb, A_VH, g_IVf + ((size_t)bh * LI + r0) * DH, tid);
        CP_COMMIT();
        CP_WAIT(0);
        __syncthreads();

        if (warp < 4) {
            float sacc[8][4];
#pragma unroll
            for (int j = 0; j < 8; j++)
#pragma unroll
                for (int p = 0; p < 4; p++) sacc[j][p] = 0.f;
            qk_tile(sacc, sb, wm, lane);

            const int l = wm + g;
            float mt0 = -1e30f, mt1 = -1e30f;
#pragma unroll
            for (int j = 0; j < 8; j++) {
                const int r = 8 * j + 2 * t4;
                sacc[j][0] = sacc[j][0] * 0.125f + imsk[r0 + r];
                sacc[j][1] = sacc[j][1] * 0.125f + imsk[r0 + r + 1];
                sacc[j][2] = sacc[j][2] * 0.125f + imsk[r0 + r];
                sacc[j][3] = sacc[j][3] * 0.125f + imsk[r0 + r + 1];
                mt0 = fmaxf(mt0, fmaxf(sacc[j][0], sacc[j][1]));
                mt1 = fmaxf(mt1, fmaxf(sacc[j][2], sacc[j][3]));
            }
            mt0 = fmaxf(mt0, __shfl_xor_sync(0xffffffffu, mt0, 1));
            mt0 = fmaxf(mt0, __shfl_xor_sync(0xffffffffu, mt0, 2));
            mt1 = fmaxf(mt1, __shfl_xor_sync(0xffffffffu, mt1, 1));
            mt1 = fmaxf(mt1, __shfl_xor_sync(0xffffffffu, mt1, 2));
            float mn0 = fmaxf(mrow[0], mt0), mn1 = fmaxf(mrow[1], mt1);
            float cr0 = __expf(mrow[0] - mn0), cr1 = __expf(mrow[1] - mn1);
            mrow[0] = mn0; mrow[1] = mn1;
            float ps0 = 0.f, ps1 = 0.f;
#pragma unroll
            for (int j = 0; j < 8; j++) {
                float p00 = __expf(sacc[j][0] - mn0), p01 = __expf(sacc[j][1] - mn0);
                float p10 = __expf(sacc[j][2] - mn1), p11 = __expf(sacc[j][3] - mn1);
                ps0 += p00 + p01; ps1 += p10 + p11;
                int cidx = 8 * j + 2 * t4;
                *(uint32_t*)(sm + A_SPH + (l * PST + cidx) * 2) = pk2h(p00, p01);
                *(uint32_t*)(sm + A_SPH + ((l + 8) * PST + cidx) * 2) = pk2h(p10, p11);
            }
            ps0 += __shfl_xor_sync(0xffffffffu, ps0, 1);
            ps0 += __shfl_xor_sync(0xffffffffu, ps0, 2);
            ps1 += __shfl_xor_sync(0xffffffffu, ps1, 1);
            ps1 += __shfl_xor_sync(0xffffffffu, ps1, 2);
            ssum[0] = ssum[0] * cr0 + ps0;
            ssum[1] = ssum[1] * cr1 + ps1;
            if (t4 == 0) { corr_sm[l] = cr0; corr_sm[l + 8] = cr1; }
        }
        __syncthreads();

        {
            float c0r = corr_sm[wm2 + g], c1r = corr_sm[wm2 + 8 + g];
#pragma unroll
            for (int nf = 0; nf < 4; nf++) {
                cacc[nf][0] *= c0r; cacc[nf][1] *= c0r;
                cacc[nf][2] *= c1r; cacc[nf][3] *= c1r;
            }
            pv_tile(cacc, sb, wm2, wn2, lane);
        }
        __syncthreads();
    }

    if (warp < 4 && t4 == 0) {
        ((float*)(sm + A_SSI))[wm + g] = ssum[0];
        ((float*)(sm + A_SSI))[wm + g + 8] = ssum[1];
    }
    __syncthreads();

    {
        const float tg = tanhf(gate[h]);
        const float* stash = (const float*)(sm + A_SP1);
        const float* ssmv = (const float*)(sm + A_SSM);
        const float* ssiv = (const float*)(sm + A_SSI);
        const float rnm0 = 1.f / ssmv[wm2 + g], rni0 = tg / ssiv[wm2 + g];
        const float rnm1 = 1.f / ssmv[wm2 + 8 + g], rni1 = tg / ssiv[wm2 + 8 + g];
#pragma unroll
        for (int nf = 0; nf < 4; nf++) {
            const int d = wn2 + 8 * nf + 2 * t4;
            float2 o0, o1;
            o0.x = stash[(wm2 + g) * 68 + d] * rnm0 + cacc[nf][0] * rni0;
            o0.y = stash[(wm2 + g) * 68 + d + 1] * rnm0 + cacc[nf][1] * rni0;
            o1.x = stash[(wm2 + 8 + g) * 68 + d] * rnm1 + cacc[nf][2] * rni1;
            o1.y = stash[(wm2 + 8 + g) * 68 + d + 1] * rnm1 + cacc[nf][3] * rni1;
            *(float2*)(outp + ((size_t)(b * SQ + l0 + wm2 + g)) * HIDDEN + h * DH + d) = o0;
            *(float2*)(outp + ((size_t)(b * SQ + l0 + wm2 + 8 + g)) * HIDDEN + h * DH + d) = o1;
        }
    }
}

// ---------------------------------------------------------------------------
extern "C" void kernel_launch(void* const* d_in, const int* in_sizes, int n_in,
                              void* d_out, int out_size)
{
    (void)in_sizes; (void)n_in; (void)out_size;
    const float* hs    = (const float*)d_in[0];
    const float* amask = (const float*)d_in[1];
    const float* ihs   = (const float*)d_in[2];
    const float* imask = (const float*)d_in[3];
    const float* Wq    = (const float*)d_in[4];
    const float* bq    = (const float*)d_in[5];
    const float* Wk    = (const float*)d_in[6];
    const float* bk    = (const float*)d_in[7];
    const float* Wv    = (const float*)d_in[8];
    const float* bv    = (const float*)d_in[9];
    const float* gate  = (const float*)d_in[10];
    const float* dist  = (const float*)d_in[11];
    float* out = (float*)d_out;

    __nv_bfloat16 *qh, *ql, *kh, *kl, *ikh, *ikl, *eh;
    __half *vf, *ivf;
    __nv_bfloat16 *xc, *ixc, *wc;
    cudaGetSymbolAddress((void**)&qh, g_Qh);
    cudaGetSymbolAddress((void**)&ql, g_Ql);
    cudaGetSymbolAddress((void**)&kh, g_Kh);
    cudaGetSymbolAddress((void**)&kl, g_Kl);
    cudaGetSymbolAddress((void**)&vf, g_Vf);
    cudaGetSymbolAddress((void**)&ikh, g_IKh);
    cudaGetSymbolAddress((void**)&ikl, g_IKl);
    cudaGetSymbolAddress((void**)&ivf, g_IVf);
    cudaGetSymbolAddress((void**)&eh, g_Eh);
    cudaGetSymbolAddress((void**)&xc, g_Xcat);
    cudaGetSymbolAddress((void**)&ixc, g_IXcat);
    cudaGetSymbolAddress((void**)&wc, g_Wcat);

    cudaFuncSetAttribute(gemm_mma, cudaFuncAttributeMaxDynamicSharedMemorySize, GEMM_SMEM);
    cudaFuncSetAttribute(attn_mma, cudaFuncAttributeMaxDynamicSharedMemorySize, A_TOTAL);

    conv_all<<<NX_BASE3 + NX_W, 256>>>((const float4*)hs, xc,
                                       (const float4*)ihs, ixc, dist, eh,
                                       Wq, Wk, Wv, wc);

    gemm_mma<<<416, 256, GEMM_SMEM>>>(xc, ixc, wc, bq, bk, bv,
                                      qh, ql, kh, kl, vf,
                                      ikh, ikl, ivf);

    attn_mma<<<dim3(SQ / 64, BHN), 256, A_TOTAL>>>(amask, imask, gate, out);
}

// round 11
// speedup vs baseline: 1.2921x; 1.1573x over previous
#include <cuda_runtime.h>
#include <cuda_bf16.h>
#include <cuda_fp16.h>
#include <math.h>
#include <cstdint>

#define NB 4
#define NH 16
#define DH 64
#define SQ 1024
#define LI 128
#define HIDDEN 1024
#define BHN (NB * NH)
#define KW 2048   // stored operand width (hi|lo)

// ---------------- scratch (all fp16 now) ------------------------------------
__device__ __align__(16) __half g_Qh[BHN * SQ * DH];
__device__ __align__(16) __half g_Ql[BHN * SQ * DH];
__device__ __align__(16) __half g_Kf[BHN * SQ * DH];
__device__ __align__(16) __half g_Vf[BHN * SQ * DH];
__device__ __align__(16) __half g_IKf[BHN * LI * DH];
__device__ __align__(16) __half g_IVf[BHN * LI * DH];
__device__ __align__(16) __half g_Ef[2048 * DH];

__device__ __align__(16) __half g_Xcat[NB * SQ * KW];
__device__ __align__(16) __half g_IXcat[NB * LI * KW];
__device__ __align__(16) __half g_Wcat[3 * HIDDEN * KW];

// ---------------- helpers ---------------------------------------------------
__device__ __forceinline__ uint32_t smem_u32(const void* p) {
    uint32_t a;
    asm("{ .reg .u64 t; cvta.to.shared.u64 t, %1; cvt.u32.u64 %0, t; }" : "=r"(a) : "l"(p));
    return a;
}
__device__ __forceinline__ void ldsm4(uint32_t& r0, uint32_t& r1, uint32_t& r2,
                                      uint32_t& r3, uint32_t addr) {
    asm volatile("ldmatrix.sync.aligned.m8n8.x4.shared.b16 {%0,%1,%2,%3}, [%4];"
                 : "=r"(r0), "=r"(r1), "=r"(r2), "=r"(r3) : "r"(addr));
}
__device__ __forceinline__ void ldsm4t(uint32_t& r0, uint32_t& r1, uint32_t& r2,
                                       uint32_t& r3, uint32_t addr) {
    asm volatile("ldmatrix.sync.aligned.m8n8.x4.trans.shared.b16 {%0,%1,%2,%3}, [%4];"
                 : "=r"(r0), "=r"(r1), "=r"(r2), "=r"(r3) : "r"(addr));
}
__device__ __forceinline__ void mma16816h(float* c, uint32_t a0, uint32_t a1,
                                          uint32_t a2, uint32_t a3,
                                          uint32_t b0, uint32_t b1) {
    asm volatile(
        "mma.sync.aligned.m16n8k16.row.col.f32.f16.f16.f32 "
        "{%0,%1,%2,%3}, {%4,%5,%6,%7}, {%8,%9}, {%0,%1,%2,%3};"
        : "+f"(c[0]), "+f"(c[1]), "+f"(c[2]), "+f"(c[3])
        : "r"(a0), "r"(a1), "r"(a2), "r"(a3), "r"(b0), "r"(b1));
}
__device__ __forceinline__ uint32_t pk2h(float a, float b) {
    __half2 t = __floats2half2_rn(a, b);
    return *(uint32_t*)&t;
}
__device__ __forceinline__ void cpasync16(uint32_t dst, const void* src) {
    asm volatile("cp.async.cg.shared.global [%0], [%1], 16;" :: "r"(dst), "l"(src));
}
#define CP_COMMIT() asm volatile("cp.async.commit_group;" ::: "memory")
#define CP_WAIT(n)  asm volatile("cp.async.wait_group %0;" :: "n"(n) : "memory")

// ---------------------------------------------------------------------------
// Conversions: X / X-instruct / E / W merged (all fp16 outputs).
// ---------------------------------------------------------------------------
#define NX_MAIN (NB * SQ * HIDDEN / 4 / 256)
#define NX_INST (NB * LI * HIDDEN / 4 / 256)
#define NX_E    (2048 * 64 / 256)
#define NX_W    3072
#define NX_BASE3 (NX_MAIN + NX_INST + NX_E)

__global__ __launch_bounds__(256)
void conv_all(const float4* __restrict__ xm, __half* __restrict__ dm,
              const float4* __restrict__ xi, __half* __restrict__ di,
              const float* __restrict__ dist, __half* __restrict__ eh,
              const float* __restrict__ Wq, const float* __restrict__ Wk,
              const float* __restrict__ Wv, __half* __restrict__ wdst)
{
    __shared__ float t[32][33];
    int blk = blockIdx.x;
    if (blk >= NX_BASE3) {
        int wblk = blk - NX_BASE3;
        int z = wblk >> 10, rem = wblk & 1023;
        int bx = rem & 31, by = rem >> 5;
        const float* W = (z == 0) ? Wq : (z == 1) ? Wk : Wv;
        int tx = threadIdx.x & 31, ty = threadIdx.x >> 5;
        int n = bx * 32 + tx, k0 = by * 32;
#pragma unroll
        for (int j = 0; j < 4; j++)
            t[ty + 8 * j][tx] = W[(size_t)(k0 + ty + 8 * j) * HIDDEN + n];
        __syncthreads();
        size_t nrow = (size_t)z * HIDDEN + bx * 32;
#pragma unroll
        for (int j = 0; j < 4; j++) {
            float v = t[tx][ty + 8 * j];
            __half h = __float2half(v);
            __half l = __float2half(v - __half2float(h));
            __half* o = wdst + (nrow + ty + 8 * j) * KW + k0 + tx;
            o[0]    = h;
            o[1024] = l;
        }
        return;
    }
    if (blk >= NX_MAIN + NX_INST) {
        int i = (blk - NX_MAIN - NX_INST) * 256 + threadIdx.x;
        float v = (i < 2047 * 64) ? dist[i] : 0.f;
        eh[i] = __float2half(v);
        return;
    }
    const float4* src = (blk < NX_MAIN) ? xm : xi;
    __half* dst = (blk < NX_MAIN) ? dm : di;
    int i = ((blk < NX_MAIN) ? blk : blk - NX_MAIN) * 256 + threadIdx.x;
    int row = i >> 8, c4 = (i & 255) * 4;
    float4 v = src[i];
    __half hx = __float2half(v.x), hy = __float2half(v.y);
    __half hz = __float2half(v.z), hw = __float2half(v.w);
    uint2 H, L;
    H.x = pk2h(__half2float(hx), __half2float(hy));
    H.y = pk2h(__half2float(hz), __half2float(hw));
    L.x = pk2h(v.x - __half2float(hx), v.y - __half2float(hy));
    L.y = pk2h(v.z - __half2float(hz), v.w - __half2float(hw));
    // note: H recomputed exactly (round of round = same value)
    __half* rb = dst + (size_t)row * KW + c4;
    *(uint2*)(rb)        = H;
    *(uint2*)(rb + 1024) = L;
}

// ---------------------------------------------------------------------------
// Merged projection GEMM (fp16 3-term): Q -> fp16 hi/lo; K,V -> fp16 single.
// ---------------------------------------------------------------------------
#define AST 72
#define TA (128 * AST * 2)
#define TB (256 * AST * 2)
#define GEMM_SMEM (2 * (TA + TB))

__global__ __launch_bounds__(256, 1)
void gemm_mma(const __half* __restrict__ Am, const __half* __restrict__ Ai,
              const __half* __restrict__ Bm,
              const float* __restrict__ bq, const float* __restrict__ bk,
              const float* __restrict__ bv,
              __half* oQh, __half* oQl, __half* oKf, __half* oVf,
              __half* oIKf, __half* oIVf)
{
    extern __shared__ char smem[];
    const uint32_t sb = smem_u32(smem);
    const int tid = threadIdx.x, warp = tid >> 5, lane = tid & 31;

    const __half* A;
    int msh, Slen, m0, n0g, inst;
    {
        int blk = blockIdx.x;
        if (blk < 384) {
            A = Am; msh = 10; Slen = SQ; inst = 0;
            m0 = (blk / 12) * 128; n0g = (blk % 12) * 256;
        } else {
            blk -= 384;
            A = Ai; msh = 7; Slen = LI; inst = 1;
            m0 = (blk / 8) * 128; n0g = 1024 + (blk % 8) * 256;
        }
    }
    const int wm = (warp >> 2) * 64, wn = (warp & 3) * 64;

    const int cr = tid >> 3, cko = (tid & 7) * 8;
    const __half* Ag = A + (size_t)(m0 + cr) * KW + cko;
    const __half* Bg = Bm + (size_t)(n0g + cr) * KW + cko;
    const uint32_t sAo = (cr * AST + cko) * 2;

    float acc[4][8][4];
#pragma unroll
    for (int i = 0; i < 4; i++)
#pragma unroll
        for (int j = 0; j < 8; j++)
#pragma unroll
            for (int p = 0; p < 4; p++) acc[i][j][p] = 0.f;

#pragma unroll
    for (int i = 0; i < 4; i++)
        cpasync16(sb + sAo + i * 32 * AST * 2, Ag + (size_t)(i * 32) * KW);
#pragma unroll
    for (int i = 0; i < 8; i++)
        cpasync16(sb + TA + sAo + i * 32 * AST * 2, Bg + (size_t)(i * 32) * KW);
    CP_COMMIT();

    const int NCH = 48;
    for (int c = 0; c < NCH; c++) {
        const int p = c & 1;
        if (c + 1 < NCH) {
            const int pn = (c + 1) & 1;
            const int cn = c + 1;
            const int aoff = (cn < 16) ? cn * 64 : cn * 64 - 1024;
            const int boff = (cn < 32) ? cn * 64 : cn * 64 - 2048;
#pragma unroll
            for (int i = 0; i < 4; i++)
                cpasync16(sb + pn * (TA + TB) + sAo + i * 32 * AST * 2,
                          Ag + (size_t)(i * 32) * KW + aoff);
#pragma unroll
            for (int i = 0; i < 8; i++)
                cpasync16(sb + pn * (TA + TB) + TA + sAo + i * 32 * AST * 2,
                          Bg + (size_t)(i * 32) * KW + boff);
            CP_COMMIT();
            CP_WAIT(1);
        } else {
            CP_WAIT(0);
        }
        __syncthreads();

        const uint32_t aw = sb + p * (TA + TB) +
                            ((wm + (lane & 15)) * AST + (lane >> 4) * 8) * 2;
        const uint32_t bw = sb + p * (TA + TB) + TA +
                            ((wn + (lane & 15)) * AST + (lane >> 4) * 8) * 2;
#pragma unroll
        for (int k16 = 0; k16 < 4; k16++) {
            const uint32_t ko = k16 * 32;
            uint32_t a[4][4], b[4][4];
#pragma unroll
            for (int mt = 0; mt < 4; mt++)
                ldsm4(a[mt][0], a[mt][1], a[mt][2], a[mt][3],
                      aw + mt * 16 * AST * 2 + ko);
#pragma unroll
            for (int nb = 0; nb < 4; nb++)
                ldsm4(b[nb][0], b[nb][1], b[nb][2], b[nb][3],
                      bw + nb * 16 * AST * 2 + ko);
#pragma unroll
            for (int mt = 0; mt < 4; mt++)
#pragma unroll
                for (int nb = 0; nb < 4; nb++) {
                    mma16816h(acc[mt][2 * nb], a[mt][0], a[mt][1], a[mt][2], a[mt][3],
                              b[nb][0], b[nb][2]);
                    mma16816h(acc[mt][2 * nb + 1], a[mt][0], a[mt][1], a[mt][2], a[mt][3],
                              b[nb][1], b[nb][3]);
                }
        }
        __syncthreads();
    }

#pragma unroll
    for (int nt = 0; nt < 8; nt++) {
        const int n = n0g + wn + nt * 8 + (lane & 3) * 2;
        const int wsel = n >> 10, nn = n & 1023;
        const float* bias = (wsel == 0) ? bq : (wsel == 1) ? bk : bv;
        const float b0 = bias[nn], b1 = bias[nn + 1];
        const size_t hoff = ((size_t)(nn >> 6)) * Slen;
        const int d = nn & 63;
        if (wsel == 0) {
            // Q: fp16 hi/lo
#pragma unroll
            for (int mt = 0; mt < 4; mt++)
#pragma unroll
                for (int half = 0; half < 2; half++) {
                    const int r = m0 + wm + mt * 16 + (lane >> 2) + half * 8;
                    const int bb = r >> msh, t = r - (bb << msh);
                    float vx = acc[mt][nt][half * 2 + 0] + b0;
                    float vy = acc[mt][nt][half * 2 + 1] + b1;
                    __half hx = __float2half(vx), hy = __float2half(vy);
                    size_t off = ((size_t)bb * NH * Slen + hoff + t) * DH + d;
                    *(uint32_t*)(oQh + off) = pk2h(__half2float(hx), __half2float(hy));
                    *(uint32_t*)(oQl + off) = pk2h(vx - __half2float(hx),
                                                   vy - __half2float(hy));
                }
        } else {
            __half* pv = (wsel == 1) ? (inst ? oIKf : oKf) : (inst ? oIVf : oVf);
#pragma unroll
            for (int mt = 0; mt < 4; mt++)
#pragma unroll
                for (int half = 0; half < 2; half++) {
                    const int r = m0 + wm + mt * 16 + (lane >> 2) + half * 8;
                    const int bb = r >> msh, t = r - (bb << msh);
                    float vx = acc[mt][nt][half * 2 + 0] + b0;
                    float vy = acc[mt][nt][half * 2 + 1] + b1;
                    size_t off = ((size_t)bb * NH * Slen + hoff + t) * DH + d;
                    *(uint32_t*)(pv + off) = pk2h(vx, vy);
                }
        }
    }
}

// ---------------------------------------------------------------------------
// Attention v4 (all fp16): QK 2-term, P1 sliding window, P2 by warps 4-7,
// PV single fp16. 90 KB smem, 2 CTAs/SM.
// ---------------------------------------------------------------------------
#define PST 72
#define P12 132
#define A_SQH 0
#define A_SQL 9216
#define A_KH  18432
#define A_VH  27648
#define A_E0  36864
#define A_E1  46080
#define A_P1A 55296
#define A_P1B 64512
#define A_P2  73728            // 16896 bytes
#define A_SPH A_P2             // alias: probs fp16 (after P2 reads, bar-guarded)
#define A_STASH A_P1A          // alias: main ctx stash (after main pass)
#define A_CORR 90624
#define A_SSM 90880
#define A_SSI 91136
#define A_AMSK 91392
#define A_IMSK 91648
#define A_TOTAL 92160

__device__ __forceinline__ void cpa_tile64(uint32_t sb, int dstoff,
                                           const __half* src, int tid)
{
#pragma unroll
    for (int it = 0; it < 2; it++) {
        int i = tid + it * 256;
        int r = i >> 3, c = (i & 7) * 8;
        cpasync16(sb + dstoff + (r * PST + c) * 2, src + r * 64 + c);
    }
}
__device__ __forceinline__ float ldh(const char* sm, int base, int idx) {
    return __half2float(*(const __half*)(sm + base + idx * 2));
}

// QK: 2-term (Qh + Ql) x K, fp16.
__device__ __forceinline__ void qk_tile(float sacc[8][4], uint32_t sb,
                                        int wm, int lane)
{
#pragma unroll
    for (int k = 0; k < 4; k++) {
        const uint32_t ko = (k * 16 + (lane >> 4) * 8) * 2;
        uint32_t aH[4], aL[4];
        ldsm4(aH[0], aH[1], aH[2], aH[3],
              sb + A_SQH + (wm + (lane & 15)) * PST * 2 + ko);
        ldsm4(aL[0], aL[1], aL[2], aL[3],
              sb + A_SQL + (wm + (lane & 15)) * PST * 2 + ko);
#pragma unroll
        for (int nb = 0; nb < 4; nb++) {
            uint32_t bK[4];
            ldsm4(bK[0], bK[1], bK[2], bK[3],
                  sb + A_KH + (nb * 16 + (lane & 15)) * PST * 2 + ko);
            mma16816h(sacc[2 * nb], aH[0], aH[1], aH[2], aH[3], bK[0], bK[2]);
            mma16816h(sacc[2 * nb + 1], aH[0], aH[1], aH[2], aH[3], bK[1], bK[3]);
            mma16816h(sacc[2 * nb], aL[0], aL[1], aL[2], aL[3], bK[0], bK[2]);
            mma16816h(sacc[2 * nb + 1], aL[0], aL[1], aL[2], aL[3], bK[1], bK[3]);
        }
    }
}

// P1 fresh chunk: Qh @ E(ebuf)^T -> p1buf [64 l][64 w], by score warps.
__device__ __forceinline__ void p1_fresh(uint32_t sb, char* sm, int ebuf,
                                         int p1buf, int wm, int lane,
                                         int g, int t4)
{
    float pacc[8][4];
#pragma unroll
    for (int j = 0; j < 8; j++)
#pragma unroll
        for (int p = 0; p < 4; p++) pacc[j][p] = 0.f;
#pragma unroll
    for (int k = 0; k < 4; k++) {
        const uint32_t ko = (k * 16 + (lane >> 4) * 8) * 2;
        uint32_t a[4];
        ldsm4(a[0], a[1], a[2], a[3],
              sb + A_SQH + (wm + (lane & 15)) * PST * 2 + ko);
#pragma unroll
        for (int nb = 0; nb < 4; nb++) {
            uint32_t be[4];
            ldsm4(be[0], be[1], be[2], be[3],
                  sb + ebuf + (nb * 16 + (lane & 15)) * PST * 2 + ko);
            mma16816h(pacc[2 * nb], a[0], a[1], a[2], a[3], be[0], be[2]);
            mma16816h(pacc[2 * nb + 1], a[0], a[1], a[2], a[3], be[1], be[3]);
        }
    }
#pragma unroll
    for (int j = 0; j < 8; j++) {
        int w = 8 * j + 2 * t4;
        *(uint32_t*)(sm + p1buf + ((wm + g) * PST + w) * 2) =
            pk2h(pacc[j][0], pacc[j][1]);
        *(uint32_t*)(sm + p1buf + ((wm + 8 + g) * PST + w) * 2) =
            pk2h(pacc[j][2], pacc[j][3]);
    }
}

// P2: K @ E^T (both chunks) -> A_P2 [64 r][128 w], by warps 4-7 (16 rows each).
__device__ __forceinline__ void p2_tile(uint32_t sb, char* sm, int rt,
                                        int m0p, int lane, int g, int t4)
{
#pragma unroll
    for (int c = 0; c < 2; c++) {
        const int ebuf = ((rt + c) & 1) ? A_E1 : A_E0;
        float pacc[8][4];
#pragma unroll
        for (int j = 0; j < 8; j++)
#pragma unroll
            for (int p = 0; p < 4; p++) pacc[j][p] = 0.f;
#pragma unroll
        for (int k = 0; k < 4; k++) {
            const uint32_t ko = (k * 16 + (lane >> 4) * 8) * 2;
            uint32_t a[4];
            ldsm4(a[0], a[1], a[2], a[3],
                  sb + A_KH + (m0p + (lane & 15)) * PST * 2 + ko);
#pragma unroll
            for (int nb = 0; nb < 4; nb++) {
                uint32_t be[4];
                ldsm4(be[0], be[1], be[2], be[3],
                      sb + ebuf + (nb * 16 + (lane & 15)) * PST * 2 + ko);
                mma16816h(pacc[2 * nb], a[0], a[1], a[2], a[3], be[0], be[2]);
                mma16816h(pacc[2 * nb + 1], a[0], a[1], a[2], a[3], be[1], be[3]);
            }
        }
#pragma unroll
        for (int j = 0; j < 8; j++) {
            int w = c * 64 + 8 * j + 2 * t4;
            *(uint32_t*)(sm + A_P2 + ((m0p + g) * P12 + w) * 2) =
                pk2h(pacc[j][0], pacc[j][1]);
            *(uint32_t*)(sm + A_P2 + ((m0p + 8 + g) * P12 + w) * 2) =
                pk2h(pacc[j][2], pacc[j][3]);
        }
    }
}

// PV single-term fp16.
__device__ __forceinline__ void pv_tile(float cacc[4][4], uint32_t sb,
                                        int wm2, int wn2, int lane)
{
#pragma unroll
    for (int kk = 0; kk < 4; kk++) {
        const uint32_t ko = (kk * 16 + (lane >> 4) * 8) * 2;
        uint32_t aP[4];
        ldsm4(aP[0], aP[1], aP[2], aP[3],
              sb + A_SPH + (wm2 + (lane & 15)) * PST * 2 + ko);
        const uint32_t trow = (kk * 16 + (lane & 7) + 8 * ((lane >> 3) & 1)) * PST;
#pragma unroll
        for (int dh = 0; dh < 2; dh++) {
            const uint32_t tcol = wn2 + dh * 16 + ((lane >> 4) & 1) * 8;
            uint32_t v[4];
            ldsm4t(v[0], v[1], v[2], v[3], sb + A_VH + (trow + tcol) * 2);
            const int nf = dh * 2;
            mma16816h(cacc[nf], aP[0], aP[1], aP[2], aP[3], v[0], v[1]);
            mma16816h(cacc[nf + 1], aP[0], aP[1], aP[2], aP[3], v[2], v[3]);
        }
    }
}

__global__ __launch_bounds__(256, 2)
void attn_mma(const float* __restrict__ amask, const float* __restrict__ imask,
              const float* __restrict__ gate, float* __restrict__ outp)
{
    extern __shared__ char sm[];
    const uint32_t sb = smem_u32(sm);
    const int tid = threadIdx.x, warp = tid >> 5, lane = tid & 31;
    const int g = lane >> 2, t4 = lane & 3;
    const int bh = blockIdx.y, b = bh >> 4, h = bh & 15;
    const int l0 = blockIdx.x * 64;
    const int wm = warp * 16;
    const int wm2 = (warp >> 1) * 16, wn2 = (warp & 1) * 32;

    cpa_tile64(sb, A_SQH, g_Qh + ((size_t)bh * SQ + l0) * DH, tid);
    cpa_tile64(sb, A_SQL, g_Ql + ((size_t)bh * SQ + l0) * DH, tid);
    if (tid < 32)
        ((float4*)(sm + A_IMSK))[tid] = ((const float4*)(imask + b * LI))[tid];

    float cacc[4][4];
#pragma unroll
    for (int i = 0; i < 4; i++)
#pragma unroll
        for (int j = 0; j < 4; j++) cacc[i][j] = 0.f;
    float mrow[2] = {-1e30f, -1e30f}, ssum[2] = {0.f, 0.f};
    float* corr_sm = (float*)(sm + A_CORR);
    const float* amsk = (const float*)(sm + A_AMSK);
    const float* imsk = (const float*)(sm + A_IMSK);

    // ======================= main pass =======================
    for (int rt = 0; rt < 16; rt++) {
        const int r0 = rt * 64;
        const int epb = (rt & 1) ? A_E1 : A_E0;   // fresh chunk0 buffer
        const int p1b = (rt & 1) ? A_P1B : A_P1A;

        cpa_tile64(sb, A_KH, g_Kf + ((size_t)bh * SQ + r0) * DH, tid);
        cpa_tile64(sb, A_VH, g_Vf + ((size_t)bh * SQ + r0) * DH, tid);
        cpa_tile64(sb, epb, g_Ef + (size_t)(l0 - r0 + 960) * 64, tid);
        if (rt == 0)
            cpa_tile64(sb, A_E1, g_Ef + (size_t)(l0 + 1024) * 64, tid);
        if (tid < 64) ((float*)(sm + A_AMSK))[tid] = amask[b * SQ + r0 + tid];
        CP_COMMIT();
        CP_WAIT(0);
        __syncthreads();

        float sacc[8][4];
        if (warp < 4) {
#pragma unroll
            for (int j = 0; j < 8; j++)
#pragma unroll
                for (int p = 0; p < 4; p++) sacc[j][p] = 0.f;
            qk_tile(sacc, sb, wm, lane);
            p1_fresh(sb, sm, epb, p1b, wm, lane, g, t4);
            if (rt == 0)
                p1_fresh(sb, sm, A_E1, A_P1B, wm, lane, g, t4);
        } else {
            p2_tile(sb, sm, rt, (warp - 4) * 16, lane, g, t4);
        }
        __syncthreads();

        if (warp < 4) {
            const int l = wm + g;
            const int p1c0 = (rt & 1) ? A_P1B : A_P1A;        // chunk0 buffer
            const int p1c1 = (rt & 1) ? A_P1A : A_P1B;        // chunk1 buffer
#pragma unroll
            for (int j = 0; j < 8; j++) {
                const int r = 8 * j + 2 * t4;
                const int w = l - r + 63;
                const int w1 = w - 1, w2 = w + 8, w3 = w + 7;
                float p1a = ldh(sm, (w  >= 64) ? p1c1 : p1c0, l * PST + (w  & 63));
                float p1b_ = ldh(sm, (w1 >= 64) ? p1c1 : p1c0, l * PST + (w1 & 63));
                float p1c = ldh(sm, (w2 >= 64) ? p1c1 : p1c0, (l + 8) * PST + (w2 & 63));
                float p1d = ldh(sm, (w3 >= 64) ? p1c1 : p1c0, (l + 8) * PST + (w3 & 63));
                sacc[j][0] = (sacc[j][0] + p1a + ldh(sm, A_P2, r * P12 + w)) * 0.125f + amsk[r];
                sacc[j][1] = (sacc[j][1] + p1b_ + ldh(sm, A_P2, (r + 1) * P12 + w1)) * 0.125f + amsk[r + 1];
                sacc[j][2] = (sacc[j][2] + p1c + ldh(sm, A_P2, r * P12 + w2)) * 0.125f + amsk[r];
                sacc[j][3] = (sacc[j][3] + p1d + ldh(sm, A_P2, (r + 1) * P12 + w3)) * 0.125f + amsk[r + 1];
            }
            float mt0 = -1e30f, mt1 = -1e30f;
#pragma unroll
            for (int j = 0; j < 8; j++) {
                mt0 = fmaxf(mt0, fmaxf(sacc[j][0], sacc[j][1]));
                mt1 = fmaxf(mt1, fmaxf(sacc[j][2], sacc[j][3]));
            }
            mt0 = fmaxf(mt0, __shfl_xor_sync(0xffffffffu, mt0, 1));
            mt0 = fmaxf(mt0, __shfl_xor_sync(0xffffffffu, mt0, 2));
            mt1 = fmaxf(mt1, __shfl_xor_sync(0xffffffffu, mt1, 1));
            mt1 = fmaxf(mt1, __shfl_xor_sync(0xffffffffu, mt1, 2));
            // all P1/P2 reads done -> safe to overwrite P2 region with probs
            asm volatile("bar.sync 1, 128;" ::: "memory");
            float mn0 = fmaxf(mrow[0], mt0), mn1 = fmaxf(mrow[1], mt1);
            float cr0 = __expf(mrow[0] - mn0), cr1 = __expf(mrow[1] - mn1);
            mrow[0] = mn0; mrow[1] = mn1;
            float ps0 = 0.f, ps1 = 0.f;
#pragma unroll
            for (int j = 0; j < 8; j++) {
                float p00 = __expf(sacc[j][0] - mn0), p01 = __expf(sacc[j][1] - mn0);
                float p10 = __expf(sacc[j][2] - mn1), p11 = __expf(sacc[j][3] - mn1);
                ps0 += p00 + p01; ps1 += p10 + p11;
                int cidx = 8 * j + 2 * t4;
                *(uint32_t*)(sm + A_SPH + (l * PST + cidx) * 2) = pk2h(p00, p01);
                *(uint32_t*)(sm + A_SPH + ((l + 8) * PST + cidx) * 2) = pk2h(p10, p11);
            }
            ps0 += __shfl_xor_sync(0xffffffffu, ps0, 1);
            ps0 += __shfl_xor_sync(0xffffffffu, ps0, 2);
            ps1 += __shfl_xor_sync(0xffffffffu, ps1, 1);
            ps1 += __shfl_xor_sync(0xffffffffu, ps1, 2);
            ssum[0] = ssum[0] * cr0 + ps0;
            ssum[1] = ssum[1] * cr1 + ps1;
            if (t4 == 0) { corr_sm[l] = cr0; corr_sm[l + 8] = cr1; }
        }
        __syncthreads();

        {
            float c0r = corr_sm[wm2 + g], c1r = corr_sm[wm2 + 8 + g];
#pragma unroll
            for (int nf = 0; nf < 4; nf++) {
                cacc[nf][0] *= c0r; cacc[nf][1] *= c0r;
                cacc[nf][2] *= c1r; cacc[nf][3] *= c1r;
            }
            pv_tile(cacc, sb, wm2, wn2, lane);
        }
        __syncthreads();
    }

    // stash main ctx + ssum, reset (stash aliases P1A/P1B)
    {
        float* stash = (float*)(sm + A_STASH);
#pragma unroll
        for (int nf = 0; nf < 4; nf++) {
            int d = wn2 + 8 * nf + 2 * t4;
            stash[(wm2 + g) * 68 + d] = cacc[nf][0];
            stash[(wm2 + g) * 68 + d + 1] = cacc[nf][1];
            stash[(wm2 + 8 + g) * 68 + d] = cacc[nf][2];
            stash[(wm2 + 8 + g) * 68 + d + 1] = cacc[nf][3];
            cacc[nf][0] = cacc[nf][1] = cacc[nf][2] = cacc[nf][3] = 0.f;
        }
        if (warp < 4 && t4 == 0) {
            ((float*)(sm + A_SSM))[wm + g] = ssum[0];
            ((float*)(sm + A_SSM))[wm + g + 8] = ssum[1];
        }
        mrow[0] = mrow[1] = -1e30f; ssum[0] = ssum[1] = 0.f;
    }
    __syncthreads();

    // ======================= instruct pass =======================
    for (int rt = 0; rt < 2; rt++) {
        const int r0 = rt * 64;
        cpa_tile64(sb, A_KH, g_IKf + ((size_t)bh * LI + r0) * DH, tid);
        cpa_tile64(sb, A_VH, g_IVf + ((size_t)bh * LI + r0) * DH, tid);
        CP_COMMIT();
        CP_WAIT(0);
        __syncthreads();

        if (warp < 4) {
            float sacc[8][4];
#pragma unroll
            for (int j = 0; j < 8; j++)
#pragma unroll
                for (int p = 0; p < 4; p++) sacc[j][p] = 0.f;
            qk_tile(sacc, sb, wm, lane);

            const int l = wm + g;
            float mt0 = -1e30f, mt1 = -1e30f;
#pragma unroll
            for (int j = 0; j < 8; j++) {
                const int r = 8 * j + 2 * t4;
                sacc[j][0] = sacc[j][0] * 0.125f + imsk[r0 + r];
                sacc[j][1] = sacc[j][1] * 0.125f + imsk[r0 + r + 1];
                sacc[j][2] = sacc[j][2] * 0.125f + imsk[r0 + r];
                sacc[j][3] = sacc[j][3] * 0.125f + imsk[r0 + r + 1];
                mt0 = fmaxf(mt0, fmaxf(sacc[j][0], sacc[j][1]));
                mt1 = fmaxf(mt1, fmaxf(sacc[j][2], sacc[j][3]));
            }
            mt0 = fmaxf(mt0, __shfl_xor_sync(0xffffffffu, mt0, 1));
            mt0 = fmaxf(mt0, __shfl_xor_sync(0xffffffffu, mt0, 2));
            mt1 = fmaxf(mt1, __shfl_xor_sync(0xffffffffu, mt1, 1));
            mt1 = fmaxf(mt1, __shfl_xor_sync(0xffffffffu, mt1, 2));
            float mn0 = fmaxf(mrow[0], mt0), mn1 = fmaxf(mrow[1], mt1);
            float cr0 = __expf(mrow[0] - mn0), cr1 = __expf(mrow[1] - mn1);
            mrow[0] = mn0; mrow[1] = mn1;
            float ps0 = 0.f, ps1 = 0.f;
#pragma unroll
            for (int j = 0; j < 8; j++) {
                float p00 = __expf(sacc[j][0] - mn0), p01 = __expf(sacc[j][1] - mn0);
                float p10 = __expf(sacc[j][2] - mn1), p11 = __expf(sacc[j][3] - mn1);
                ps0 += p00 + p01; ps1 += p10 + p11;
                int cidx = 8 * j + 2 * t4;
                *(uint32_t*)(sm + A_SPH + (l * PST + cidx) * 2) = pk2h(p00, p01);
                *(uint32_t*)(sm + A_SPH + ((l + 8) * PST + cidx) * 2) = pk2h(p10, p11);
            }
            ps0 += __shfl_xor_sync(0xffffffffu, ps0, 1);
            ps0 += __shfl_xor_sync(0xffffffffu, ps0, 2);
            ps1 += __shfl_xor_sync(0xffffffffu, ps1, 1);
            ps1 += __shfl_xor_sync(0xffffffffu, ps1, 2);
            ssum[0] = ssum[0] * cr0 + ps0;
            ssum[1] = ssum[1] * cr1 + ps1;
            if (t4 == 0) { corr_sm[l] = cr0; corr_sm[l + 8] = cr1; }
        }
        __syncthreads();

        {
            float c0r = corr_sm[wm2 + g], c1r = corr_sm[wm2 + 8 + g];
#pragma unroll
            for (int nf = 0; nf < 4; nf++) {
                cacc[nf][0] *= c0r; cacc[nf][1] *= c0r;
                cacc[nf][2] *= c1r; cacc[nf][3] *= c1r;
            }
            pv_tile(cacc, sb, wm2, wn2, lane);
        }
        __syncthreads();
    }

    if (warp < 4 && t4 == 0) {
        ((float*)(sm + A_SSI))[wm + g] = ssum[0];
        ((float*)(sm + A_SSI))[wm + g + 8] = ssum[1];
    }
    __syncthreads();

    {
        const float tg = tanhf(gate[h]);
        const float* stash = (const float*)(sm + A_STASH);
        const float* ssmv = (const float*)(sm + A_SSM);
        const float* ssiv = (const float*)(sm + A_SSI);
        const float rnm0 = 1.f / ssmv[wm2 + g], rni0 = tg / ssiv[wm2 + g];
        const float rnm1 = 1.f / ssmv[wm2 + 8 + g], rni1 = tg / ssiv[wm2 + 8 + g];
#pragma unroll
        for (int nf = 0; nf < 4; nf++) {
            const int d = wn2 + 8 * nf + 2 * t4;
            float2 o0, o1;
            o0.x = stash[(wm2 + g) * 68 + d] * rnm0 + cacc[nf][0] * rni0;
            o0.y = stash[(wm2 + g) * 68 + d + 1] * rnm0 + cacc[nf][1] * rni0;
            o1.x = stash[(wm2 + 8 + g) * 68 + d] * rnm1 + cacc[nf][2] * rni1;
            o1.y = stash[(wm2 + 8 + g) * 68 + d + 1] * rnm1 + cacc[nf][3] * rni1;
            *(float2*)(outp + ((size_t)(b * SQ + l0 + wm2 + g)) * HIDDEN + h * DH + d) = o0;
            *(float2*)(outp + ((size_t)(b * SQ + l0 + wm2 + 8 + g)) * HIDDEN + h * DH + d) = o1;
        }
    }
}

// ---------------------------------------------------------------------------
extern "C" void kernel_launch(void* const* d_in, const int* in_sizes, int n_in,
                              void* d_out, int out_size)
{
    (void)in_sizes; (void)n_in; (void)out_size;
    const float* hs    = (const float*)d_in[0];
    const float* amask = (const float*)d_in[1];
    const float* ihs   = (const float*)d_in[2];
    const float* imask = (const float*)d_in[3];
    const float* Wq    = (const float*)d_in[4];
    const float* bq    = (const float*)d_in[5];
    const float* Wk    = (const float*)d_in[6];
    const float* bk    = (const float*)d_in[7];
    const float* Wv    = (const float*)d_in[8];
    const float* bv    = (const float*)d_in[9];
    const float* gate  = (const float*)d_in[10];
    const float* dist  = (const float*)d_in[11];
    float* out = (float*)d_out;

    __half *qh, *ql, *kf, *vf, *ikf, *ivf, *ef, *xc, *ixc, *wc;
    cudaGetSymbolAddress((void**)&qh, g_Qh);
    cudaGetSymbolAddress((void**)&ql, g_Ql);
    cudaGetSymbolAddress((void**)&kf, g_Kf);
    cudaGetSymbolAddress((void**)&vf, g_Vf);
    cudaGetSymbolAddress((void**)&ikf, g_IKf);
    cudaGetSymbolAddress((void**)&ivf, g_IVf);
    cudaGetSymbolAddress((void**)&ef, g_Ef);
    cudaGetSymbolAddress((void**)&xc, g_Xcat);
    cudaGetSymbolAddress((void**)&ixc, g_IXcat);
    cudaGetSymbolAddress((void**)&wc, g_Wcat);

    cudaFuncSetAttribute(gemm_mma, cudaFuncAttributeMaxDynamicSharedMemorySize, GEMM_SMEM);
    cudaFuncSetAttribute(attn_mma, cudaFuncAttributeMaxDynamicSharedMemorySize, A_TOTAL);

    conv_all<<<NX_BASE3 + NX_W, 256>>>((const float4*)hs, xc,
                                       (const float4*)ihs, ixc, dist, ef,
                                       Wq, Wk, Wv, wc);

    gemm_mma<<<416, 256, GEMM_SMEM>>>(xc, ixc, wc, bq, bk, bv,
                                      qh, ql, kf, vf, ikf, ivf);

    attn_mma<<<dim3(SQ / 64, BHN), 256, A_TOTAL>>>(amask, imask, gate, out);
}

// round 12
// speedup vs baseline: 1.5077x; 1.1669x over previous
#include <cuda_runtime.h>
#include <cuda_bf16.h>
#include <cuda_fp16.h>
#include <math.h>
#include <cstdint>

#define NB 4
#define NH 16
#define DH 64
#define SQ 1024
#define LI 128
#define HIDDEN 1024
#define BHN (NB * NH)
#define KW 2048   // X operand width (hi|lo); W is 1024 (hi only)

// ---------------- scratch (all fp16) ----------------------------------------
__device__ __align__(16) __half g_Qh[BHN * SQ * DH];
__device__ __align__(16) __half g_Ql[BHN * SQ * DH];
__device__ __align__(16) __half g_Kf[BHN * SQ * DH];
__device__ __align__(16) __half g_Vf[BHN * SQ * DH];
__device__ __align__(16) __half g_IKf[BHN * LI * DH];
__device__ __align__(16) __half g_IVf[BHN * LI * DH];
__device__ __align__(16) __half g_Ef[2048 * DH];

__device__ __align__(16) __half g_Xcat[NB * SQ * KW];
__device__ __align__(16) __half g_IXcat[NB * LI * KW];
__device__ __align__(16) __half g_Wh[3 * HIDDEN * HIDDEN];   // [n(3072)][k(1024)]

// ---------------- helpers ---------------------------------------------------
__device__ __forceinline__ uint32_t smem_u32(const void* p) {
    uint32_t a;
    asm("{ .reg .u64 t; cvta.to.shared.u64 t, %1; cvt.u32.u64 %0, t; }" : "=r"(a) : "l"(p));
    return a;
}
__device__ __forceinline__ void ldsm4(uint32_t& r0, uint32_t& r1, uint32_t& r2,
                                      uint32_t& r3, uint32_t addr) {
    asm volatile("ldmatrix.sync.aligned.m8n8.x4.shared.b16 {%0,%1,%2,%3}, [%4];"
                 : "=r"(r0), "=r"(r1), "=r"(r2), "=r"(r3) : "r"(addr));
}
__device__ __forceinline__ void ldsm4t(uint32_t& r0, uint32_t& r1, uint32_t& r2,
                                       uint32_t& r3, uint32_t addr) {
    asm volatile("ldmatrix.sync.aligned.m8n8.x4.trans.shared.b16 {%0,%1,%2,%3}, [%4];"
                 : "=r"(r0), "=r"(r1), "=r"(r2), "=r"(r3) : "r"(addr));
}
__device__ __forceinline__ void mma16816h(float* c, uint32_t a0, uint32_t a1,
                                          uint32_t a2, uint32_t a3,
                                          uint32_t b0, uint32_t b1) {
    asm volatile(
        "mma.sync.aligned.m16n8k16.row.col.f32.f16.f16.f32 "
        "{%0,%1,%2,%3}, {%4,%5,%6,%7}, {%8,%9}, {%0,%1,%2,%3};"
        : "+f"(c[0]), "+f"(c[1]), "+f"(c[2]), "+f"(c[3])
        : "r"(a0), "r"(a1), "r"(a2), "r"(a3), "r"(b0), "r"(b1));
}
__device__ __forceinline__ uint32_t pk2h(float a, float b) {
    __half2 t = __floats2half2_rn(a, b);
    return *(uint32_t*)&t;
}
__device__ __forceinline__ void cpasync16(uint32_t dst, const void* src) {
    asm volatile("cp.async.cg.shared.global [%0], [%1], 16;" :: "r"(dst), "l"(src));
}
#define CP_COMMIT() asm volatile("cp.async.commit_group;" ::: "memory")
#define CP_WAIT(n)  asm volatile("cp.async.wait_group %0;" :: "n"(n) : "memory")

// ---------------------------------------------------------------------------
// Conversions: X / X-instruct / E / W merged.
// ---------------------------------------------------------------------------
#define NX_MAIN (NB * SQ * HIDDEN / 4 / 256)
#define NX_INST (NB * LI * HIDDEN / 4 / 256)
#define NX_E    (2048 * 64 / 256)
#define NX_W    3072
#define NX_BASE3 (NX_MAIN + NX_INST + NX_E)

__global__ __launch_bounds__(256)
void conv_all(const float4* __restrict__ xm, __half* __restrict__ dm,
              const float4* __restrict__ xi, __half* __restrict__ di,
              const float* __restrict__ dist, __half* __restrict__ eh,
              const float* __restrict__ Wq, const float* __restrict__ Wk,
              const float* __restrict__ Wv, __half* __restrict__ wdst)
{
    __shared__ float t[32][33];
    int blk = blockIdx.x;
    if (blk >= NX_BASE3) {
        int wblk = blk - NX_BASE3;
        int z = wblk >> 10, rem = wblk & 1023;
        int bx = rem & 31, by = rem >> 5;
        const float* W = (z == 0) ? Wq : (z == 1) ? Wk : Wv;
        int tx = threadIdx.x & 31, ty = threadIdx.x >> 5;
        int n = bx * 32 + tx, k0 = by * 32;
#pragma unroll
        for (int j = 0; j < 4; j++)
            t[ty + 8 * j][tx] = W[(size_t)(k0 + ty + 8 * j) * HIDDEN + n];
        __syncthreads();
        size_t nrow = (size_t)z * HIDDEN + bx * 32;
#pragma unroll
        for (int j = 0; j < 4; j++)
            wdst[(nrow + ty + 8 * j) * HIDDEN + k0 + tx] = __float2half(t[tx][ty + 8 * j]);
        return;
    }
    if (blk >= NX_MAIN + NX_INST) {
        int i = (blk - NX_MAIN - NX_INST) * 256 + threadIdx.x;
        float v = (i < 2047 * 64) ? dist[i] : 0.f;
        eh[i] = __float2half(v);
        return;
    }
    const float4* src = (blk < NX_MAIN) ? xm : xi;
    __half* dst = (blk < NX_MAIN) ? dm : di;
    int i = ((blk < NX_MAIN) ? blk : blk - NX_MAIN) * 256 + threadIdx.x;
    int row = i >> 8, c4 = (i & 255) * 4;
    float4 v = src[i];
    __half hx = __float2half(v.x), hy = __float2half(v.y);
    __half hz = __float2half(v.z), hw = __float2half(v.w);
    uint2 H, L;
    H.x = pk2h(__half2float(hx), __half2float(hy));
    H.y = pk2h(__half2float(hz), __half2float(hw));
    L.x = pk2h(v.x - __half2float(hx), v.y - __half2float(hy));
    L.y = pk2h(v.z - __half2float(hz), v.w - __half2float(hw));
    __half* rb = dst + (size_t)row * KW + c4;
    *(uint2*)(rb)        = H;
    *(uint2*)(rb + 1024) = L;
}

// ---------------------------------------------------------------------------
// Merged projection GEMM: K'=2048 ((Xh+Xl) x Wh). Q -> fp16 hi/lo; K,V fp16.
// ---------------------------------------------------------------------------
#define AST 72
#define TA (128 * AST * 2)
#define TB (256 * AST * 2)
#define GEMM_SMEM (2 * (TA + TB))

__global__ __launch_bounds__(256, 1)
void gemm_mma(const __half* __restrict__ Am, const __half* __restrict__ Ai,
              const __half* __restrict__ Bm,
              const float* __restrict__ bq, const float* __restrict__ bk,
              const float* __restrict__ bv,
              __half* oQh, __half* oQl, __half* oKf, __half* oVf,
              __half* oIKf, __half* oIVf)
{
    extern __shared__ char smem[];
    const uint32_t sb = smem_u32(smem);
    const int tid = threadIdx.x, warp = tid >> 5, lane = tid & 31;

    const __half* A;
    int msh, Slen, m0, n0g, inst;
    {
        int blk = blockIdx.x;
        if (blk < 384) {
            A = Am; msh = 10; Slen = SQ; inst = 0;
            m0 = (blk / 12) * 128; n0g = (blk % 12) * 256;
        } else {
            blk -= 384;
            A = Ai; msh = 7; Slen = LI; inst = 1;
            m0 = (blk / 8) * 128; n0g = 1024 + (blk % 8) * 256;
        }
    }
    const int wm = (warp >> 2) * 64, wn = (warp & 3) * 64;

    const int cr = tid >> 3, cko = (tid & 7) * 8;
    const __half* Ag = A + (size_t)(m0 + cr) * KW + cko;
    const __half* Bg = Bm + (size_t)(n0g + cr) * HIDDEN + cko;
    const uint32_t sAo = (cr * AST + cko) * 2;

    float acc[4][8][4];
#pragma unroll
    for (int i = 0; i < 4; i++)
#pragma unroll
        for (int j = 0; j < 8; j++)
#pragma unroll
            for (int p = 0; p < 4; p++) acc[i][j][p] = 0.f;

#pragma unroll
    for (int i = 0; i < 4; i++)
        cpasync16(sb + sAo + i * 32 * AST * 2, Ag + (size_t)(i * 32) * KW);
#pragma unroll
    for (int i = 0; i < 8; i++)
        cpasync16(sb + TA + sAo + i * 32 * AST * 2, Bg + (size_t)(i * 32) * HIDDEN);
    CP_COMMIT();

    const int NCH = 32;   // chunks: X over [Xh|Xl] (2048), W over Wh (1024, repeated)
    for (int c = 0; c < NCH; c++) {
        const int p = c & 1;
        if (c + 1 < NCH) {
            const int pn = (c + 1) & 1;
            const int cn = c + 1;
            const int aoff = cn * 64;
            const int boff = (cn & 15) * 64;
#pragma unroll
            for (int i = 0; i < 4; i++)
                cpasync16(sb + pn * (TA + TB) + sAo + i * 32 * AST * 2,
                          Ag + (size_t)(i * 32) * KW + aoff);
#pragma unroll
            for (int i = 0; i < 8; i++)
                cpasync16(sb + pn * (TA + TB) + TA + sAo + i * 32 * AST * 2,
                          Bg + (size_t)(i * 32) * HIDDEN + boff);
            CP_COMMIT();
            CP_WAIT(1);
        } else {
            CP_WAIT(0);
        }
        __syncthreads();

        const uint32_t aw = sb + p * (TA + TB) +
                            ((wm + (lane & 15)) * AST + (lane >> 4) * 8) * 2;
        const uint32_t bw = sb + p * (TA + TB) + TA +
                            ((wn + (lane & 15)) * AST + (lane >> 4) * 8) * 2;
#pragma unroll
        for (int k16 = 0; k16 < 4; k16++) {
            const uint32_t ko = k16 * 32;
            uint32_t a[4][4], b[4][4];
#pragma unroll
            for (int mt = 0; mt < 4; mt++)
                ldsm4(a[mt][0], a[mt][1], a[mt][2], a[mt][3],
                      aw + mt * 16 * AST * 2 + ko);
#pragma unroll
            for (int nb = 0; nb < 4; nb++)
                ldsm4(b[nb][0], b[nb][1], b[nb][2], b[nb][3],
                      bw + nb * 16 * AST * 2 + ko);
#pragma unroll
            for (int mt = 0; mt < 4; mt++)
#pragma unroll
                for (int nb = 0; nb < 4; nb++) {
                    mma16816h(acc[mt][2 * nb], a[mt][0], a[mt][1], a[mt][2], a[mt][3],
                              b[nb][0], b[nb][2]);
                    mma16816h(acc[mt][2 * nb + 1], a[mt][0], a[mt][1], a[mt][2], a[mt][3],
                              b[nb][1], b[nb][3]);
                }
        }
        __syncthreads();
    }

#pragma unroll
    for (int nt = 0; nt < 8; nt++) {
        const int n = n0g + wn + nt * 8 + (lane & 3) * 2;
        const int wsel = n >> 10, nn = n & 1023;
        const float* bias = (wsel == 0) ? bq : (wsel == 1) ? bk : bv;
        const float b0 = bias[nn], b1 = bias[nn + 1];
        const size_t hoff = ((size_t)(nn >> 6)) * Slen;
        const int d = nn & 63;
        if (wsel == 0) {
#pragma unroll
            for (int mt = 0; mt < 4; mt++)
#pragma unroll
                for (int half = 0; half < 2; half++) {
                    const int r = m0 + wm + mt * 16 + (lane >> 2) + half * 8;
                    const int bb = r >> msh, t = r - (bb << msh);
                    float vx = acc[mt][nt][half * 2 + 0] + b0;
                    float vy = acc[mt][nt][half * 2 + 1] + b1;
                    __half hx = __float2half(vx), hy = __float2half(vy);
                    size_t off = ((size_t)bb * NH * Slen + hoff + t) * DH + d;
                    *(uint32_t*)(oQh + off) = pk2h(__half2float(hx), __half2float(hy));
                    *(uint32_t*)(oQl + off) = pk2h(vx - __half2float(hx),
                                                   vy - __half2float(hy));
                }
        } else {
            __half* pv = (wsel == 1) ? (inst ? oIKf : oKf) : (inst ? oIVf : oVf);
#pragma unroll
            for (int mt = 0; mt < 4; mt++)
#pragma unroll
                for (int half = 0; half < 2; half++) {
                    const int r = m0 + wm + mt * 16 + (lane >> 2) + half * 8;
                    const int bb = r >> msh, t = r - (bb << msh);
                    float vx = acc[mt][nt][half * 2 + 0] + b0;
                    float vy = acc[mt][nt][half * 2 + 1] + b1;
                    size_t off = ((size_t)bb * NH * Slen + hoff + t) * DH + d;
                    *(uint32_t*)(pv + off) = pk2h(vx, vy);
                }
        }
    }
}

// ---------------------------------------------------------------------------
// Attention v5 (all fp16): QK 2-term, P1 sliding window split across all 8
// warps (96 MMAs/warp/tile, perfectly balanced), P2 by warps 4-7, PV fp16.
// ---------------------------------------------------------------------------
#define PST 72
#define P12 132
#define A_SQH 0
#define A_SQL 9216
#define A_KH  18432
#define A_VH  27648
#define A_E0  36864
#define A_E1  46080
#define A_P1A 55296
#define A_P1B 64512
#define A_P2  73728
#define A_SPH A_P2
#define A_STASH A_P1A
#define A_CORR 90624
#define A_SSM 90880
#define A_SSI 91136
#define A_AMSK 91392
#define A_IMSK 91648
#define A_TOTAL 92160

__device__ __forceinline__ void cpa_tile64(uint32_t sb, int dstoff,
                                           const __half* src, int tid)
{
#pragma unroll
    for (int it = 0; it < 2; it++) {
        int i = tid + it * 256;
        int r = i >> 3, c = (i & 7) * 8;
        cpasync16(sb + dstoff + (r * PST + c) * 2, src + r * 64 + c);
    }
}
__device__ __forceinline__ float ldh(const char* sm, int base, int idx) {
    return __half2float(*(const __half*)(sm + base + idx * 2));
}

// QK: 2-term (Qh + Ql) x K, fp16.
__device__ __forceinline__ void qk_tile(float sacc[8][4], uint32_t sb,
                                        int wm, int lane)
{
#pragma unroll
    for (int k = 0; k < 4; k++) {
        const uint32_t ko = (k * 16 + (lane >> 4) * 8) * 2;
        uint32_t aH[4], aL[4];
        ldsm4(aH[0], aH[1], aH[2], aH[3],
              sb + A_SQH + (wm + (lane & 15)) * PST * 2 + ko);
        ldsm4(aL[0], aL[1], aL[2], aL[3],
              sb + A_SQL + (wm + (lane & 15)) * PST * 2 + ko);
#pragma unroll
        for (int nb = 0; nb < 4; nb++) {
            uint32_t bK[4];
            ldsm4(bK[0], bK[1], bK[2], bK[3],
                  sb + A_KH + (nb * 16 + (lane & 15)) * PST * 2 + ko);
            mma16816h(sacc[2 * nb], aH[0], aH[1], aH[2], aH[3], bK[0], bK[2]);
            mma16816h(sacc[2 * nb + 1], aH[0], aH[1], aH[2], aH[3], bK[1], bK[3]);
            mma16816h(sacc[2 * nb], aL[0], aL[1], aL[2], aL[3], bK[0], bK[2]);
            mma16816h(sacc[2 * nb + 1], aL[0], aL[1], aL[2], aL[3], bK[1], bK[3]);
        }
    }
}

// P1 half-chunk: Qh[m0p..m0p+15] @ E(ebuf)[nb0*16 .. nb0*16+31]^T.
__device__ __forceinline__ void p1_half(uint32_t sb, char* sm, int ebuf,
                                        int p1buf, int m0p, int nb0,
                                        int lane, int g, int t4)
{
    float pacc[4][4];
#pragma unroll
    for (int j = 0; j < 4; j++)
#pragma unroll
        for (int p = 0; p < 4; p++) pacc[j][p] = 0.f;
#pragma unroll
    for (int k = 0; k < 4; k++) {
        const uint32_t ko = (k * 16 + (lane >> 4) * 8) * 2;
        uint32_t a[4];
        ldsm4(a[0], a[1], a[2], a[3],
              sb + A_SQH + (m0p + (lane & 15)) * PST * 2 + ko);
#pragma unroll
        for (int nbl = 0; nbl < 2; nbl++) {
            const int gnb = nb0 + nbl;
            uint32_t be[4];
            ldsm4(be[0], be[1], be[2], be[3],
                  sb + ebuf + (gnb * 16 + (lane & 15)) * PST * 2 + ko);
            mma16816h(pacc[2 * nbl], a[0], a[1], a[2], a[3], be[0], be[2]);
            mma16816h(pacc[2 * nbl + 1], a[0], a[1], a[2], a[3], be[1], be[3]);
        }
    }
#pragma unroll
    for (int jl = 0; jl < 4; jl++) {
        int w = 8 * (2 * nb0 + jl) + 2 * t4;
        *(uint32_t*)(sm + p1buf + ((m0p + g) * PST + w) * 2) =
            pk2h(pacc[jl][0], pacc[jl][1]);
        *(uint32_t*)(sm + p1buf + ((m0p + 8 + g) * PST + w) * 2) =
            pk2h(pacc[jl][2], pacc[jl][3]);
    }
}

// P2: K @ E^T (both chunks) -> A_P2 [64 r][128 w], by warps 4-7.
__device__ __forceinline__ void p2_tile(uint32_t sb, char* sm, int rt,
                                        int m0p, int lane, int g, int t4)
{
#pragma unroll
    for (int c = 0; c < 2; c++) {
        const int ebuf = ((rt + c) & 1) ? A_E1 : A_E0;
        float pacc[8][4];
#pragma unroll
        for (int j = 0; j < 8; j++)
#pragma unroll
            for (int p = 0; p < 4; p++) pacc[j][p] = 0.f;
#pragma unroll
        for (int k = 0; k < 4; k++) {
            const uint32_t ko = (k * 16 + (lane >> 4) * 8) * 2;
            uint32_t a[4];
            ldsm4(a[0], a[1], a[2], a[3],
                  sb + A_KH + (m0p + (lane & 15)) * PST * 2 + ko);
#pragma unroll
            for (int nb = 0; nb < 4; nb++) {
                uint32_t be[4];
                ldsm4(be[0], be[1], be[2], be[3],
                      sb + ebuf + (nb * 16 + (lane & 15)) * PST * 2 + ko);
                mma16816h(pacc[2 * nb], a[0], a[1], a[2], a[3], be[0], be[2]);
                mma16816h(pacc[2 * nb + 1], a[0], a[1], a[2], a[3], be[1], be[3]);
            }
        }
#pragma unroll
        for (int j = 0; j < 8; j++) {
            int w = c * 64 + 8 * j + 2 * t4;
            *(uint32_t*)(sm + A_P2 + ((m0p + g) * P12 + w) * 2) =
                pk2h(pacc[j][0], pacc[j][1]);
            *(uint32_t*)(sm + A_P2 + ((m0p + 8 + g) * P12 + w) * 2) =
                pk2h(pacc[j][2], pacc[j][3]);
        }
    }
}

// PV single-term fp16.
__device__ __forceinline__ void pv_tile(float cacc[4][4], uint32_t sb,
                                        int wm2, int wn2, int lane)
{
#pragma unroll
    for (int kk = 0; kk < 4; kk++) {
        const uint32_t ko = (kk * 16 + (lane >> 4) * 8) * 2;
        uint32_t aP[4];
        ldsm4(aP[0], aP[1], aP[2], aP[3],
              sb + A_SPH + (wm2 + (lane & 15)) * PST * 2 + ko);
        const uint32_t trow = (kk * 16 + (lane & 7) + 8 * ((lane >> 3) & 1)) * PST;
#pragma unroll
        for (int dh = 0; dh < 2; dh++) {
            const uint32_t tcol = wn2 + dh * 16 + ((lane >> 4) & 1) * 8;
            uint32_t v[4];
            ldsm4t(v[0], v[1], v[2], v[3], sb + A_VH + (trow + tcol) * 2);
            const int nf = dh * 2;
            mma16816h(cacc[nf], aP[0], aP[1], aP[2], aP[3], v[0], v[1]);
            mma16816h(cacc[nf + 1], aP[0], aP[1], aP[2], aP[3], v[2], v[3]);
        }
    }
}

__global__ __launch_bounds__(256, 2)
void attn_mma(const float* __restrict__ amask, const float* __restrict__ imask,
              const float* __restrict__ gate, float* __restrict__ outp)
{
    extern __shared__ char sm[];
    const uint32_t sb = smem_u32(sm);
    const int tid = threadIdx.x, warp = tid >> 5, lane = tid & 31;
    const int g = lane >> 2, t4 = lane & 3;
    const int bh = blockIdx.y, b = bh >> 4, h = bh & 15;
    const int l0 = blockIdx.x * 64;
    const int wm = warp * 16;
    const int wm2 = (warp >> 1) * 16, wn2 = (warp & 1) * 32;

    cpa_tile64(sb, A_SQH, g_Qh + ((size_t)bh * SQ + l0) * DH, tid);
    cpa_tile64(sb, A_SQL, g_Ql + ((size_t)bh * SQ + l0) * DH, tid);
    if (tid < 32)
        ((float4*)(sm + A_IMSK))[tid] = ((const float4*)(imask + b * LI))[tid];

    float cacc[4][4];
#pragma unroll
    for (int i = 0; i < 4; i++)
#pragma unroll
        for (int j = 0; j < 4; j++) cacc[i][j] = 0.f;
    float mrow[2] = {-1e30f, -1e30f}, ssum[2] = {0.f, 0.f};
    float* corr_sm = (float*)(sm + A_CORR);
    const float* amsk = (const float*)(sm + A_AMSK);
    const float* imsk = (const float*)(sm + A_IMSK);

    // ======================= main pass =======================
    for (int rt = 0; rt < 16; rt++) {
        const int r0 = rt * 64;
        const int epb = (rt & 1) ? A_E1 : A_E0;
        const int p1b = (rt & 1) ? A_P1B : A_P1A;

        cpa_tile64(sb, A_KH, g_Kf + ((size_t)bh * SQ + r0) * DH, tid);
        cpa_tile64(sb, A_VH, g_Vf + ((size_t)bh * SQ + r0) * DH, tid);
        cpa_tile64(sb, epb, g_Ef + (size_t)(l0 - r0 + 960) * 64, tid);
        if (rt == 0)
            cpa_tile64(sb, A_E1, g_Ef + (size_t)(l0 + 1024) * 64, tid);
        if (tid < 64) ((float*)(sm + A_AMSK))[tid] = amask[b * SQ + r0 + tid];
        CP_COMMIT();
        CP_WAIT(0);
        __syncthreads();

        float sacc[8][4];
        if (warp < 4) {
#pragma unroll
            for (int j = 0; j < 8; j++)
#pragma unroll
                for (int p = 0; p < 4; p++) sacc[j][p] = 0.f;
            qk_tile(sacc, sb, wm, lane);
            p1_half(sb, sm, epb, p1b, wm, 0, lane, g, t4);
            if (rt == 0)
                p1_half(sb, sm, A_E1, A_P1B, wm, 0, lane, g, t4);
        } else {
            const int m0p = (warp - 4) * 16;
            p2_tile(sb, sm, rt, m0p, lane, g, t4);
            p1_half(sb, sm, epb, p1b, m0p, 2, lane, g, t4);
            if (rt == 0)
                p1_half(sb, sm, A_E1, A_P1B, m0p, 2, lane, g, t4);
        }
        __syncthreads();

        if (warp < 4) {
            const int l = wm + g;
            const int p1c0 = (rt & 1) ? A_P1B : A_P1A;
            const int p1c1 = (rt & 1) ? A_P1A : A_P1B;
#pragma unroll
            for (int j = 0; j < 8; j++) {
                const int r = 8 * j + 2 * t4;
                const int w = l - r + 63;
                const int w1 = w - 1, w2 = w + 8, w3 = w + 7;
                float p1a  = ldh(sm, (w  >= 64) ? p1c1 : p1c0, l * PST + (w  & 63));
                float p1b_ = ldh(sm, (w1 >= 64) ? p1c1 : p1c0, l * PST + (w1 & 63));
                float p1c  = ldh(sm, (w2 >= 64) ? p1c1 : p1c0, (l + 8) * PST + (w2 & 63));
                float p1d  = ldh(sm, (w3 >= 64) ? p1c1 : p1c0, (l + 8) * PST + (w3 & 63));
                sacc[j][0] = (sacc[j][0] + p1a  + ldh(sm, A_P2, r * P12 + w)) * 0.125f + amsk[r];
                sacc[j][1] = (sacc[j][1] + p1b_ + ldh(sm, A_P2, (r + 1) * P12 + w1)) * 0.125f + amsk[r + 1];
                sacc[j][2] = (sacc[j][2] + p1c  + ldh(sm, A_P2, r * P12 + w2)) * 0.125f + amsk[r];
                sacc[j][3] = (sacc[j][3] + p1d  + ldh(sm, A_P2, (r + 1) * P12 + w3)) * 0.125f + amsk[r + 1];
            }
            float mt0 = -1e30f, mt1 = -1e30f;
#pragma unroll
            for (int j = 0; j < 8; j++) {
                mt0 = fmaxf(mt0, fmaxf(sacc[j][0], sacc[j][1]));
                mt1 = fmaxf(mt1, fmaxf(sacc[j][2], sacc[j][3]));
            }
            mt0 = fmaxf(mt0, __shfl_xor_sync(0xffffffffu, mt0, 1));
            mt0 = fmaxf(mt0, __shfl_xor_sync(0xffffffffu, mt0, 2));
            mt1 = fmaxf(mt1, __shfl_xor_sync(0xffffffffu, mt1, 1));
            mt1 = fmaxf(mt1, __shfl_xor_sync(0xffffffffu, mt1, 2));
            asm volatile("bar.sync 1, 128;" ::: "memory");
            float mn0 = fmaxf(mrow[0], mt0), mn1 = fmaxf(mrow[1], mt1);
            float cr0 = __expf(mrow[0] - mn0), cr1 = __expf(mrow[1] - mn1);
            mrow[0] = mn0; mrow[1] = mn1;
            float ps0 = 0.f, ps1 = 0.f;
#pragma unroll
            for (int j = 0; j < 8; j++) {
                float p00 = __expf(sacc[j][0] - mn0), p01 = __expf(sacc[j][1] - mn0);
                float p10 = __expf(sacc[j][2] - mn1), p11 = __expf(sacc[j][3] - mn1);
                ps0 += p00 + p01; ps1 += p10 + p11;
                int cidx = 8 * j + 2 * t4;
                *(uint32_t*)(sm + A_SPH + (l * PST + cidx) * 2) = pk2h(p00, p01);
                *(uint32_t*)(sm + A_SPH + ((l + 8) * PST + cidx) * 2) = pk2h(p10, p11);
            }
            ps0 += __shfl_xor_sync(0xffffffffu, ps0, 1);
            ps0 += __shfl_xor_sync(0xffffffffu, ps0, 2);
            ps1 += __shfl_xor_sync(0xffffffffu, ps1, 1);
            ps1 += __shfl_xor_sync(0xffffffffu, ps1, 2);
            ssum[0] = ssum[0] * cr0 + ps0;
            ssum[1] = ssum[1] * cr1 + ps1;
            if (t4 == 0) { corr_sm[l] = cr0; corr_sm[l + 8] = cr1; }
        }
        __syncthreads();

        {
            float c0r = corr_sm[wm2 + g], c1r = corr_sm[wm2 + 8 + g];
#pragma unroll
            for (int nf = 0; nf < 4; nf++) {
                cacc[nf][0] *= c0r; cacc[nf][1] *= c0r;
                cacc[nf][2] *= c1r; cacc[nf][3] *= c1r;
            }
            pv_tile(cacc, sb, wm2, wn2, lane);
        }
        __syncthreads();
    }

    // stash main ctx + ssum, reset
    {
        float* stash = (float*)(sm + A_STASH);
#pragma unroll
        for (int nf = 0; nf < 4; nf++) {
            int d = wn2 + 8 * nf + 2 * t4;
            stash[(wm2 + g) * 68 + d] = cacc[nf][0];
            stash[(wm2 + g) * 68 + d + 1] = cacc[nf][1];
            stash[(wm2 + 8 + g) * 68 + d] = cacc[nf][2];
            stash[(wm2 + 8 + g) * 68 + d + 1] = cacc[nf][3];
            cacc[nf][0] = cacc[nf][1] = cacc[nf][2] = cacc[nf][3] = 0.f;
        }
        if (warp < 4 && t4 == 0) {
            ((float*)(sm + A_SSM))[wm + g] = ssum[0];
            ((float*)(sm + A_SSM))[wm + g + 8] = ssum[1];
        }
        mrow[0] = mrow[1] = -1e30f; ssum[0] = ssum[1] = 0.f;
    }
    __syncthreads();

    // ======================= instruct pass =======================
    for (int rt = 0; rt < 2; rt++) {
        const int r0 = rt * 64;
        cpa_tile64(sb, A_KH, g_IKf + ((size_t)bh * LI + r0) * DH, tid);
        cpa_tile64(sb, A_VH, g_IVf + ((size_t)bh * LI + r0) * DH, tid);
        CP_COMMIT();
        CP_WAIT(0);
        __syncthreads();

        if (warp < 4) {
            float sacc[8][4];
#pragma unroll
            for (int j = 0; j < 8; j++)
#pragma unroll
                for (int p = 0; p < 4; p++) sacc[j][p] = 0.f;
            qk_tile(sacc, sb, wm, lane);

            const int l = wm + g;
            float mt0 = -1e30f, mt1 = -1e30f;
#pragma unroll
            for (int j = 0; j < 8; j++) {
                const int r = 8 * j + 2 * t4;
                sacc[j][0] = sacc[j][0] * 0.125f + imsk[r0 + r];
                sacc[j][1] = sacc[j][1] * 0.125f + imsk[r0 + r + 1];
                sacc[j][2] = sacc[j][2] * 0.125f + imsk[r0 + r];
                sacc[j][3] = sacc[j][3] * 0.125f + imsk[r0 + r + 1];
                mt0 = fmaxf(mt0, fmaxf(sacc[j][0], sacc[j][1]));
                mt1 = fmaxf(mt1, fmaxf(sacc[j][2], sacc[j][3]));
            }
            mt0 = fmaxf(mt0, __shfl_xor_sync(0xffffffffu, mt0, 1));
            mt0 = fmaxf(mt0, __shfl_xor_sync(0xffffffffu, mt0, 2));
            mt1 = fmaxf(mt1, __shfl_xor_sync(0xffffffffu, mt1, 1));
            mt1 = fmaxf(mt1, __shfl_xor_sync(0xffffffffu, mt1, 2));
            float mn0 = fmaxf(mrow[0], mt0), mn1 = fmaxf(mrow[1], mt1);
            float cr0 = __expf(mrow[0] - mn0), cr1 = __expf(mrow[1] - mn1);
            mrow[0] = mn0; mrow[1] = mn1;
            float ps0 = 0.f, ps1 = 0.f;
#pragma unroll
            for (int j = 0; j < 8; j++) {
                float p00 = __expf(sacc[j][0] - mn0), p01 = __expf(sacc[j][1] - mn0);
                float p10 = __expf(sacc[j][2] - mn1), p11 = __expf(sacc[j][3] - mn1);
                ps0 += p00 + p01; ps1 += p10 + p11;
                int cidx = 8 * j + 2 * t4;
                *(uint32_t*)(sm + A_SPH + (l * PST + cidx) * 2) = pk2h(p00, p01);
                *(uint32_t*)(sm + A_SPH + ((l + 8) * PST + cidx) * 2) = pk2h(p10, p11);
            }
            ps0 += __shfl_xor_sync(0xffffffffu, ps0, 1);
            ps0 += __shfl_xor_sync(0xffffffffu, ps0, 2);
            ps1 += __shfl_xor_sync(0xffffffffu, ps1, 1);
            ps1 += __shfl_xor_sync(0xffffffffu, ps1, 2);
            ssum[0] = ssum[0] * cr0 + ps0;
            ssum[1] = ssum[1] * cr1 + ps1;
            if (t4 == 0) { corr_sm[l] = cr0; corr_sm[l + 8] = cr1; }
        }
        __syncthreads();

        {
            float c0r = corr_sm[wm2 + g], c1r = corr_sm[wm2 + 8 + g];
#pragma unroll
            for (int nf = 0; nf < 4; nf++) {
                cacc[nf][0] *= c0r; cacc[nf][1] *= c0r;
                cacc[nf][2] *= c1r; cacc[nf][3] *= c1r;
            }
            pv_tile(cacc, sb, wm2, wn2, lane);
        }
        __syncthreads();
    }

    if (warp < 4 && t4 == 0) {
        ((float*)(sm + A_SSI))[wm + g] = ssum[0];
        ((float*)(sm + A_SSI))[wm + g + 8] = ssum[1];
    }
    __syncthreads();

    {
        const float tg = tanhf(gate[h]);
        const float* stash = (const float*)(sm + A_STASH);
        const float* ssmv = (const float*)(sm + A_SSM);
        const float* ssiv = (const float*)(sm + A_SSI);
        const float rnm0 = 1.f / ssmv[wm2 + g], rni0 = tg / ssiv[wm2 + g];
        const float rnm1 = 1.f / ssmv[wm2 + 8 + g], rni1 = tg / ssiv[wm2 + 8 + g];
#pragma unroll
        for (int nf = 0; nf < 4; nf++) {
            const int d = wn2 + 8 * nf + 2 * t4;
            float2 o0, o1;
            o0.x = stash[(wm2 + g) * 68 + d] * rnm0 + cacc[nf][0] * rni0;
            o0.y = stash[(wm2 + g) * 68 + d + 1] * rnm0 + cacc[nf][1] * rni0;
            o1.x = stash[(wm2 + 8 + g) * 68 + d] * rnm1 + cacc[nf][2] * rni1;
            o1.y = stash[(wm2 + 8 + g) * 68 + d + 1] * rnm1 + cacc[nf][3] * rni1;
            *(float2*)(outp + ((size_t)(b * SQ + l0 + wm2 + g)) * HIDDEN + h * DH + d) = o0;
            *(float2*)(outp + ((size_t)(b * SQ + l0 + wm2 + 8 + g)) * HIDDEN + h * DH + d) = o1;
        }
    }
}

// ---------------------------------------------------------------------------
extern "C" void kernel_launch(void* const* d_in, const int* in_sizes, int n_in,
                              void* d_out, int out_size)
{
    (void)in_sizes; (void)n_in; (void)out_size;
    const float* hs    = (const float*)d_in[0];
    const float* amask = (const float*)d_in[1];
    const float* ihs   = (const float*)d_in[2];
    const float* imask = (const float*)d_in[3];
    const float* Wq    = (const float*)d_in[4];
    const float* bq    = (const float*)d_in[5];
    const float* Wk    = (const float*)d_in[6];
    const float* bk    = (const float*)d_in[7];
    const float* Wv    = (const float*)d_in[8];
    const float* bv    = (const float*)d_in[9];
    const float* gate  = (const float*)d_in[10];
    const float* dist  = (const float*)d_in[11];
    float* out = (float*)d_out;

    __half *qh, *ql, *kf, *vf, *ikf, *ivf, *ef, *xc, *ixc, *wc;
    cudaGetSymbolAddress((void**)&qh, g_Qh);
    cudaGetSymbolAddress((void**)&ql, g_Ql);
    cudaGetSymbolAddress((void**)&kf, g_Kf);
    cudaGetSymbolAddress((void**)&vf, g_Vf);
    cudaGetSymbolAddress((void**)&ikf, g_IKf);
    cudaGetSymbolAddress((void**)&ivf, g_IVf);
    cudaGetSymbolAddress((void**)&ef, g_Ef);
    cudaGetSymbolAddress((void**)&xc, g_Xcat);
    cudaGetSymbolAddress((void**)&ixc, g_IXcat);
    cudaGetSymbolAddress((void**)&wc, g_Wh);

    cudaFuncSetAttribute(gemm_mma, cudaFuncAttributeMaxDynamicSharedMemorySize, GEMM_SMEM);
    cudaFuncSetAttribute(attn_mma, cudaFuncAttributeMaxDynamicSharedMemorySize, A_TOTAL);

    conv_all<<<NX_BASE3 + NX_W, 256>>>((const float4*)hs, xc,
                                       (const float4*)ihs, ixc, dist, ef,
                                       Wq, Wk, Wv, wc);

    gemm_mma<<<416, 256, GEMM_SMEM>>>(xc, ixc, wc, bq, bk, bv,
                                      qh, ql, kf, vf, ikf, ivf);

    attn_mma<<<dim3(SQ / 64, BHN), 256, A_TOTAL>>>(amask, imask, gate, out);
}

// round 13
// speedup vs baseline: 1.8776x; 1.2453x over previous
#include <cuda_runtime.h>
#include <cuda_bf16.h>
#include <cuda_fp16.h>
#include <math.h>
#include <cstdint>

#define NB 4
#define NH 16
#define DH 64
#define SQ 1024
#define LI 128
#define HIDDEN 1024
#define BHN (NB * NH)

// ---------------- scratch (all fp16) ----------------------------------------
__device__ __align__(16) __half g_Qh[BHN * SQ * DH];
__device__ __align__(16) __half g_Ql[BHN * SQ * DH];
__device__ __align__(16) __half g_Kf[BHN * SQ * DH];
__device__ __align__(16) __half g_Vf[BHN * SQ * DH];
__device__ __align__(16) __half g_IKf[BHN * LI * DH];
__device__ __align__(16) __half g_IVf[BHN * LI * DH];
__device__ __align__(16) __half g_Ef[2048 * DH];

__device__ __align__(16) __half g_Xh[NB * SQ * HIDDEN];
__device__ __align__(16) __half g_IXh[NB * LI * HIDDEN];
__device__ __align__(16) __half g_Wh[3 * HIDDEN * HIDDEN];   // [n(3072)][k(1024)]

// ---------------- helpers ---------------------------------------------------
__device__ __forceinline__ uint32_t smem_u32(const void* p) {
    uint32_t a;
    asm("{ .reg .u64 t; cvta.to.shared.u64 t, %1; cvt.u32.u64 %0, t; }" : "=r"(a) : "l"(p));
    return a;
}
__device__ __forceinline__ void ldsm4(uint32_t& r0, uint32_t& r1, uint32_t& r2,
                                      uint32_t& r3, uint32_t addr) {
    asm volatile("ldmatrix.sync.aligned.m8n8.x4.shared.b16 {%0,%1,%2,%3}, [%4];"
                 : "=r"(r0), "=r"(r1), "=r"(r2), "=r"(r3) : "r"(addr));
}
__device__ __forceinline__ void ldsm4t(uint32_t& r0, uint32_t& r1, uint32_t& r2,
                                       uint32_t& r3, uint32_t addr) {
    asm volatile("ldmatrix.sync.aligned.m8n8.x4.trans.shared.b16 {%0,%1,%2,%3}, [%4];"
                 : "=r"(r0), "=r"(r1), "=r"(r2), "=r"(r3) : "r"(addr));
}
__device__ __forceinline__ void mma16816h(float* c, uint32_t a0, uint32_t a1,
                                          uint32_t a2, uint32_t a3,
                                          uint32_t b0, uint32_t b1) {
    asm volatile(
        "mma.sync.aligned.m16n8k16.row.col.f32.f16.f16.f32 "
        "{%0,%1,%2,%3}, {%4,%5,%6,%7}, {%8,%9}, {%0,%1,%2,%3};"
        : "+f"(c[0]), "+f"(c[1]), "+f"(c[2]), "+f"(c[3])
        : "r"(a0), "r"(a1), "r"(a2), "r"(a3), "r"(b0), "r"(b1));
}
__device__ __forceinline__ uint32_t pk2h(float a, float b) {
    __half2 t = __floats2half2_rn(a, b);
    return *(uint32_t*)&t;
}
__device__ __forceinline__ void cpasync16(uint32_t dst, const void* src) {
    asm volatile("cp.async.cg.shared.global [%0], [%1], 16;" :: "r"(dst), "l"(src));
}
#define CP_COMMIT() asm volatile("cp.async.commit_group;" ::: "memory")
#define CP_WAIT(n)  asm volatile("cp.async.wait_group %0;" :: "n"(n) : "memory")

// ---------------------------------------------------------------------------
// Conversions: X / X-instruct / E / W merged (single-term fp16 everywhere).
// ---------------------------------------------------------------------------
#define NX_MAIN (NB * SQ * HIDDEN / 4 / 256)
#define NX_INST (NB * LI * HIDDEN / 4 / 256)
#define NX_E    (2048 * 64 / 256)
#define NX_W    3072
#define NX_BASE3 (NX_MAIN + NX_INST + NX_E)

__global__ __launch_bounds__(256)
void conv_all(const float4* __restrict__ xm, __half* __restrict__ dm,
              const float4* __restrict__ xi, __half* __restrict__ di,
              const float* __restrict__ dist, __half* __restrict__ eh,
              const float* __restrict__ Wq, const float* __restrict__ Wk,
              const float* __restrict__ Wv, __half* __restrict__ wdst)
{
    __shared__ float t[32][33];
    int blk = blockIdx.x;
    if (blk >= NX_BASE3) {
        int wblk = blk - NX_BASE3;
        int z = wblk >> 10, rem = wblk & 1023;
        int bx = rem & 31, by = rem >> 5;
        const float* W = (z == 0) ? Wq : (z == 1) ? Wk : Wv;
        int tx = threadIdx.x & 31, ty = threadIdx.x >> 5;
        int n = bx * 32 + tx, k0 = by * 32;
#pragma unroll
        for (int j = 0; j < 4; j++)
            t[ty + 8 * j][tx] = W[(size_t)(k0 + ty + 8 * j) * HIDDEN + n];
        __syncthreads();
        size_t nrow = (size_t)z * HIDDEN + bx * 32;
#pragma unroll
        for (int j = 0; j < 4; j++)
            wdst[(nrow + ty + 8 * j) * HIDDEN + k0 + tx] = __float2half(t[tx][ty + 8 * j]);
        return;
    }
    if (blk >= NX_MAIN + NX_INST) {
        int i = (blk - NX_MAIN - NX_INST) * 256 + threadIdx.x;
        float v = (i < 2047 * 64) ? dist[i] : 0.f;
        eh[i] = __float2half(v);
        return;
    }
    const float4* src = (blk < NX_MAIN) ? xm : xi;
    __half* dst = (blk < NX_MAIN) ? dm : di;
    int i = ((blk < NX_MAIN) ? blk : blk - NX_MAIN) * 256 + threadIdx.x;
    float4 v = src[i];
    uint2 H;
    H.x = pk2h(v.x, v.y);
    H.y = pk2h(v.z, v.w);
    *(uint2*)(dst + (size_t)i * 4) = H;
}

// ---------------------------------------------------------------------------
// Merged projection GEMM: K=1024 fp16. Q -> fp16 hi/lo; K,V -> fp16 single.
// ---------------------------------------------------------------------------
#define AST 72
#define TA (128 * AST * 2)
#define TB (256 * AST * 2)
#define GEMM_SMEM (2 * (TA + TB))

__global__ __launch_bounds__(256, 1)
void gemm_mma(const __half* __restrict__ Am, const __half* __restrict__ Ai,
              const __half* __restrict__ Bm,
              const float* __restrict__ bq, const float* __restrict__ bk,
              const float* __restrict__ bv,
              __half* oQh, __half* oQl, __half* oKf, __half* oVf,
              __half* oIKf, __half* oIVf)
{
    extern __shared__ char smem[];
    const uint32_t sb = smem_u32(smem);
    const int tid = threadIdx.x, warp = tid >> 5, lane = tid & 31;

    const __half* A;
    int msh, Slen, m0, n0g, inst;
    {
        int blk = blockIdx.x;
        if (blk < 384) {
            A = Am; msh = 10; Slen = SQ; inst = 0;
            m0 = (blk / 12) * 128; n0g = (blk % 12) * 256;
        } else {
            blk -= 384;
            A = Ai; msh = 7; Slen = LI; inst = 1;
            m0 = (blk / 8) * 128; n0g = 1024 + (blk % 8) * 256;
        }
    }
    const int wm = (warp >> 2) * 64, wn = (warp & 3) * 64;

    const int cr = tid >> 3, cko = (tid & 7) * 8;
    const __half* Ag = A + (size_t)(m0 + cr) * HIDDEN + cko;
    const __half* Bg = Bm + (size_t)(n0g + cr) * HIDDEN + cko;
    const uint32_t sAo = (cr * AST + cko) * 2;

    float acc[4][8][4];
#pragma unroll
    for (int i = 0; i < 4; i++)
#pragma unroll
        for (int j = 0; j < 8; j++)
#pragma unroll
            for (int p = 0; p < 4; p++) acc[i][j][p] = 0.f;

#pragma unroll
    for (int i = 0; i < 4; i++)
        cpasync16(sb + sAo + i * 32 * AST * 2, Ag + (size_t)(i * 32) * HIDDEN);
#pragma unroll
    for (int i = 0; i < 8; i++)
        cpasync16(sb + TA + sAo + i * 32 * AST * 2, Bg + (size_t)(i * 32) * HIDDEN);
    CP_COMMIT();

    const int NCH = 16;
    for (int c = 0; c < NCH; c++) {
        const int p = c & 1;
        if (c + 1 < NCH) {
            const int pn = (c + 1) & 1;
            const int koff = (c + 1) * 64;
#pragma unroll
            for (int i = 0; i < 4; i++)
                cpasync16(sb + pn * (TA + TB) + sAo + i * 32 * AST * 2,
                          Ag + (size_t)(i * 32) * HIDDEN + koff);
#pragma unroll
            for (int i = 0; i < 8; i++)
                cpasync16(sb + pn * (TA + TB) + TA + sAo + i * 32 * AST * 2,
                          Bg + (size_t)(i * 32) * HIDDEN + koff);
            CP_COMMIT();
            CP_WAIT(1);
        } else {
            CP_WAIT(0);
        }
        __syncthreads();

        const uint32_t aw = sb + p * (TA + TB) +
                            ((wm + (lane & 15)) * AST + (lane >> 4) * 8) * 2;
        const uint32_t bw = sb + p * (TA + TB) + TA +
                            ((wn + (lane & 15)) * AST + (lane >> 4) * 8) * 2;
#pragma unroll
        for (int k16 = 0; k16 < 4; k16++) {
            const uint32_t ko = k16 * 32;
            uint32_t a[4][4], b[4][4];
#pragma unroll
            for (int mt = 0; mt < 4; mt++)
                ldsm4(a[mt][0], a[mt][1], a[mt][2], a[mt][3],
                      aw + mt * 16 * AST * 2 + ko);
#pragma unroll
            for (int nb = 0; nb < 4; nb++)
                ldsm4(b[nb][0], b[nb][1], b[nb][2], b[nb][3],
                      bw + nb * 16 * AST * 2 + ko);
#pragma unroll
            for (int mt = 0; mt < 4; mt++)
#pragma unroll
                for (int nb = 0; nb < 4; nb++) {
                    mma16816h(acc[mt][2 * nb], a[mt][0], a[mt][1], a[mt][2], a[mt][3],
                              b[nb][0], b[nb][2]);
                    mma16816h(acc[mt][2 * nb + 1], a[mt][0], a[mt][1], a[mt][2], a[mt][3],
                              b[nb][1], b[nb][3]);
                }
        }
        __syncthreads();
    }

#pragma unroll
    for (int nt = 0; nt < 8; nt++) {
        const int n = n0g + wn + nt * 8 + (lane & 3) * 2;
        const int wsel = n >> 10, nn = n & 1023;
        const float* bias = (wsel == 0) ? bq : (wsel == 1) ? bk : bv;
        const float b0 = bias[nn], b1 = bias[nn + 1];
        const size_t hoff = ((size_t)(nn >> 6)) * Slen;
        const int d = nn & 63;
        if (wsel == 0) {
#pragma unroll
            for (int mt = 0; mt < 4; mt++)
#pragma unroll
                for (int half = 0; half < 2; half++) {
                    const int r = m0 + wm + mt * 16 + (lane >> 2) + half * 8;
                    const int bb = r >> msh, t = r - (bb << msh);
                    float vx = acc[mt][nt][half * 2 + 0] + b0;
                    float vy = acc[mt][nt][half * 2 + 1] + b1;
                    __half hx = __float2half(vx), hy = __float2half(vy);
                    size_t off = ((size_t)bb * NH * Slen + hoff + t) * DH + d;
                    *(uint32_t*)(oQh + off) = pk2h(__half2float(hx), __half2float(hy));
                    *(uint32_t*)(oQl + off) = pk2h(vx - __half2float(hx),
                                                   vy - __half2float(hy));
                }
        } else {
            __half* pv = (wsel == 1) ? (inst ? oIKf : oKf) : (inst ? oIVf : oVf);
#pragma unroll
            for (int mt = 0; mt < 4; mt++)
#pragma unroll
                for (int half = 0; half < 2; half++) {
                    const int r = m0 + wm + mt * 16 + (lane >> 2) + half * 8;
                    const int bb = r >> msh, t = r - (bb << msh);
                    float vx = acc[mt][nt][half * 2 + 0] + b0;
                    float vy = acc[mt][nt][half * 2 + 1] + b1;
                    size_t off = ((size_t)bb * NH * Slen + hoff + t) * DH + d;
                    *(uint32_t*)(pv + off) = pk2h(vx, vy);
                }
        }
    }
}

// ---------------------------------------------------------------------------
// Attention v5 (unchanged from R12): QK 2-term, P1 sliding window balanced
// across 8 warps, P2 by warps 4-7, PV fp16. 90 KB smem, 2 CTAs/SM.
// ---------------------------------------------------------------------------
#define PST 72
#define P12 132
#define A_SQH 0
#define A_SQL 9216
#define A_KH  18432
#define A_VH  27648
#define A_E0  36864
#define A_E1  46080
#define A_P1A 55296
#define A_P1B 64512
#define A_P2  73728
#define A_SPH A_P2
#define A_STASH A_P1A
#define A_CORR 90624
#define A_SSM 90880
#define A_SSI 91136
#define A_AMSK 91392
#define A_IMSK 91648
#define A_TOTAL 92160

__device__ __forceinline__ void cpa_tile64(uint32_t sb, int dstoff,
                                           const __half* src, int tid)
{
#pragma unroll
    for (int it = 0; it < 2; it++) {
        int i = tid + it * 256;
        int r = i >> 3, c = (i & 7) * 8;
        cpasync16(sb + dstoff + (r * PST + c) * 2, src + r * 64 + c);
    }
}
__device__ __forceinline__ float ldh(const char* sm, int base, int idx) {
    return __half2float(*(const __half*)(sm + base + idx * 2));
}

__device__ __forceinline__ void qk_tile(float sacc[8][4], uint32_t sb,
                                        int wm, int lane)
{
#pragma unroll
    for (int k = 0; k < 4; k++) {
        const uint32_t ko = (k * 16 + (lane >> 4) * 8) * 2;
        uint32_t aH[4], aL[4];
        ldsm4(aH[0], aH[1], aH[2], aH[3],
              sb + A_SQH + (wm + (lane & 15)) * PST * 2 + ko);
        ldsm4(aL[0], aL[1], aL[2], aL[3],
              sb + A_SQL + (wm + (lane & 15)) * PST * 2 + ko);
#pragma unroll
        for (int nb = 0; nb < 4; nb++) {
            uint32_t bK[4];
            ldsm4(bK[0], bK[1], bK[2], bK[3],
                  sb + A_KH + (nb * 16 + (lane & 15)) * PST * 2 + ko);
            mma16816h(sacc[2 * nb], aH[0], aH[1], aH[2], aH[3], bK[0], bK[2]);
            mma16816h(sacc[2 * nb + 1], aH[0], aH[1], aH[2], aH[3], bK[1], bK[3]);
            mma16816h(sacc[2 * nb], aL[0], aL[1], aL[2], aL[3], bK[0], bK[2]);
            mma16816h(sacc[2 * nb + 1], aL[0], aL[1], aL[2], aL[3], bK[1], bK[3]);
        }
    }
}

__device__ __forceinline__ void p1_half(uint32_t sb, char* sm, int ebuf,
                                        int p1buf, int m0p, int nb0,
                                        int lane, int g, int t4)
{
    float pacc[4][4];
#pragma unroll
    for (int j = 0; j < 4; j++)
#pragma unroll
        for (int p = 0; p < 4; p++) pacc[j][p] = 0.f;
#pragma unroll
    for (int k = 0; k < 4; k++) {
        const uint32_t ko = (k * 16 + (lane >> 4) * 8) * 2;
        uint32_t a[4];
        ldsm4(a[0], a[1], a[2], a[3],
              sb + A_SQH + (m0p + (lane & 15)) * PST * 2 + ko);
#pragma unroll
        for (int nbl = 0; nbl < 2; nbl++) {
            const int gnb = nb0 + nbl;
            uint32_t be[4];
            ldsm4(be[0], be[1], be[2], be[3],
                  sb + ebuf + (gnb * 16 + (lane & 15)) * PST * 2 + ko);
            mma16816h(pacc[2 * nbl], a[0], a[1], a[2], a[3], be[0], be[2]);
            mma16816h(pacc[2 * nbl + 1], a[0], a[1], a[2], a[3], be[1], be[3]);
        }
    }
#pragma unroll
    for (int jl = 0; jl < 4; jl++) {
        int w = 8 * (2 * nb0 + jl) + 2 * t4;
        *(uint32_t*)(sm + p1buf + ((m0p + g) * PST + w) * 2) =
            pk2h(pacc[jl][0], pacc[jl][1]);
        *(uint32_t*)(sm + p1buf + ((m0p + 8 + g) * PST + w) * 2) =
            pk2h(pacc[jl][2], pacc[jl][3]);
    }
}

__device__ __forceinline__ void p2_tile(uint32_t sb, char* sm, int rt,
                                        int m0p, int lane, int g, int t4)
{
#pragma unroll
    for (int c = 0; c < 2; c++) {
        const int ebuf = ((rt + c) & 1) ? A_E1 : A_E0;
        float pacc[8][4];
#pragma unroll
        for (int j = 0; j < 8; j++)
#pragma unroll
            for (int p = 0; p < 4; p++) pacc[j][p] = 0.f;
#pragma unroll
        for (int k = 0; k < 4; k++) {
            const uint32_t ko = (k * 16 + (lane >> 4) * 8) * 2;
            uint32_t a[4];
            ldsm4(a[0], a[1], a[2], a[3],
                  sb + A_KH + (m0p + (lane & 15)) * PST * 2 + ko);
#pragma unroll
            for (int nb = 0; nb < 4; nb++) {
                uint32_t be[4];
                ldsm4(be[0], be[1], be[2], be[3],
                      sb + ebuf + (nb * 16 + (lane & 15)) * PST * 2 + ko);
                mma16816h(pacc[2 * nb], a[0], a[1], a[2], a[3], be[0], be[2]);
                mma16816h(pacc[2 * nb + 1], a[0], a[1], a[2], a[3], be[1], be[3]);
            }
        }
#pragma unroll
        for (int j = 0; j < 8; j++) {
            int w = c * 64 + 8 * j + 2 * t4;
            *(uint32_t*)(sm + A_P2 + ((m0p + g) * P12 + w) * 2) =
                pk2h(pacc[j][0], pacc[j][1]);
            *(uint32_t*)(sm + A_P2 + ((m0p + 8 + g) * P12 + w) * 2) =
                pk2h(pacc[j][2], pacc[j][3]);
        }
    }
}

__device__ __forceinline__ void pv_tile(float cacc[4][4], uint32_t sb,
                                        int wm2, int wn2, int lane)
{
#pragma unroll
    for (int kk = 0; kk < 4; kk++) {
        const uint32_t ko = (kk * 16 + (lane >> 4) * 8) * 2;
        uint32_t aP[4];
        ldsm4(aP[0], aP[1], aP[2], aP[3],
              sb + A_SPH + (wm2 + (lane & 15)) * PST * 2 + ko);
        const uint32_t trow = (kk * 16 + (lane & 7) + 8 * ((lane >> 3) & 1)) * PST;
#pragma unroll
        for (int dh = 0; dh < 2; dh++) {
            const uint32_t tcol = wn2 + dh * 16 + ((lane >> 4) & 1) * 8;
            uint32_t v[4];
            ldsm4t(v[0], v[1], v[2], v[3], sb + A_VH + (trow + tcol) * 2);
            const int nf = dh * 2;
            mma16816h(cacc[nf], aP[0], aP[1], aP[2], aP[3], v[0], v[1]);
            mma16816h(cacc[nf + 1], aP[0], aP[1], aP[2], aP[3], v[2], v[3]);
        }
    }
}

__global__ __launch_bounds__(256, 2)
void attn_mma(const float* __restrict__ amask, const float* __restrict__ imask,
              const float* __restrict__ gate, float* __restrict__ outp)
{
    extern __shared__ char sm[];
    const uint32_t sb = smem_u32(sm);
    const int tid = threadIdx.x, warp = tid >> 5, lane = tid & 31;
    const int g = lane >> 2, t4 = lane & 3;
    const int bh = blockIdx.y, b = bh >> 4, h = bh & 15;
    const int l0 = blockIdx.x * 64;
    const int wm = warp * 16;
    const int wm2 = (warp >> 1) * 16, wn2 = (warp & 1) * 32;

    cpa_tile64(sb, A_SQH, g_Qh + ((size_t)bh * SQ + l0) * DH, tid);
    cpa_tile64(sb, A_SQL, g_Ql + ((size_t)bh * SQ + l0) * DH, tid);
    if (tid < 32)
        ((float4*)(sm + A_IMSK))[tid] = ((const float4*)(imask + b * LI))[tid];

    float cacc[4][4];
#pragma unroll
    for (int i = 0; i < 4; i++)
#pragma unroll
        for (int j = 0; j < 4; j++) cacc[i][j] = 0.f;
    float mrow[2] = {-1e30f, -1e30f}, ssum[2] = {0.f, 0.f};
    float* corr_sm = (float*)(sm + A_CORR);
    const float* amsk = (const float*)(sm + A_AMSK);
    const float* imsk = (const float*)(sm + A_IMSK);

    // ======================= main pass =======================
    for (int rt = 0; rt < 16; rt++) {
        const int r0 = rt * 64;
        const int epb = (rt & 1) ? A_E1 : A_E0;
        const int p1b = (rt & 1) ? A_P1B : A_P1A;

        cpa_tile64(sb, A_KH, g_Kf + ((size_t)bh * SQ + r0) * DH, tid);
        cpa_tile64(sb, A_VH, g_Vf + ((size_t)bh * SQ + r0) * DH, tid);
        cpa_tile64(sb, epb, g_Ef + (size_t)(l0 - r0 + 960) * 64, tid);
        if (rt == 0)
            cpa_tile64(sb, A_E1, g_Ef + (size_t)(l0 + 1024) * 64, tid);
        if (tid < 64) ((float*)(sm + A_AMSK))[tid] = amask[b * SQ + r0 + tid];
        CP_COMMIT();
        CP_WAIT(0);
        __syncthreads();

        float sacc[8][4];
        if (warp < 4) {
#pragma unroll
            for (int j = 0; j < 8; j++)
#pragma unroll
                for (int p = 0; p < 4; p++) sacc[j][p] = 0.f;
            qk_tile(sacc, sb, wm, lane);
            p1_half(sb, sm, epb, p1b, wm, 0, lane, g, t4);
            if (rt == 0)
                p1_half(sb, sm, A_E1, A_P1B, wm, 0, lane, g, t4);
        } else {
            const int m0p = (warp - 4) * 16;
            p2_tile(sb, sm, rt, m0p, lane, g, t4);
            p1_half(sb, sm, epb, p1b, m0p, 2, lane, g, t4);
            if (rt == 0)
                p1_half(sb, sm, A_E1, A_P1B, m0p, 2, lane, g, t4);
        }
        __syncthreads();

        if (warp < 4) {
            const int l = wm + g;
            const int p1c0 = (rt & 1) ? A_P1B : A_P1A;
            const int p1c1 = (rt & 1) ? A_P1A : A_P1B;
#pragma unroll
            for (int j = 0; j < 8; j++) {
                const int r = 8 * j + 2 * t4;
                const int w = l - r + 63;
                const int w1 = w - 1, w2 = w + 8, w3 = w + 7;
                float p1a  = ldh(sm, (w  >= 64) ? p1c1 : p1c0, l * PST + (w  & 63));
                float p1b_ = ldh(sm, (w1 >= 64) ? p1c1 : p1c0, l * PST + (w1 & 63));
                float p1c  = ldh(sm, (w2 >= 64) ? p1c1 : p1c0, (l + 8) * PST + (w2 & 63));
                float p1d  = ldh(sm, (w3 >= 64) ? p1c1 : p1c0, (l + 8) * PST + (w3 & 63));
                sacc[j][0] = (sacc[j][0] + p1a  + ldh(sm, A_P2, r * P12 + w)) * 0.125f + amsk[r];
                sacc[j][1] = (sacc[j][1] + p1b_ + ldh(sm, A_P2, (r + 1) * P12 + w1)) * 0.125f + amsk[r + 1];
                sacc[j][2] = (sacc[j][2] + p1c  + ldh(sm, A_P2, r * P12 + w2)) * 0.125f + amsk[r];
                sacc[j][3] = (sacc[j][3] + p1d  + ldh(sm, A_P2, (r + 1) * P12 + w3)) * 0.125f + amsk[r + 1];
            }
            float mt0 = -1e30f, mt1 = -1e30f;
#pragma unroll
            for (int j = 0; j < 8; j++) {
                mt0 = fmaxf(mt0, fmaxf(sacc[j][0], sacc[j][1]));
                mt1 = fmaxf(mt1, fmaxf(sacc[j][2], sacc[j][3]));
            }
            mt0 = fmaxf(mt0, __shfl_xor_sync(0xffffffffu, mt0, 1));
            mt0 = fmaxf(mt0, __shfl_xor_sync(0xffffffffu, mt0, 2));
            mt1 = fmaxf(mt1, __shfl_xor_sync(0xffffffffu, mt1, 1));
            mt1 = fmaxf(mt1, __shfl_xor_sync(0xffffffffu, mt1, 2));
            asm volatile("bar.sync 1, 128;" ::: "memory");
            float mn0 = fmaxf(mrow[0], mt0), mn1 = fmaxf(mrow[1], mt1);
            float cr0 = __expf(mrow[0] - mn0), cr1 = __expf(mrow[1] - mn1);
            mrow[0] = mn0; mrow[1] = mn1;
            float ps0 = 0.f, ps1 = 0.f;
#pragma unroll
            for (int j = 0; j < 8; j++) {
                float p00 = __expf(sacc[j][0] - mn0), p01 = __expf(sacc[j][1] - mn0);
                float p10 = __expf(sacc[j][2] - mn1), p11 = __expf(sacc[j][3] - mn1);
                ps0 += p00 + p01; ps1 += p10 + p11;
                int cidx = 8 * j + 2 * t4;
                *(uint32_t*)(sm + A_SPH + (l * PST + cidx) * 2) = pk2h(p00, p01);
                *(uint32_t*)(sm + A_SPH + ((l + 8) * PST + cidx) * 2) = pk2h(p10, p11);
            }
            ps0 += __shfl_xor_sync(0xffffffffu, ps0, 1);
            ps0 += __shfl_xor_sync(0xffffffffu, ps0, 2);
            ps1 += __shfl_xor_sync(0xffffffffu, ps1, 1);
            ps1 += __shfl_xor_sync(0xffffffffu, ps1, 2);
            ssum[0] = ssum[0] * cr0 + ps0;
            ssum[1] = ssum[1] * cr1 + ps1;
            if (t4 == 0) { corr_sm[l] = cr0; corr_sm[l + 8] = cr1; }
        }
        __syncthreads();

        {
            float c0r = corr_sm[wm2 + g], c1r = corr_sm[wm2 + 8 + g];
#pragma unroll
            for (int nf = 0; nf < 4; nf++) {
                cacc[nf][0] *= c0r; cacc[nf][1] *= c0r;
                cacc[nf][2] *= c1r; cacc[nf][3] *= c1r;
            }
            pv_tile(cacc, sb, wm2, wn2, lane);
        }
        __syncthreads();
    }

    // stash main ctx + ssum, reset
    {
        float* stash = (float*)(sm + A_STASH);
#pragma unroll
        for (int nf = 0; nf < 4; nf++) {
            int d = wn2 + 8 * nf + 2 * t4;
            stash[(wm2 + g) * 68 + d] = cacc[nf][0];
            stash[(wm2 + g) * 68 + d + 1] = cacc[nf][1];
            stash[(wm2 + 8 + g) * 68 + d] = cacc[nf][2];
            stash[(wm2 + 8 + g) * 68 + d + 1] = cacc[nf][3];
            cacc[nf][0] = cacc[nf][1] = cacc[nf][2] = cacc[nf][3] = 0.f;
        }
        if (warp < 4 && t4 == 0) {
            ((float*)(sm + A_SSM))[wm + g] = ssum[0];
            ((float*)(sm + A_SSM))[wm + g + 8] = ssum[1];
        }
        mrow[0] = mrow[1] = -1e30f; ssum[0] = ssum[1] = 0.f;
    }
    __syncthreads();

    // ======================= instruct pass =======================
    for (int rt = 0; rt < 2; rt++) {
        const int r0 = rt * 64;
        cpa_tile64(sb, A_KH, g_IKf + ((size_t)bh * LI + r0) * DH, tid);
        cpa_tile64(sb, A_VH, g_IVf + ((size_t)bh * LI + r0) * DH, tid);
        CP_COMMIT();
        CP_WAIT(0);
        __syncthreads();

        if (warp < 4) {
            float sacc[8][4];
#pragma unroll
            for (int j = 0; j < 8; j++)
#pragma unroll
                for (int p = 0; p < 4; p++) sacc[j][p] = 0.f;
            qk_tile(sacc, sb, wm, lane);

            const int l = wm + g;
            float mt0 = -1e30f, mt1 = -1e30f;
#pragma unroll
            for (int j = 0; j < 8; j++) {
                const int r = 8 * j + 2 * t4;
                sacc[j][0] = sacc[j][0] * 0.125f + imsk[r0 + r];
                sacc[j][1] = sacc[j][1] * 0.125f + imsk[r0 + r + 1];
                sacc[j][2] = sacc[j][2] * 0.125f + imsk[r0 + r];
                sacc[j][3] = sacc[j][3] * 0.125f + imsk[r0 + r + 1];
                mt0 = fmaxf(mt0, fmaxf(sacc[j][0], sacc[j][1]));
                mt1 = fmaxf(mt1, fmaxf(sacc[j][2], sacc[j][3]));
            }
            mt0 = fmaxf(mt0, __shfl_xor_sync(0xffffffffu, mt0, 1));
            mt0 = fmaxf(mt0, __shfl_xor_sync(0xffffffffu, mt0, 2));
            mt1 = fmaxf(mt1, __shfl_xor_sync(0xffffffffu, mt1, 1));
            mt1 = fmaxf(mt1, __shfl_xor_sync(0xffffffffu, mt1, 2));
            float mn0 = fmaxf(mrow[0], mt0), mn1 = fmaxf(mrow[1], mt1);
            float cr0 = __expf(mrow[0] - mn0), cr1 = __expf(mrow[1] - mn1);
            mrow[0] = mn0; mrow[1] = mn1;
            float ps0 = 0.f, ps1 = 0.f;
#pragma unroll
            for (int j = 0; j < 8; j++) {
                float p00 = __expf(sacc[j][0] - mn0), p01 = __expf(sacc[j][1] - mn0);
                float p10 = __expf(sacc[j][2] - mn1), p11 = __expf(sacc[j][3] - mn1);
                ps0 += p00 + p01; ps1 += p10 + p11;
                int cidx = 8 * j + 2 * t4;
                *(uint32_t*)(sm + A_SPH + (l * PST + cidx) * 2) = pk2h(p00, p01);
                *(uint32_t*)(sm + A_SPH + ((l + 8) * PST + cidx) * 2) = pk2h(p10, p11);
            }
            ps0 += __shfl_xor_sync(0xffffffffu, ps0, 1);
            ps0 += __shfl_xor_sync(0xffffffffu, ps0, 2);
            ps1 += __shfl_xor_sync(0xffffffffu, ps1, 1);
            ps1 += __shfl_xor_sync(0xffffffffu, ps1, 2);
            ssum[0] = ssum[0] * cr0 + ps0;
            ssum[1] = ssum[1] * cr1 + ps1;
            if (t4 == 0) { corr_sm[l] = cr0; corr_sm[l + 8] = cr1; }
        }
        __syncthreads();

        {
            float c0r = corr_sm[wm2 + g], c1r = corr_sm[wm2 + 8 + g];
#pragma unroll
            for (int nf = 0; nf < 4; nf++) {
                cacc[nf][0] *= c0r; cacc[nf][1] *= c0r;
                cacc[nf][2] *= c1r; cacc[nf][3] *= c1r;
            }
            pv_tile(cacc, sb, wm2, wn2, lane);
        }
        __syncthreads();
    }

    if (warp < 4 && t4 == 0) {
        ((float*)(sm + A_SSI))[wm + g] = ssum[0];
        ((float*)(sm + A_SSI))[wm + g + 8] = ssum[1];
    }
    __syncthreads();

    {
        const float tg = tanhf(gate[h]);
        const float* stash = (const float*)(sm + A_STASH);
        const float* ssmv = (const float*)(sm + A_SSM);
        const float* ssiv = (const float*)(sm + A_SSI);
        const float rnm0 = 1.f / ssmv[wm2 + g], rni0 = tg / ssiv[wm2 + g];
        const float rnm1 = 1.f / ssmv[wm2 + 8 + g], rni1 = tg / ssiv[wm2 + 8 + g];
#pragma unroll
        for (int nf = 0; nf < 4; nf++) {
            const int d = wn2 + 8 * nf + 2 * t4;
            float2 o0, o1;
            o0.x = stash[(wm2 + g) * 68 + d] * rnm0 + cacc[nf][0] * rni0;
            o0.y = stash[(wm2 + g) * 68 + d + 1] * rnm0 + cacc[nf][1] * rni0;
            o1.x = stash[(wm2 + 8 + g) * 68 + d] * rnm1 + cacc[nf][2] * rni1;
            o1.y = stash[(wm2 + 8 + g) * 68 + d + 1] * rnm1 + cacc[nf][3] * rni1;
            *(float2*)(outp + ((size_t)(b * SQ + l0 + wm2 + g)) * HIDDEN + h * DH + d) = o0;
            *(float2*)(outp + ((size_t)(b * SQ + l0 + wm2 + 8 + g)) * HIDDEN + h * DH + d) = o1;
        }
    }
}

// ---------------------------------------------------------------------------
extern "C" void kernel_launch(void* const* d_in, const int* in_sizes, int n_in,
                              void* d_out, int out_size)
{
    (void)in_sizes; (void)n_in; (void)out_size;
    const float* hs    = (const float*)d_in[0];
    const float* amask = (const float*)d_in[1];
    const float* ihs   = (const float*)d_in[2];
    const float* imask = (const float*)d_in[3];
    const float* Wq    = (const float*)d_in[4];
    const float* bq    = (const float*)d_in[5];
    const float* Wk    = (const float*)d_in[6];
    const float* bk    = (const float*)d_in[7];
    const float* Wv    = (const float*)d_in[8];
    const float* bv    = (const float*)d_in[9];
    const float* gate  = (const float*)d_in[10];
    const float* dist  = (const float*)d_in[11];
    float* out = (float*)d_out;

    __half *qh, *ql, *kf, *vf, *ikf, *ivf, *ef, *xc, *ixc, *wc;
    cudaGetSymbolAddress((void**)&qh, g_Qh);
    cudaGetSymbolAddress((void**)&ql, g_Ql);
    cudaGetSymbolAddress((void**)&kf, g_Kf);
    cudaGetSymbolAddress((void**)&vf, g_Vf);
    cudaGetSymbolAddress((void**)&ikf, g_IKf);
    cudaGetSymbolAddress((void**)&ivf, g_IVf);
    cudaGetSymbolAddress((void**)&ef, g_Ef);
    cudaGetSymbolAddress((void**)&xc, g_Xh);
    cudaGetSymbolAddress((void**)&ixc, g_IXh);
    cudaGetSymbolAddress((void**)&wc, g_Wh);

    cudaFuncSetAttribute(gemm_mma, cudaFuncAttributeMaxDynamicSharedMemorySize, GEMM_SMEM);
    cudaFuncSetAttribute(attn_mma, cudaFuncAttributeMaxDynamicSharedMemorySize, A_TOTAL);

    conv_all<<<NX_BASE3 + NX_W, 256>>>((const float4*)hs, xc,
                                       (const float4*)ihs, ixc, dist, ef,
                                       Wq, Wk, Wv, wc);

    gemm_mma<<<416, 256, GEMM_SMEM>>>(xc, ixc, wc, bq, bk, bv,
                                      qh, ql, kf, vf, ikf, ivf);

    attn_mma<<<dim3(SQ / 64, BHN), 256, A_TOTAL>>>(amask, imask, gate, out);
}

// round 14
// speedup vs baseline: 2.0168x; 1.0741x over previous
#include <cuda_runtime.h>
#include <cuda_bf16.h>
#include <cuda_fp16.h>
#include <math.h>
#include <cstdint>

#define NB 4
#define NH 16
#define DH 64
#define SQ 1024
#define LI 128
#define HIDDEN 1024
#define BHN (NB * NH)

// ---------------- scratch (all fp16, single-term) ---------------------------
__device__ __align__(16) __half g_Qf[BHN * SQ * DH];
__device__ __align__(16) __half g_Kf[BHN * SQ * DH];
__device__ __align__(16) __half g_Vf[BHN * SQ * DH];
__device__ __align__(16) __half g_IKf[BHN * LI * DH];
__device__ __align__(16) __half g_IVf[BHN * LI * DH];
__device__ __align__(16) __half g_Ef[2048 * DH];

__device__ __align__(16) __half g_Xh[NB * SQ * HIDDEN];
__device__ __align__(16) __half g_IXh[NB * LI * HIDDEN];
__device__ __align__(16) __half g_Wh[3 * HIDDEN * HIDDEN];   // [n(3072)][k(1024)]

// ---------------- helpers ---------------------------------------------------
__device__ __forceinline__ uint32_t smem_u32(const void* p) {
    uint32_t a;
    asm("{ .reg .u64 t; cvta.to.shared.u64 t, %1; cvt.u32.u64 %0, t; }" : "=r"(a) : "l"(p));
    return a;
}
__device__ __forceinline__ void ldsm4(uint32_t& r0, uint32_t& r1, uint32_t& r2,
                                      uint32_t& r3, uint32_t addr) {
    asm volatile("ldmatrix.sync.aligned.m8n8.x4.shared.b16 {%0,%1,%2,%3}, [%4];"
                 : "=r"(r0), "=r"(r1), "=r"(r2), "=r"(r3) : "r"(addr));
}
__device__ __forceinline__ void ldsm4t(uint32_t& r0, uint32_t& r1, uint32_t& r2,
                                       uint32_t& r3, uint32_t addr) {
    asm volatile("ldmatrix.sync.aligned.m8n8.x4.trans.shared.b16 {%0,%1,%2,%3}, [%4];"
                 : "=r"(r0), "=r"(r1), "=r"(r2), "=r"(r3) : "r"(addr));
}
__device__ __forceinline__ void mma16816h(float* c, uint32_t a0, uint32_t a1,
                                          uint32_t a2, uint32_t a3,
                                          uint32_t b0, uint32_t b1) {
    asm volatile(
        "mma.sync.aligned.m16n8k16.row.col.f32.f16.f16.f32 "
        "{%0,%1,%2,%3}, {%4,%5,%6,%7}, {%8,%9}, {%0,%1,%2,%3};"
        : "+f"(c[0]), "+f"(c[1]), "+f"(c[2]), "+f"(c[3])
        : "r"(a0), "r"(a1), "r"(a2), "r"(a3), "r"(b0), "r"(b1));
}
__device__ __forceinline__ uint32_t pk2h(float a, float b) {
    __half2 t = __floats2half2_rn(a, b);
    return *(uint32_t*)&t;
}
__device__ __forceinline__ void cpasync16(uint32_t dst, const void* src) {
    asm volatile("cp.async.cg.shared.global [%0], [%1], 16;" :: "r"(dst), "l"(src));
}
#define CP_COMMIT() asm volatile("cp.async.commit_group;" ::: "memory")
#define CP_WAIT(n)  asm volatile("cp.async.wait_group %0;" :: "n"(n) : "memory")

// ---------------------------------------------------------------------------
// Conversions: X / X-instruct / E / W merged (single-term fp16 everywhere).
// ---------------------------------------------------------------------------
#define NX_MAIN (NB * SQ * HIDDEN / 4 / 256)
#define NX_INST (NB * LI * HIDDEN / 4 / 256)
#define NX_E    (2048 * 64 / 256)
#define NX_W    3072
#define NX_BASE3 (NX_MAIN + NX_INST + NX_E)

__global__ __launch_bounds__(256)
void conv_all(const float4* __restrict__ xm, __half* __restrict__ dm,
              const float4* __restrict__ xi, __half* __restrict__ di,
              const float* __restrict__ dist, __half* __restrict__ eh,
              const float* __restrict__ Wq, const float* __restrict__ Wk,
              const float* __restrict__ Wv, __half* __restrict__ wdst)
{
    __shared__ float t[32][33];
    int blk = blockIdx.x;
    if (blk >= NX_BASE3) {
        int wblk = blk - NX_BASE3;
        int z = wblk >> 10, rem = wblk & 1023;
        int bx = rem & 31, by = rem >> 5;
        const float* W = (z == 0) ? Wq : (z == 1) ? Wk : Wv;
        int tx = threadIdx.x & 31, ty = threadIdx.x >> 5;
        int n = bx * 32 + tx, k0 = by * 32;
#pragma unroll
        for (int j = 0; j < 4; j++)
            t[ty + 8 * j][tx] = W[(size_t)(k0 + ty + 8 * j) * HIDDEN + n];
        __syncthreads();
        size_t nrow = (size_t)z * HIDDEN + bx * 32;
#pragma unroll
        for (int j = 0; j < 4; j++)
            wdst[(nrow + ty + 8 * j) * HIDDEN + k0 + tx] = __float2half(t[tx][ty + 8 * j]);
        return;
    }
    if (blk >= NX_MAIN + NX_INST) {
        int i = (blk - NX_MAIN - NX_INST) * 256 + threadIdx.x;
        float v = (i < 2047 * 64) ? dist[i] : 0.f;
        eh[i] = __float2half(v);
        return;
    }
    const float4* src = (blk < NX_MAIN) ? xm : xi;
    __half* dst = (blk < NX_MAIN) ? dm : di;
    int i = ((blk < NX_MAIN) ? blk : blk - NX_MAIN) * 256 + threadIdx.x;
    float4 v = src[i];
    uint2 H;
    H.x = pk2h(v.x, v.y);
    H.y = pk2h(v.z, v.w);
    *(uint2*)(dst + (size_t)i * 4) = H;
}

// ---------------------------------------------------------------------------
// Merged projection GEMM: K=1024 fp16, all outputs single fp16.
// ---------------------------------------------------------------------------
#define AST 72
#define TA (128 * AST * 2)
#define TB (256 * AST * 2)
#define GEMM_SMEM (2 * (TA + TB))

__global__ __launch_bounds__(256, 1)
void gemm_mma(const __half* __restrict__ Am, const __half* __restrict__ Ai,
              const __half* __restrict__ Bm,
              const float* __restrict__ bq, const float* __restrict__ bk,
              const float* __restrict__ bv,
              __half* oQf, __half* oKf, __half* oVf,
              __half* oIKf, __half* oIVf)
{
    extern __shared__ char smem[];
    const uint32_t sb = smem_u32(smem);
    const int tid = threadIdx.x, warp = tid >> 5, lane = tid & 31;

    const __half* A;
    int msh, Slen, m0, n0g, inst;
    {
        int blk = blockIdx.x;
        if (blk < 384) {
            A = Am; msh = 10; Slen = SQ; inst = 0;
            m0 = (blk / 12) * 128; n0g = (blk % 12) * 256;
        } else {
            blk -= 384;
            A = Ai; msh = 7; Slen = LI; inst = 1;
            m0 = (blk / 8) * 128; n0g = 1024 + (blk % 8) * 256;
        }
    }
    const int wm = (warp >> 2) * 64, wn = (warp & 3) * 64;

    const int cr = tid >> 3, cko = (tid & 7) * 8;
    const __half* Ag = A + (size_t)(m0 + cr) * HIDDEN + cko;
    const __half* Bg = Bm + (size_t)(n0g + cr) * HIDDEN + cko;
    const uint32_t sAo = (cr * AST + cko) * 2;

    float acc[4][8][4];
#pragma unroll
    for (int i = 0; i < 4; i++)
#pragma unroll
        for (int j = 0; j < 8; j++)
#pragma unroll
            for (int p = 0; p < 4; p++) acc[i][j][p] = 0.f;

#pragma unroll
    for (int i = 0; i < 4; i++)
        cpasync16(sb + sAo + i * 32 * AST * 2, Ag + (size_t)(i * 32) * HIDDEN);
#pragma unroll
    for (int i = 0; i < 8; i++)
        cpasync16(sb + TA + sAo + i * 32 * AST * 2, Bg + (size_t)(i * 32) * HIDDEN);
    CP_COMMIT();

    const int NCH = 16;
    for (int c = 0; c < NCH; c++) {
        const int p = c & 1;
        if (c + 1 < NCH) {
            const int pn = (c + 1) & 1;
            const int koff = (c + 1) * 64;
#pragma unroll
            for (int i = 0; i < 4; i++)
                cpasync16(sb + pn * (TA + TB) + sAo + i * 32 * AST * 2,
                          Ag + (size_t)(i * 32) * HIDDEN + koff);
#pragma unroll
            for (int i = 0; i < 8; i++)
                cpasync16(sb + pn * (TA + TB) + TA + sAo + i * 32 * AST * 2,
                          Bg + (size_t)(i * 32) * HIDDEN + koff);
            CP_COMMIT();
            CP_WAIT(1);
        } else {
            CP_WAIT(0);
        }
        __syncthreads();

        const uint32_t aw = sb + p * (TA + TB) +
                            ((wm + (lane & 15)) * AST + (lane >> 4) * 8) * 2;
        const uint32_t bw = sb + p * (TA + TB) + TA +
                            ((wn + (lane & 15)) * AST + (lane >> 4) * 8) * 2;
#pragma unroll
        for (int k16 = 0; k16 < 4; k16++) {
            const uint32_t ko = k16 * 32;
            uint32_t a[4][4], b[4][4];
#pragma unroll
            for (int mt = 0; mt < 4; mt++)
                ldsm4(a[mt][0], a[mt][1], a[mt][2], a[mt][3],
                      aw + mt * 16 * AST * 2 + ko);
#pragma unroll
            for (int nb = 0; nb < 4; nb++)
                ldsm4(b[nb][0], b[nb][1], b[nb][2], b[nb][3],
                      bw + nb * 16 * AST * 2 + ko);
#pragma unroll
            for (int mt = 0; mt < 4; mt++)
#pragma unroll
                for (int nb = 0; nb < 4; nb++) {
                    mma16816h(acc[mt][2 * nb], a[mt][0], a[mt][1], a[mt][2], a[mt][3],
                              b[nb][0], b[nb][2]);
                    mma16816h(acc[mt][2 * nb + 1], a[mt][0], a[mt][1], a[mt][2], a[mt][3],
                              b[nb][1], b[nb][3]);
                }
        }
        __syncthreads();
    }

#pragma unroll
    for (int nt = 0; nt < 8; nt++) {
        const int n = n0g + wn + nt * 8 + (lane & 3) * 2;
        const int wsel = n >> 10, nn = n & 1023;
        const float* bias = (wsel == 0) ? bq : (wsel == 1) ? bk : bv;
        const float b0 = bias[nn], b1 = bias[nn + 1];
        const size_t hoff = ((size_t)(nn >> 6)) * Slen;
        const int d = nn & 63;
        __half* pv = inst ? ((wsel == 1) ? oIKf : oIVf)
                          : ((wsel == 0) ? oQf : (wsel == 1) ? oKf : oVf);
#pragma unroll
        for (int mt = 0; mt < 4; mt++)
#pragma unroll
            for (int half = 0; half < 2; half++) {
                const int r = m0 + wm + mt * 16 + (lane >> 2) + half * 8;
                const int bb = r >> msh, t = r - (bb << msh);
                float vx = acc[mt][nt][half * 2 + 0] + b0;
                float vy = acc[mt][nt][half * 2 + 1] + b1;
                size_t off = ((size_t)bb * NH * Slen + hoff + t) * DH + d;
                *(uint32_t*)(pv + off) = pk2h(vx, vy);
            }
    }
}

// ---------------------------------------------------------------------------
// Attention v6: single-term fp16 QK (32 MMAs/warp); all P1-fresh on score
// warps (32); P2-only on warps 4-7 (64); PV all warps (16). 64 MMAs/warp/tile.
// ---------------------------------------------------------------------------
#define PST 72
#define P12 132
#define A_SQH 0
#define A_KH  9216
#define A_VH  18432
#define A_E0  27648
#define A_E1  36864
#define A_P1A 46080
#define A_P1B 55296
#define A_P2  64512
#define A_SPH A_P2
#define A_STASH A_P1A
#define A_CORR 81408
#define A_SSM 81664
#define A_SSI 81920
#define A_AMSK 82176
#define A_IMSK 82432
#define A_TOTAL 82944

__device__ __forceinline__ void cpa_tile64(uint32_t sb, int dstoff,
                                           const __half* src, int tid)
{
#pragma unroll
    for (int it = 0; it < 2; it++) {
        int i = tid + it * 256;
        int r = i >> 3, c = (i & 7) * 8;
        cpasync16(sb + dstoff + (r * PST + c) * 2, src + r * 64 + c);
    }
}
__device__ __forceinline__ float ldh(const char* sm, int base, int idx) {
    return __half2float(*(const __half*)(sm + base + idx * 2));
}

// QK single-term fp16: 32 MMAs.
__device__ __forceinline__ void qk_tile(float sacc[8][4], uint32_t sb,
                                        int wm, int lane)
{
#pragma unroll
    for (int k = 0; k < 4; k++) {
        const uint32_t ko = (k * 16 + (lane >> 4) * 8) * 2;
        uint32_t aH[4];
        ldsm4(aH[0], aH[1], aH[2], aH[3],
              sb + A_SQH + (wm + (lane & 15)) * PST * 2 + ko);
#pragma unroll
        for (int nb = 0; nb < 4; nb++) {
            uint32_t bK[4];
            ldsm4(bK[0], bK[1], bK[2], bK[3],
                  sb + A_KH + (nb * 16 + (lane & 15)) * PST * 2 + ko);
            mma16816h(sacc[2 * nb], aH[0], aH[1], aH[2], aH[3], bK[0], bK[2]);
            mma16816h(sacc[2 * nb + 1], aH[0], aH[1], aH[2], aH[3], bK[1], bK[3]);
        }
    }
}

// P1 full fresh chunk: Q[m0p..m0p+15] @ E(ebuf)^T (all 64 cols). 32 MMAs.
__device__ __forceinline__ void p1_full(uint32_t sb, char* sm, int ebuf,
                                        int p1buf, int m0p, int lane,
                                        int g, int t4)
{
    float pacc[8][4];
#pragma unroll
    for (int j = 0; j < 8; j++)
#pragma unroll
        for (int p = 0; p < 4; p++) pacc[j][p] = 0.f;
#pragma unroll
    for (int k = 0; k < 4; k++) {
        const uint32_t ko = (k * 16 + (lane >> 4) * 8) * 2;
        uint32_t a[4];
        ldsm4(a[0], a[1], a[2], a[3],
              sb + A_SQH + (m0p + (lane & 15)) * PST * 2 + ko);
#pragma unroll
        for (int nb = 0; nb < 4; nb++) {
            uint32_t be[4];
            ldsm4(be[0], be[1], be[2], be[3],
                  sb + ebuf + (nb * 16 + (lane & 15)) * PST * 2 + ko);
            mma16816h(pacc[2 * nb], a[0], a[1], a[2], a[3], be[0], be[2]);
            mma16816h(pacc[2 * nb + 1], a[0], a[1], a[2], a[3], be[1], be[3]);
        }
    }
#pragma unroll
    for (int j = 0; j < 8; j++) {
        int w = 8 * j + 2 * t4;
        *(uint32_t*)(sm + p1buf + ((m0p + g) * PST + w) * 2) =
            pk2h(pacc[j][0], pacc[j][1]);
        *(uint32_t*)(sm + p1buf + ((m0p + 8 + g) * PST + w) * 2) =
            pk2h(pacc[j][2], pacc[j][3]);
    }
}

// P2: K @ E^T (both chunks) -> A_P2 [64 r][128 w]. 64 MMAs/warp.
__device__ __forceinline__ void p2_tile(uint32_t sb, char* sm, int rt,
                                        int m0p, int lane, int g, int t4)
{
#pragma unroll
    for (int c = 0; c < 2; c++) {
        const int ebuf = ((rt + c) & 1) ? A_E1 : A_E0;
        float pacc[8][4];
#pragma unroll
        for (int j = 0; j < 8; j++)
#pragma unroll
            for (int p = 0; p < 4; p++) pacc[j][p] = 0.f;
#pragma unroll
        for (int k = 0; k < 4; k++) {
            const uint32_t ko = (k * 16 + (lane >> 4) * 8) * 2;
            uint32_t a[4];
            ldsm4(a[0], a[1], a[2], a[3],
                  sb + A_KH + (m0p + (lane & 15)) * PST * 2 + ko);
#pragma unroll
            for (int nb = 0; nb < 4; nb++) {
                uint32_t be[4];
                ldsm4(be[0], be[1], be[2], be[3],
                      sb + ebuf + (nb * 16 + (lane & 15)) * PST * 2 + ko);
                mma16816h(pacc[2 * nb], a[0], a[1], a[2], a[3], be[0], be[2]);
                mma16816h(pacc[2 * nb + 1], a[0], a[1], a[2], a[3], be[1], be[3]);
            }
        }
#pragma unroll
        for (int j = 0; j < 8; j++) {
            int w = c * 64 + 8 * j + 2 * t4;
            *(uint32_t*)(sm + A_P2 + ((m0p + g) * P12 + w) * 2) =
                pk2h(pacc[j][0], pacc[j][1]);
            *(uint32_t*)(sm + A_P2 + ((m0p + 8 + g) * P12 + w) * 2) =
                pk2h(pacc[j][2], pacc[j][3]);
        }
    }
}

// PV single-term fp16.
__device__ __forceinline__ void pv_tile(float cacc[4][4], uint32_t sb,
                                        int wm2, int wn2, int lane)
{
#pragma unroll
    for (int kk = 0; kk < 4; kk++) {
        const uint32_t ko = (kk * 16 + (lane >> 4) * 8) * 2;
        uint32_t aP[4];
        ldsm4(aP[0], aP[1], aP[2], aP[3],
              sb + A_SPH + (wm2 + (lane & 15)) * PST * 2 + ko);
        const uint32_t trow = (kk * 16 + (lane & 7) + 8 * ((lane >> 3) & 1)) * PST;
#pragma unroll
        for (int dh = 0; dh < 2; dh++) {
            const uint32_t tcol = wn2 + dh * 16 + ((lane >> 4) & 1) * 8;
            uint32_t v[4];
            ldsm4t(v[0], v[1], v[2], v[3], sb + A_VH + (trow + tcol) * 2);
            const int nf = dh * 2;
            mma16816h(cacc[nf], aP[0], aP[1], aP[2], aP[3], v[0], v[1]);
            mma16816h(cacc[nf + 1], aP[0], aP[1], aP[2], aP[3], v[2], v[3]);
        }
    }
}

__global__ __launch_bounds__(256, 2)
void attn_mma(const float* __restrict__ amask, const float* __restrict__ imask,
              const float* __restrict__ gate, float* __restrict__ outp)
{
    extern __shared__ char sm[];
    const uint32_t sb = smem_u32(sm);
    const int tid = threadIdx.x, warp = tid >> 5, lane = tid & 31;
    const int g = lane >> 2, t4 = lane & 3;
    const int bh = blockIdx.y, b = bh >> 4, h = bh & 15;
    const int l0 = blockIdx.x * 64;
    const int wm = warp * 16;
    const int wm2 = (warp >> 1) * 16, wn2 = (warp & 1) * 32;

    cpa_tile64(sb, A_SQH, g_Qf + ((size_t)bh * SQ + l0) * DH, tid);
    if (tid < 32)
        ((float4*)(sm + A_IMSK))[tid] = ((const float4*)(imask + b * LI))[tid];

    float cacc[4][4];
#pragma unroll
    for (int i = 0; i < 4; i++)
#pragma unroll
        for (int j = 0; j < 4; j++) cacc[i][j] = 0.f;
    float mrow[2] = {-1e30f, -1e30f}, ssum[2] = {0.f, 0.f};
    float* corr_sm = (float*)(sm + A_CORR);
    const float* amsk = (const float*)(sm + A_AMSK);
    const float* imsk = (const float*)(sm + A_IMSK);

    // ======================= main pass =======================
    for (int rt = 0; rt < 16; rt++) {
        const int r0 = rt * 64;
        const int epb = (rt & 1) ? A_E1 : A_E0;
        const int p1b = (rt & 1) ? A_P1B : A_P1A;

        cpa_tile64(sb, A_KH, g_Kf + ((size_t)bh * SQ + r0) * DH, tid);
        cpa_tile64(sb, A_VH, g_Vf + ((size_t)bh * SQ + r0) * DH, tid);
        cpa_tile64(sb, epb, g_Ef + (size_t)(l0 - r0 + 960) * 64, tid);
        if (rt == 0)
            cpa_tile64(sb, A_E1, g_Ef + (size_t)(l0 + 1024) * 64, tid);
        if (tid < 64) ((float*)(sm + A_AMSK))[tid] = amask[b * SQ + r0 + tid];
        CP_COMMIT();
        CP_WAIT(0);
        __syncthreads();

        float sacc[8][4];
        if (warp < 4) {
#pragma unroll
            for (int j = 0; j < 8; j++)
#pragma unroll
                for (int p = 0; p < 4; p++) sacc[j][p] = 0.f;
            qk_tile(sacc, sb, wm, lane);
            p1_full(sb, sm, epb, p1b, wm, lane, g, t4);
            if (rt == 0)
                p1_full(sb, sm, A_E1, A_P1B, wm, lane, g, t4);
        } else {
            p2_tile(sb, sm, rt, (warp - 4) * 16, lane, g, t4);
        }
        __syncthreads();

        if (warp < 4) {
            const int l = wm + g;
            const int p1c0 = (rt & 1) ? A_P1B : A_P1A;
            const int p1c1 = (rt & 1) ? A_P1A : A_P1B;
#pragma unroll
            for (int j = 0; j < 8; j++) {
                const int r = 8 * j + 2 * t4;
                const int w = l - r + 63;
                const int w1 = w - 1, w2 = w + 8, w3 = w + 7;
                float p1a  = ldh(sm, (w  >= 64) ? p1c1 : p1c0, l * PST + (w  & 63));
                float p1b_ = ldh(sm, (w1 >= 64) ? p1c1 : p1c0, l * PST + (w1 & 63));
                float p1c  = ldh(sm, (w2 >= 64) ? p1c1 : p1c0, (l + 8) * PST + (w2 & 63));
                float p1d  = ldh(sm, (w3 >= 64) ? p1c1 : p1c0, (l + 8) * PST + (w3 & 63));
                sacc[j][0] = (sacc[j][0] + p1a  + ldh(sm, A_P2, r * P12 + w)) * 0.125f + amsk[r];
                sacc[j][1] = (sacc[j][1] + p1b_ + ldh(sm, A_P2, (r + 1) * P12 + w1)) * 0.125f + amsk[r + 1];
                sacc[j][2] = (sacc[j][2] + p1c  + ldh(sm, A_P2, r * P12 + w2)) * 0.125f + amsk[r];
                sacc[j][3] = (sacc[j][3] + p1d  + ldh(sm, A_P2, (r + 1) * P12 + w3)) * 0.125f + amsk[r + 1];
            }
            float mt0 = -1e30f, mt1 = -1e30f;
#pragma unroll
            for (int j = 0; j < 8; j++) {
                mt0 = fmaxf(mt0, fmaxf(sacc[j][0], sacc[j][1]));
                mt1 = fmaxf(mt1, fmaxf(sacc[j][2], sacc[j][3]));
            }
            mt0 = fmaxf(mt0, __shfl_xor_sync(0xffffffffu, mt0, 1));
            mt0 = fmaxf(mt0, __shfl_xor_sync(0xffffffffu, mt0, 2));
            mt1 = fmaxf(mt1, __shfl_xor_sync(0xffffffffu, mt1, 1));
            mt1 = fmaxf(mt1, __shfl_xor_sync(0xffffffffu, mt1, 2));
            asm volatile("bar.sync 1, 128;" ::: "memory");
            float mn0 = fmaxf(mrow[0], mt0), mn1 = fmaxf(mrow[1], mt1);
            float cr0 = __expf(mrow[0] - mn0), cr1 = __expf(mrow[1] - mn1);
            mrow[0] = mn0; mrow[1] = mn1;
            float ps0 = 0.f, ps1 = 0.f;
#pragma unroll
            for (int j = 0; j < 8; j++) {
                float p00 = __expf(sacc[j][0] - mn0), p01 = __expf(sacc[j][1] - mn0);
                float p10 = __expf(sacc[j][2] - mn1), p11 = __expf(sacc[j][3] - mn1);
                ps0 += p00 + p01; ps1 += p10 + p11;
                int cidx = 8 * j + 2 * t4;
                *(uint32_t*)(sm + A_SPH + (l * PST + cidx) * 2) = pk2h(p00, p01);
                *(uint32_t*)(sm + A_SPH + ((l + 8) * PST + cidx) * 2) = pk2h(p10, p11);
            }
            ps0 += __shfl_xor_sync(0xffffffffu, ps0, 1);
            ps0 += __shfl_xor_sync(0xffffffffu, ps0, 2);
            ps1 += __shfl_xor_sync(0xffffffffu, ps1, 1);
            ps1 += __shfl_xor_sync(0xffffffffu, ps1, 2);
            ssum[0] = ssum[0] * cr0 + ps0;
            ssum[1] = ssum[1] * cr1 + ps1;
            if (t4 == 0) { corr_sm[l] = cr0; corr_sm[l + 8] = cr1; }
        }
        __syncthreads();

        {
            float c0r = corr_sm[wm2 + g], c1r = corr_sm[wm2 + 8 + g];
#pragma unroll
            for (int nf = 0; nf < 4; nf++) {
                cacc[nf][0] *= c0r; cacc[nf][1] *= c0r;
                cacc[nf][2] *= c1r; cacc[nf][3] *= c1r;
            }
            pv_tile(cacc, sb, wm2, wn2, lane);
        }
        __syncthreads();
    }

    // stash main ctx + ssum, reset
    {
        float* stash = (float*)(sm + A_STASH);
#pragma unroll
        for (int nf = 0; nf < 4; nf++) {
            int d = wn2 + 8 * nf + 2 * t4;
            stash[(wm2 + g) * 68 + d] = cacc[nf][0];
            stash[(wm2 + g) * 68 + d + 1] = cacc[nf][1];
            stash[(wm2 + 8 + g) * 68 + d] = cacc[nf][2];
            stash[(wm2 + 8 + g) * 68 + d + 1] = cacc[nf][3];
            cacc[nf][0] = cacc[nf][1] = cacc[nf][2] = cacc[nf][3] = 0.f;
        }
        if (warp < 4 && t4 == 0) {
            ((float*)(sm + A_SSM))[wm + g] = ssum[0];
            ((float*)(sm + A_SSM))[wm + g + 8] = ssum[1];
        }
        mrow[0] = mrow[1] = -1e30f; ssum[0] = ssum[1] = 0.f;
    }
    __syncthreads();

    // ======================= instruct pass =======================
    for (int rt = 0; rt < 2; rt++) {
        const int r0 = rt * 64;
        cpa_tile64(sb, A_KH, g_IKf + ((size_t)bh * LI + r0) * DH, tid);
        cpa_tile64(sb, A_VH, g_IVf + ((size_t)bh * LI + r0) * DH, tid);
        CP_COMMIT();
        CP_WAIT(0);
        __syncthreads();

        if (warp < 4) {
            float sacc[8][4];
#pragma unroll
            for (int j = 0; j < 8; j++)
#pragma unroll
                for (int p = 0; p < 4; p++) sacc[j][p] = 0.f;
            qk_tile(sacc, sb, wm, lane);

            const int l = wm + g;
            float mt0 = -1e30f, mt1 = -1e30f;
#pragma unroll
            for (int j = 0; j < 8; j++) {
                const int r = 8 * j + 2 * t4;
                sacc[j][0] = sacc[j][0] * 0.125f + imsk[r0 + r];
                sacc[j][1] = sacc[j][1] * 0.125f + imsk[r0 + r + 1];
                sacc[j][2] = sacc[j][2] * 0.125f + imsk[r0 + r];
                sacc[j][3] = sacc[j][3] * 0.125f + imsk[r0 + r + 1];
                mt0 = fmaxf(mt0, fmaxf(sacc[j][0], sacc[j][1]));
                mt1 = fmaxf(mt1, fmaxf(sacc[j][2], sacc[j][3]));
            }
            mt0 = fmaxf(mt0, __shfl_xor_sync(0xffffffffu, mt0, 1));
            mt0 = fmaxf(mt0, __shfl_xor_sync(0xffffffffu, mt0, 2));
            mt1 = fmaxf(mt1, __shfl_xor_sync(0xffffffffu, mt1, 1));
            mt1 = fmaxf(mt1, __shfl_xor_sync(0xffffffffu, mt1, 2));
            float mn0 = fmaxf(mrow[0], mt0), mn1 = fmaxf(mrow[1], mt1);
            float cr0 = __expf(mrow[0] - mn0), cr1 = __expf(mrow[1] - mn1);
            mrow[0] = mn0; mrow[1] = mn1;
            float ps0 = 0.f, ps1 = 0.f;
#pragma unroll
            for (int j = 0; j < 8; j++) {
                float p00 = __expf(sacc[j][0] - mn0), p01 = __expf(sacc[j][1] - mn0);
                float p10 = __expf(sacc[j][2] - mn1), p11 = __expf(sacc[j][3] - mn1);
                ps0 += p00 + p01; ps1 += p10 + p11;
                int cidx = 8 * j + 2 * t4;
                *(uint32_t*)(sm + A_SPH + (l * PST + cidx) * 2) = pk2h(p00, p01);
                *(uint32_t*)(sm + A_SPH + ((l + 8) * PST + cidx) * 2) = pk2h(p10, p11);
            }
            ps0 += __shfl_xor_sync(0xffffffffu, ps0, 1);
            ps0 += __shfl_xor_sync(0xffffffffu, ps0, 2);
            ps1 += __shfl_xor_sync(0xffffffffu, ps1, 1);
            ps1 += __shfl_xor_sync(0xffffffffu, ps1, 2);
            ssum[0] = ssum[0] * cr0 + ps0;
            ssum[1] = ssum[1] * cr1 + ps1;
            if (t4 == 0) { corr_sm[l] = cr0; corr_sm[l + 8] = cr1; }
        }
        __syncthreads();

        {
            float c0r = corr_sm[wm2 + g], c1r = corr_sm[wm2 + 8 + g];
#pragma unroll
            for (int nf = 0; nf < 4; nf++) {
                cacc[nf][0] *= c0r; cacc[nf][1] *= c0r;
                cacc[nf][2] *= c1r; cacc[nf][3] *= c1r;
            }
            pv_tile(cacc, sb, wm2, wn2, lane);
        }
        __syncthreads();
    }

    if (warp < 4 && t4 == 0) {
        ((float*)(sm + A_SSI))[wm + g] = ssum[0];
        ((float*)(sm + A_SSI))[wm + g + 8] = ssum[1];
    }
    __syncthreads();

    {
        const float tg = tanhf(gate[h]);
        const float* stash = (const float*)(sm + A_STASH);
        const float* ssmv = (const float*)(sm + A_SSM);
        const float* ssiv = (const float*)(sm + A_SSI);
        const float rnm0 = 1.f / ssmv[wm2 + g], rni0 = tg / ssiv[wm2 + g];
        const float rnm1 = 1.f / ssmv[wm2 + 8 + g], rni1 = tg / ssiv[wm2 + 8 + g];
#pragma unroll
        for (int nf = 0; nf < 4; nf++) {
            const int d = wn2 + 8 * nf + 2 * t4;
            float2 o0, o1;
            o0.x = stash[(wm2 + g) * 68 + d] * rnm0 + cacc[nf][0] * rni0;
            o0.y = stash[(wm2 + g) * 68 + d + 1] * rnm0 + cacc[nf][1] * rni0;
            o1.x = stash[(wm2 + 8 + g) * 68 + d] * rnm1 + cacc[nf][2] * rni1;
            o1.y = stash[(wm2 + 8 + g) * 68 + d + 1] * rnm1 + cacc[nf][3] * rni1;
            *(float2*)(outp + ((size_t)(b * SQ + l0 + wm2 + g)) * HIDDEN + h * DH + d) = o0;
            *(float2*)(outp + ((size_t)(b * SQ + l0 + wm2 + 8 + g)) * HIDDEN + h * DH + d) = o1;
        }
    }
}

// ---------------------------------------------------------------------------
extern "C" void kernel_launch(void* const* d_in, const int* in_sizes, int n_in,
                              void* d_out, int out_size)
{
    (void)in_sizes; (void)n_in; (void)out_size;
    const float* hs    = (const float*)d_in[0];
    const float* amask = (const float*)d_in[1];
    const float* ihs   = (const float*)d_in[2];
    const float* imask = (const float*)d_in[3];
    const float* Wq    = (const float*)d_in[4];
    const float* bq    = (const float*)d_in[5];
    const float* Wk    = (const float*)d_in[6];
    const float* bk    = (const float*)d_in[7];
    const float* Wv    = (const float*)d_in[8];
    const float* bv    = (const float*)d_in[9];
    const float* gate  = (const float*)d_in[10];
    const float* dist  = (const float*)d_in[11];
    float* out = (float*)d_out;

    __half *qf, *kf, *vf, *ikf, *ivf, *ef, *xc, *ixc, *wc;
    cudaGetSymbolAddress((void**)&qf, g_Qf);
    cudaGetSymbolAddress((void**)&kf, g_Kf);
    cudaGetSymbolAddress((void**)&vf, g_Vf);
    cudaGetSymbolAddress((void**)&ikf, g_IKf);
    cudaGetSymbolAddress((void**)&ivf, g_IVf);
    cudaGetSymbolAddress((void**)&ef, g_Ef);
    cudaGetSymbolAddress((void**)&xc, g_Xh);
    cudaGetSymbolAddress((void**)&ixc, g_IXh);
    cudaGetSymbolAddress((void**)&wc, g_Wh);

    cudaFuncSetAttribute(gemm_mma, cudaFuncAttributeMaxDynamicSharedMemorySize, GEMM_SMEM);
    cudaFuncSetAttribute(attn_mma, cudaFuncAttributeMaxDynamicSharedMemorySize, A_TOTAL);

    conv_all<<<NX_BASE3 + NX_W, 256>>>((const float4*)hs, xc,
                                       (const float4*)ihs, ixc, dist, ef,
                                       Wq, Wk, Wv, wc);

    gemm_mma<<<416, 256, GEMM_SMEM>>>(xc, ixc, wc, bq, bk, bv,
                                      qf, kf, vf, ikf, ivf);

    attn_mma<<<dim3(SQ / 64, BHN), 256, A_TOTAL>>>(amask, imask, gate, out);
}